// round 2
// baseline (speedup 1.0000x reference)
#include <cuda_runtime.h>
#include <math.h>

#define NN 100000
#define EE 1600000
#define EA (EE + NN)   // edges + self loops = 1,700,000
#define HC 128         // heads*hidden = 4*32
#define F2 64          // out channels
#define NEG_SLOPE 0.2f

// ---------------- scratch (device globals; no allocation allowed) ----------
__device__ float g_h1[NN * HC];       // x @ W1
__device__ float g_out1[NN * HC];     // layer1 aggregation accumulator (init b1)
__device__ float g_h2[NN * F2];       // elu(out1) @ W2
__device__ float g_as1[NN * 4], g_ad1[NN * 4], g_m1[NN * 4], g_d1[NN * 4];
__device__ float g_as2[NN], g_ad2[NN], g_m2[NN], g_d2[NN];
__device__ int   g_src[EA], g_dst[EA];
__device__ int   g_is64;

// ---------------- helpers ---------------------------------------------------
__device__ __forceinline__ float lrelu(float x) {
    return x > 0.f ? x : NEG_SLOPE * x;
}
__device__ __forceinline__ void atomicMaxF(float* addr, float v) {
    if (v >= 0.f) atomicMax((int*)addr, __float_as_int(v));
    else          atomicMin((unsigned int*)addr, __float_as_uint(v));
}
__device__ __forceinline__ int clampN(int v) {
    return v < 0 ? 0 : (v >= NN ? NN - 1 : v);
}

// ---------------- dtype detect: int64 edge buffer has zero hi-words ----------
__global__ void k_detect(const int* __restrict__ ei32) {
    // If underlying dtype is int64 (little-endian), odd int32 slots are the
    // hi-words of indices < 2^31 -> all zero. With int32 data these slots are
    // uniform random node ids; P(8 zeros) ~ (1e-5)^8.
    int all_zero = 1;
#pragma unroll
    for (int i = 0; i < 8; i++)
        if (ei32[2 * i + 1] != 0) all_zero = 0;
    g_is64 = all_zero;
}

// ---------------- edge index load (int32 or int64), append self loops --------
__global__ void k_edges(const void* __restrict__ ei) {
    int i = blockIdx.x * blockDim.x + threadIdx.x;
    if (i >= EA) return;
    if (i < EE) {
        int s, d;
        if (g_is64) {
            const long long* p = (const long long*)ei;
            s = (int)p[i]; d = (int)p[EE + i];
        } else {
            const int* p = (const int*)ei;
            s = p[i]; d = p[EE + i];
        }
        g_src[i] = clampN(s);
        g_dst[i] = clampN(d);
    } else {
        g_src[i] = i - EE;
        g_dst[i] = i - EE;
    }
}

// ---------------- GEMM1: C[M,128] = A[M,128] @ W[128,128] -------------------
// block: 256 threads, tile 64 rows x 128 cols, thread micro-tile 4x8
__global__ void k_gemm1(const float* __restrict__ A, const float* __restrict__ W,
                        float* __restrict__ C, int M) {
    __shared__ float As[64][16];
    __shared__ float Bs[16][128];
    int tid = threadIdx.x;
    int row0 = blockIdx.x * 64;
    int tr = tid >> 4;    // 0..15 -> rows tr*4..tr*4+3
    int tc = tid & 15;    // 0..15 -> cols tc*8..tc*8+7
    float acc[4][8];
#pragma unroll
    for (int i = 0; i < 4; i++)
#pragma unroll
        for (int j = 0; j < 8; j++) acc[i][j] = 0.f;

    for (int k0 = 0; k0 < 128; k0 += 16) {
        {
            int r = tid >> 2, kk = (tid & 3) * 4;
            float4 av = make_float4(0.f, 0.f, 0.f, 0.f);
            if (row0 + r < M)
                av = *(const float4*)&A[(size_t)(row0 + r) * 128 + k0 + kk];
            *(float4*)&As[r][kk] = av;
        }
#pragma unroll
        for (int s = 0; s < 2; s++) {
            int p = tid * 4 + s * 1024;
            int bk = p >> 7, bj = p & 127;
            *(float4*)&Bs[bk][bj] = *(const float4*)&W[(size_t)(k0 + bk) * 128 + bj];
        }
        __syncthreads();
#pragma unroll
        for (int kk = 0; kk < 16; kk++) {
            float a[4], b[8];
#pragma unroll
            for (int i = 0; i < 4; i++) a[i] = As[tr * 4 + i][kk];
#pragma unroll
            for (int j = 0; j < 8; j++) b[j] = Bs[kk][tc * 8 + j];
#pragma unroll
            for (int i = 0; i < 4; i++)
#pragma unroll
                for (int j = 0; j < 8; j++) acc[i][j] = fmaf(a[i], b[j], acc[i][j]);
        }
        __syncthreads();
    }
#pragma unroll
    for (int i = 0; i < 4; i++) {
        int r = row0 + tr * 4 + i;
        if (r < M) {
            *(float4*)&C[(size_t)r * 128 + tc * 8]     = make_float4(acc[i][0], acc[i][1], acc[i][2], acc[i][3]);
            *(float4*)&C[(size_t)r * 128 + tc * 8 + 4] = make_float4(acc[i][4], acc[i][5], acc[i][6], acc[i][7]);
        }
    }
}

// ---------------- GEMM2: C[M,64] = elu(A)[M,128] @ W[128,64] ----------------
// A already contains b1 (folded into the aggregation accumulator init).
__global__ void k_gemm2(const float* __restrict__ A,
                        const float* __restrict__ W, float* __restrict__ C, int M) {
    __shared__ float As[64][16];
    __shared__ float Bs[16][64];
    int tid = threadIdx.x;
    int row0 = blockIdx.x * 64;
    int tr = tid >> 4;   // rows tr*4..+3
    int tc = tid & 15;   // cols tc*4..+3
    float acc[4][4];
#pragma unroll
    for (int i = 0; i < 4; i++)
#pragma unroll
        for (int j = 0; j < 4; j++) acc[i][j] = 0.f;

    for (int k0 = 0; k0 < 128; k0 += 16) {
        {
            int r = tid >> 2, kk = (tid & 3) * 4;
            float4 av = make_float4(0.f, 0.f, 0.f, 0.f);
            if (row0 + r < M) {
                float4 v = *(const float4*)&A[(size_t)(row0 + r) * 128 + k0 + kk];
                av.x = v.x > 0.f ? v.x : expm1f(v.x);
                av.y = v.y > 0.f ? v.y : expm1f(v.y);
                av.z = v.z > 0.f ? v.z : expm1f(v.z);
                av.w = v.w > 0.f ? v.w : expm1f(v.w);
            }
            *(float4*)&As[r][kk] = av;
        }
        {
            int p = tid * 4;
            int bk = p >> 6, bj = p & 63;
            *(float4*)&Bs[bk][bj] = *(const float4*)&W[(size_t)(k0 + bk) * 64 + bj];
        }
        __syncthreads();
#pragma unroll
        for (int kk = 0; kk < 16; kk++) {
            float a[4], b[4];
#pragma unroll
            for (int i = 0; i < 4; i++) a[i] = As[tr * 4 + i][kk];
#pragma unroll
            for (int j = 0; j < 4; j++) b[j] = Bs[kk][tc * 4 + j];
#pragma unroll
            for (int i = 0; i < 4; i++)
#pragma unroll
                for (int j = 0; j < 4; j++) acc[i][j] = fmaf(a[i], b[j], acc[i][j]);
        }
        __syncthreads();
    }
#pragma unroll
    for (int i = 0; i < 4; i++) {
        int r = row0 + tr * 4 + i;
        if (r < M)
            *(float4*)&C[(size_t)r * 64 + tc * 4] = make_float4(acc[i][0], acc[i][1], acc[i][2], acc[i][3]);
    }
}

// ---------------- layer1 attention coeffs + state init ----------------------
// one warp per node
__global__ void k_att1(const float* __restrict__ att_src, const float* __restrict__ att_dst,
                       const float* __restrict__ b1) {
    int w = blockIdx.x * 8 + (threadIdx.x >> 5);
    int lane = threadIdx.x & 31;
    if (w >= NN) return;
    const float* hrow = &g_h1[(size_t)w * 128];
    float h0 = hrow[lane], h1 = hrow[32 + lane], h2 = hrow[64 + lane], h3 = hrow[96 + lane];
    float s0 = h0 * att_src[lane],      s1 = h1 * att_src[32 + lane];
    float s2 = h2 * att_src[64 + lane], s3 = h3 * att_src[96 + lane];
    float d0 = h0 * att_dst[lane],      d1 = h1 * att_dst[32 + lane];
    float d2 = h2 * att_dst[64 + lane], d3 = h3 * att_dst[96 + lane];
#pragma unroll
    for (int off = 16; off; off >>= 1) {
        s0 += __shfl_xor_sync(~0u, s0, off); s1 += __shfl_xor_sync(~0u, s1, off);
        s2 += __shfl_xor_sync(~0u, s2, off); s3 += __shfl_xor_sync(~0u, s3, off);
        d0 += __shfl_xor_sync(~0u, d0, off); d1 += __shfl_xor_sync(~0u, d1, off);
        d2 += __shfl_xor_sync(~0u, d2, off); d3 += __shfl_xor_sync(~0u, d3, off);
    }
    if (lane == 0) {
        g_as1[w * 4 + 0] = s0; g_as1[w * 4 + 1] = s1; g_as1[w * 4 + 2] = s2; g_as1[w * 4 + 3] = s3;
        g_ad1[w * 4 + 0] = d0; g_ad1[w * 4 + 1] = d1; g_ad1[w * 4 + 2] = d2; g_ad1[w * 4 + 3] = d3;
        float ninf = -__int_as_float(0x7f800000);
        g_m1[w * 4 + 0] = ninf; g_m1[w * 4 + 1] = ninf; g_m1[w * 4 + 2] = ninf; g_m1[w * 4 + 3] = ninf;
        g_d1[w * 4 + 0] = 0.f;  g_d1[w * 4 + 1] = 0.f;  g_d1[w * 4 + 2] = 0.f;  g_d1[w * 4 + 3] = 0.f;
    }
    float* orow = &g_out1[(size_t)w * 128];
    orow[lane]      = b1[lane];
    orow[32 + lane] = b1[32 + lane];
    orow[64 + lane] = b1[64 + lane];
    orow[96 + lane] = b1[96 + lane];
}

// ---------------- layer2 attention coeffs + init (also seeds d_out = b2) ----
__global__ void k_att2(const float* __restrict__ att_src, const float* __restrict__ att_dst,
                       const float* __restrict__ b2, float* __restrict__ out) {
    int w = blockIdx.x * 8 + (threadIdx.x >> 5);
    int lane = threadIdx.x & 31;
    if (w >= NN) return;
    const float* hrow = &g_h2[(size_t)w * 64];
    float v0 = hrow[lane], v1 = hrow[32 + lane];
    float s = v0 * att_src[lane] + v1 * att_src[32 + lane];
    float d = v0 * att_dst[lane] + v1 * att_dst[32 + lane];
#pragma unroll
    for (int off = 16; off; off >>= 1) {
        s += __shfl_xor_sync(~0u, s, off);
        d += __shfl_xor_sync(~0u, d, off);
    }
    if (lane == 0) {
        g_as2[w] = s; g_ad2[w] = d;
        g_m2[w] = -__int_as_float(0x7f800000);
        g_d2[w] = 0.f;
    }
    out[(size_t)w * 64 + lane]      = b2[lane];
    out[(size_t)w * 64 + 32 + lane] = b2[32 + lane];
}

// ---------------- layer1 edge softmax: max pass ------------------------------
__global__ void k_emax1() {
    int e = blockIdx.x * blockDim.x + threadIdx.x;
    if (e >= EA) return;
    int s = g_src[e], d = g_dst[e];
    float4 as = *(const float4*)&g_as1[s * 4];
    float4 ad = *(const float4*)&g_ad1[d * 4];
    atomicMaxF(&g_m1[d * 4 + 0], lrelu(as.x + ad.x));
    atomicMaxF(&g_m1[d * 4 + 1], lrelu(as.y + ad.y));
    atomicMaxF(&g_m1[d * 4 + 2], lrelu(as.z + ad.z));
    atomicMaxF(&g_m1[d * 4 + 3], lrelu(as.w + ad.w));
}

// ---------------- layer1 edge softmax: exp-sum pass --------------------------
__global__ void k_esum1() {
    int e = blockIdx.x * blockDim.x + threadIdx.x;
    if (e >= EA) return;
    int s = g_src[e], d = g_dst[e];
    float4 as = *(const float4*)&g_as1[s * 4];
    float4 ad = *(const float4*)&g_ad1[d * 4];
    float4 m  = *(const float4*)&g_m1[d * 4];
    atomicAdd(&g_d1[d * 4 + 0], __expf(lrelu(as.x + ad.x) - m.x));
    atomicAdd(&g_d1[d * 4 + 1], __expf(lrelu(as.y + ad.y) - m.y));
    atomicAdd(&g_d1[d * 4 + 2], __expf(lrelu(as.z + ad.z) - m.z));
    atomicAdd(&g_d1[d * 4 + 3], __expf(lrelu(as.w + ad.w) - m.w));
}

// ---------------- layer1 aggregation: one warp per edge ----------------------
__global__ void k_eagg1() {
    int e = blockIdx.x * 8 + (threadIdx.x >> 5);
    int lane = threadIdx.x & 31;
    if (e >= EA) return;
    int s = g_src[e], d = g_dst[e];
    float4 as = *(const float4*)&g_as1[s * 4];
    float4 ad = *(const float4*)&g_ad1[d * 4];
    float4 m  = *(const float4*)&g_m1[d * 4];
    float4 dn = *(const float4*)&g_d1[d * 4];
    float a0 = __expf(lrelu(as.x + ad.x) - m.x) / (dn.x + 1e-16f);
    float a1 = __expf(lrelu(as.y + ad.y) - m.y) / (dn.y + 1e-16f);
    float a2 = __expf(lrelu(as.z + ad.z) - m.z) / (dn.z + 1e-16f);
    float a3 = __expf(lrelu(as.w + ad.w) - m.w) / (dn.w + 1e-16f);
    const float* hrow = &g_h1[(size_t)s * 128];
    float* orow = &g_out1[(size_t)d * 128];
    atomicAdd(&orow[lane],      hrow[lane]      * a0);
    atomicAdd(&orow[32 + lane], hrow[32 + lane] * a1);
    atomicAdd(&orow[64 + lane], hrow[64 + lane] * a2);
    atomicAdd(&orow[96 + lane], hrow[96 + lane] * a3);
}

// ---------------- layer2 edge softmax passes --------------------------------
__global__ void k_emax2() {
    int e = blockIdx.x * blockDim.x + threadIdx.x;
    if (e >= EA) return;
    int s = g_src[e], d = g_dst[e];
    atomicMaxF(&g_m2[d], lrelu(g_as2[s] + g_ad2[d]));
}
__global__ void k_esum2() {
    int e = blockIdx.x * blockDim.x + threadIdx.x;
    if (e >= EA) return;
    int s = g_src[e], d = g_dst[e];
    atomicAdd(&g_d2[d], __expf(lrelu(g_as2[s] + g_ad2[d]) - g_m2[d]));
}

// ---------------- layer2 aggregation: one warp per edge ---------------------
__global__ void k_eagg2(float* __restrict__ out) {
    int e = blockIdx.x * 8 + (threadIdx.x >> 5);
    int lane = threadIdx.x & 31;
    if (e >= EA) return;
    int s = g_src[e], d = g_dst[e];
    float alpha = __expf(lrelu(g_as2[s] + g_ad2[d]) - g_m2[d]) / (g_d2[d] + 1e-16f);
    const float* hrow = &g_h2[(size_t)s * 64];
    float* orow = &out[(size_t)d * 64];
    atomicAdd(&orow[lane],      hrow[lane]      * alpha);
    atomicAdd(&orow[32 + lane], hrow[32 + lane] * alpha);
}

// ---------------- launch ----------------------------------------------------
extern "C" void kernel_launch(void* const* d_in, const int* in_sizes, int n_in,
                              void* d_out, int out_size) {
    const float* x    = (const float*)d_in[0];
    const void*  ei   = d_in[1];
    const float* W1   = (const float*)d_in[2];
    const float* as1  = (const float*)d_in[3];
    const float* ad1  = (const float*)d_in[4];
    const float* b1   = (const float*)d_in[5];
    const float* W2   = (const float*)d_in[6];
    const float* as2  = (const float*)d_in[7];
    const float* ad2  = (const float*)d_in[8];
    const float* b2   = (const float*)d_in[9];
    float* out = (float*)d_out;

    float* p_h1;  cudaGetSymbolAddress((void**)&p_h1, g_h1);
    float* p_o1;  cudaGetSymbolAddress((void**)&p_o1, g_out1);
    float* p_h2;  cudaGetSymbolAddress((void**)&p_h2, g_h2);

    k_detect<<<1, 1>>>((const int*)ei);
    k_edges<<<(EA + 255) / 256, 256>>>(ei);
    k_gemm1<<<(NN + 63) / 64, 256>>>(x, W1, p_h1, NN);
    k_att1<<<(NN + 7) / 8, 256>>>(as1, ad1, b1);
    k_emax1<<<(EA + 255) / 256, 256>>>();
    k_esum1<<<(EA + 255) / 256, 256>>>();
    k_eagg1<<<(EA + 7) / 8, 256>>>();
    k_gemm2<<<(NN + 63) / 64, 256>>>(p_o1, W2, p_h2, NN);
    k_att2<<<(NN + 7) / 8, 256>>>(as2, ad2, b2, out);
    k_emax2<<<(EA + 255) / 256, 256>>>();
    k_esum2<<<(EA + 255) / 256, 256>>>();
    k_eagg2<<<(EA + 7) / 8, 256>>>(out);
}

// round 3
// speedup vs baseline: 1.6268x; 1.6268x over previous
#include <cuda_runtime.h>
#include <math.h>

#define NN 100000
#define EE 1600000
#define HC 128         // heads*hidden = 4*32
#define F2 64          // out channels
#define NEG_SLOPE 0.2f

// ---------------- scratch (device globals; no allocation allowed) ----------
__device__ float g_h1[NN * HC];        // x @ W1
__device__ float g_sum1[NN * HC];      // layer1 unnormalized aggregation
__device__ float g_h2[NN * F2];        // elu(out1) @ W2
__device__ float g_sum2[NN * F2];      // layer2 unnormalized aggregation
__device__ float g_as1[NN * 4], g_ad1[NN * 4], g_den1[NN * 4];
__device__ float g_as2[NN], g_ad2[NN], g_den2[NN];
__device__ int   g_src[EE], g_dst[EE];
__device__ int   g_is64;

// ---------------- helpers ---------------------------------------------------
__device__ __forceinline__ float lrelu(float x) {
    return x > 0.f ? x : NEG_SLOPE * x;
}
__device__ __forceinline__ int clampN(int v) {
    return v < 0 ? 0 : (v >= NN ? NN - 1 : v);
}
__device__ __forceinline__ void red_add_v4(float* addr, float a, float b, float c, float d) {
    asm volatile("red.global.add.v4.f32 [%0], {%1,%2,%3,%4};"
                 :: "l"(addr), "f"(a), "f"(b), "f"(c), "f"(d) : "memory");
}

// ---------------- dtype detect: int64 edge buffer has zero hi-words ----------
__global__ void k_detect(const int* __restrict__ ei32) {
    int all_zero = 1;
#pragma unroll
    for (int i = 0; i < 8; i++)
        if (ei32[2 * i + 1] != 0) all_zero = 0;
    g_is64 = all_zero;
}

// ---------------- edge index load (int32 or int64) ---------------------------
__global__ void k_edges(const void* __restrict__ ei) {
    int i = blockIdx.x * blockDim.x + threadIdx.x;
    if (i >= EE) return;
    int s, d;
    if (g_is64) {
        const long long* p = (const long long*)ei;
        s = (int)p[i]; d = (int)p[EE + i];
    } else {
        const int* p = (const int*)ei;
        s = p[i]; d = p[EE + i];
    }
    g_src[i] = clampN(s);
    g_dst[i] = clampN(d);
}

// ---------------- GEMM1: C[M,128] = A[M,128] @ W[128,128] -------------------
__global__ void k_gemm1(const float* __restrict__ A, const float* __restrict__ W,
                        float* __restrict__ C, int M) {
    __shared__ float As[64][16];
    __shared__ float Bs[16][128];
    int tid = threadIdx.x;
    int row0 = blockIdx.x * 64;
    int tr = tid >> 4;
    int tc = tid & 15;
    float acc[4][8];
#pragma unroll
    for (int i = 0; i < 4; i++)
#pragma unroll
        for (int j = 0; j < 8; j++) acc[i][j] = 0.f;

    for (int k0 = 0; k0 < 128; k0 += 16) {
        {
            int r = tid >> 2, kk = (tid & 3) * 4;
            float4 av = make_float4(0.f, 0.f, 0.f, 0.f);
            if (row0 + r < M)
                av = *(const float4*)&A[(size_t)(row0 + r) * 128 + k0 + kk];
            *(float4*)&As[r][kk] = av;
        }
#pragma unroll
        for (int s = 0; s < 2; s++) {
            int p = tid * 4 + s * 1024;
            int bk = p >> 7, bj = p & 127;
            *(float4*)&Bs[bk][bj] = *(const float4*)&W[(size_t)(k0 + bk) * 128 + bj];
        }
        __syncthreads();
#pragma unroll
        for (int kk = 0; kk < 16; kk++) {
            float a[4], b[8];
#pragma unroll
            for (int i = 0; i < 4; i++) a[i] = As[tr * 4 + i][kk];
#pragma unroll
            for (int j = 0; j < 8; j++) b[j] = Bs[kk][tc * 8 + j];
#pragma unroll
            for (int i = 0; i < 4; i++)
#pragma unroll
                for (int j = 0; j < 8; j++) acc[i][j] = fmaf(a[i], b[j], acc[i][j]);
        }
        __syncthreads();
    }
#pragma unroll
    for (int i = 0; i < 4; i++) {
        int r = row0 + tr * 4 + i;
        if (r < M) {
            *(float4*)&C[(size_t)r * 128 + tc * 8]     = make_float4(acc[i][0], acc[i][1], acc[i][2], acc[i][3]);
            *(float4*)&C[(size_t)r * 128 + tc * 8 + 4] = make_float4(acc[i][4], acc[i][5], acc[i][6], acc[i][7]);
        }
    }
}

// ---------------- GEMM2: C[M,64] = elu(A)[M,128] @ W[128,64] ----------------
__global__ void k_gemm2(const float* __restrict__ A,
                        const float* __restrict__ W, float* __restrict__ C, int M) {
    __shared__ float As[64][16];
    __shared__ float Bs[16][64];
    int tid = threadIdx.x;
    int row0 = blockIdx.x * 64;
    int tr = tid >> 4;
    int tc = tid & 15;
    float acc[4][4];
#pragma unroll
    for (int i = 0; i < 4; i++)
#pragma unroll
        for (int j = 0; j < 4; j++) acc[i][j] = 0.f;

    for (int k0 = 0; k0 < 128; k0 += 16) {
        {
            int r = tid >> 2, kk = (tid & 3) * 4;
            float4 av = make_float4(0.f, 0.f, 0.f, 0.f);
            if (row0 + r < M) {
                float4 v = *(const float4*)&A[(size_t)(row0 + r) * 128 + k0 + kk];
                av.x = v.x > 0.f ? v.x : expm1f(v.x);
                av.y = v.y > 0.f ? v.y : expm1f(v.y);
                av.z = v.z > 0.f ? v.z : expm1f(v.z);
                av.w = v.w > 0.f ? v.w : expm1f(v.w);
            }
            *(float4*)&As[r][kk] = av;
        }
        {
            int p = tid * 4;
            int bk = p >> 6, bj = p & 63;
            *(float4*)&Bs[bk][bj] = *(const float4*)&W[(size_t)(k0 + bk) * 64 + bj];
        }
        __syncthreads();
#pragma unroll
        for (int kk = 0; kk < 16; kk++) {
            float a[4], b[4];
#pragma unroll
            for (int i = 0; i < 4; i++) a[i] = As[tr * 4 + i][kk];
#pragma unroll
            for (int j = 0; j < 4; j++) b[j] = Bs[kk][tc * 4 + j];
#pragma unroll
            for (int i = 0; i < 4; i++)
#pragma unroll
                for (int j = 0; j < 4; j++) acc[i][j] = fmaf(a[i], b[j], acc[i][j]);
        }
        __syncthreads();
    }
#pragma unroll
    for (int i = 0; i < 4; i++) {
        int r = row0 + tr * 4 + i;
        if (r < M)
            *(float4*)&C[(size_t)r * 64 + tc * 4] = make_float4(acc[i][0], acc[i][1], acc[i][2], acc[i][3]);
    }
}

// ---------------- layer1 att coeffs + self-loop-seeded accumulator init -----
// one warp per node; butterfly reduction leaves full sums in ALL lanes
__global__ void k_att1(const float* __restrict__ att_src, const float* __restrict__ att_dst) {
    int w = blockIdx.x * 8 + (threadIdx.x >> 5);
    int lane = threadIdx.x & 31;
    if (w >= NN) return;
    const float* hrow = &g_h1[(size_t)w * 128];
    float h0 = hrow[lane], h1 = hrow[32 + lane], h2 = hrow[64 + lane], h3 = hrow[96 + lane];
    float s0 = h0 * att_src[lane],      s1 = h1 * att_src[32 + lane];
    float s2 = h2 * att_src[64 + lane], s3 = h3 * att_src[96 + lane];
    float d0 = h0 * att_dst[lane],      d1 = h1 * att_dst[32 + lane];
    float d2 = h2 * att_dst[64 + lane], d3 = h3 * att_dst[96 + lane];
#pragma unroll
    for (int off = 16; off; off >>= 1) {
        s0 += __shfl_xor_sync(~0u, s0, off); s1 += __shfl_xor_sync(~0u, s1, off);
        s2 += __shfl_xor_sync(~0u, s2, off); s3 += __shfl_xor_sync(~0u, s3, off);
        d0 += __shfl_xor_sync(~0u, d0, off); d1 += __shfl_xor_sync(~0u, d1, off);
        d2 += __shfl_xor_sync(~0u, d2, off); d3 += __shfl_xor_sync(~0u, d3, off);
    }
    // self-loop edge (w -> w): exp(lrelu(as + ad)) per head
    float e0 = __expf(lrelu(s0 + d0));
    float e1 = __expf(lrelu(s1 + d1));
    float e2 = __expf(lrelu(s2 + d2));
    float e3 = __expf(lrelu(s3 + d3));
    if (lane == 0) {
        *(float4*)&g_as1[w * 4]  = make_float4(s0, s1, s2, s3);
        *(float4*)&g_ad1[w * 4]  = make_float4(d0, d1, d2, d3);
        *(float4*)&g_den1[w * 4] = make_float4(e0, e1, e2, e3);
    }
    float* orow = &g_sum1[(size_t)w * 128];
    orow[lane]      = h0 * e0;
    orow[32 + lane] = h1 * e1;
    orow[64 + lane] = h2 * e2;
    orow[96 + lane] = h3 * e3;
}

// ---------------- layer2 att coeffs + self-loop-seeded init -----------------
__global__ void k_att2(const float* __restrict__ att_src, const float* __restrict__ att_dst) {
    int w = blockIdx.x * 8 + (threadIdx.x >> 5);
    int lane = threadIdx.x & 31;
    if (w >= NN) return;
    const float* hrow = &g_h2[(size_t)w * 64];
    float v0 = hrow[lane], v1 = hrow[32 + lane];
    float s = v0 * att_src[lane] + v1 * att_src[32 + lane];
    float d = v0 * att_dst[lane] + v1 * att_dst[32 + lane];
#pragma unroll
    for (int off = 16; off; off >>= 1) {
        s += __shfl_xor_sync(~0u, s, off);
        d += __shfl_xor_sync(~0u, d, off);
    }
    float e = __expf(lrelu(s + d));
    if (lane == 0) {
        g_as2[w] = s; g_ad2[w] = d; g_den2[w] = e;
    }
    float* orow = &g_sum2[(size_t)w * 64];
    orow[lane]      = v0 * e;
    orow[32 + lane] = v1 * e;
}

// ---------------- layer1 single edge pass: one warp per edge -----------------
__global__ void k_eagg1() {
    int e = blockIdx.x * 8 + (threadIdx.x >> 5);
    int lane = threadIdx.x & 31;
    if (e >= EE) return;
    int s = g_src[e], d = g_dst[e];
    // lanes' (lane&3) gives head for the exp computation; 16B broadcast loads
    float as = g_as1[s * 4 + (lane & 3)];
    float ad = g_ad1[d * 4 + (lane & 3)];
    float expv = __expf(lrelu(as + ad));
    if (lane < 4) atomicAdd(&g_den1[d * 4 + lane], expv);
    // lane's head = lane>>3 (4 heads x 8 lanes x float4 = 128 floats)
    float alpha = __shfl_sync(~0u, expv, lane >> 3);
    float4 hv = *(const float4*)&g_h1[(size_t)s * 128 + lane * 4];
    red_add_v4(&g_sum1[(size_t)d * 128 + lane * 4],
               hv.x * alpha, hv.y * alpha, hv.z * alpha, hv.w * alpha);
}

// ---------------- layer2 single edge pass: 2 edges per warp ------------------
__global__ void k_eagg2() {
    int pair = blockIdx.x * 8 + (threadIdx.x >> 5);
    int lane = threadIdx.x & 31;
    int e = pair * 2 + (lane >> 4);
    if (e >= EE) return;
    int sl = lane & 15;
    int s = g_src[e], d = g_dst[e];
    float expv = __expf(lrelu(g_as2[s] + g_ad2[d]));
    if (sl == 0) atomicAdd(&g_den2[d], expv);
    float4 hv = *(const float4*)&g_h2[(size_t)s * 64 + sl * 4];
    red_add_v4(&g_sum2[(size_t)d * 64 + sl * 4],
               hv.x * expv, hv.y * expv, hv.z * expv, hv.w * expv);
}

// ---------------- layer1 normalize (in place) + bias -------------------------
__global__ void k_norm1(const float* __restrict__ b1) {
    int idx = blockIdx.x * blockDim.x + threadIdx.x;   // float4 index
    if (idx >= NN * 32) return;
    int i4 = idx * 4;
    int node = i4 >> 7;
    int head = (i4 >> 5) & 3;
    float den = g_den1[node * 4 + head] + 1e-16f;
    float inv = __frcp_rn(den);
    float4 v = *(float4*)&g_sum1[i4];
    float4 bb = *(const float4*)&b1[i4 & 127];
    v.x = v.x * inv + bb.x; v.y = v.y * inv + bb.y;
    v.z = v.z * inv + bb.z; v.w = v.w * inv + bb.w;
    *(float4*)&g_sum1[i4] = v;
}

// ---------------- layer2 normalize + bias -> d_out ---------------------------
__global__ void k_norm2(const float* __restrict__ b2, float* __restrict__ out) {
    int idx = blockIdx.x * blockDim.x + threadIdx.x;   // float4 index
    if (idx >= NN * 16) return;
    int i4 = idx * 4;
    int node = i4 >> 6;
    float den = g_den2[node] + 1e-16f;
    float inv = __frcp_rn(den);
    float4 v = *(float4*)&g_sum2[i4];
    float4 bb = *(const float4*)&b2[i4 & 63];
    v.x = v.x * inv + bb.x; v.y = v.y * inv + bb.y;
    v.z = v.z * inv + bb.z; v.w = v.w * inv + bb.w;
    *(float4*)&out[i4] = v;
}

// ---------------- launch ----------------------------------------------------
extern "C" void kernel_launch(void* const* d_in, const int* in_sizes, int n_in,
                              void* d_out, int out_size) {
    const float* x    = (const float*)d_in[0];
    const void*  ei   = d_in[1];
    const float* W1   = (const float*)d_in[2];
    const float* as1  = (const float*)d_in[3];
    const float* ad1  = (const float*)d_in[4];
    const float* b1   = (const float*)d_in[5];
    const float* W2   = (const float*)d_in[6];
    const float* as2  = (const float*)d_in[7];
    const float* ad2  = (const float*)d_in[8];
    const float* b2   = (const float*)d_in[9];
    float* out = (float*)d_out;

    float* p_h1;  cudaGetSymbolAddress((void**)&p_h1, g_h1);
    float* p_s1;  cudaGetSymbolAddress((void**)&p_s1, g_sum1);
    float* p_h2;  cudaGetSymbolAddress((void**)&p_h2, g_h2);

    k_detect<<<1, 1>>>((const int*)ei);
    k_edges<<<(EE + 255) / 256, 256>>>(ei);
    k_gemm1<<<(NN + 63) / 64, 256>>>(x, W1, p_h1, NN);
    k_att1<<<(NN + 7) / 8, 256>>>(as1, ad1);
    k_eagg1<<<EE / 8, 256>>>();
    k_norm1<<<(NN * 32 + 255) / 256, 256>>>(b1);
    k_gemm2<<<(NN + 63) / 64, 256>>>(p_s1, W2, p_h2, NN);
    k_att2<<<(NN + 7) / 8, 256>>>(as2, ad2);
    k_eagg2<<<EE / 16, 256>>>();
    k_norm2<<<(NN * 16 + 255) / 256, 256>>>(b2, out);
}

// round 4
// speedup vs baseline: 1.8261x; 1.1225x over previous
#include <cuda_runtime.h>
#include <math.h>

#define NN 100000
#define EE 1600000
#define HC 128         // heads*hidden = 4*32
#define F2 64          // out channels
#define NEG_SLOPE 0.2f
#define SCAN_T 1024

// ---------------- scratch (device globals; no allocation allowed) ----------
__device__ float g_h1[NN * HC];        // x @ W1
__device__ float g_o1[NN * HC];        // layer1 output (normalized + b1)
__device__ float g_h2[NN * F2];        // elu(o1) @ W2
__device__ float g_as1[NN * 4], g_ad1[NN * 4];
__device__ float g_as2[NN], g_ad2[NN];
__device__ int   g_deg[NN];
__device__ int   g_roff[NN + 1];
__device__ int   g_cur[NN];
__device__ int   g_csrc[EE];           // CSR by dst: source node per slot
__device__ int   g_is64;

// ---------------- helpers ---------------------------------------------------
__device__ __forceinline__ float lrelu(float x) {
    return x > 0.f ? x : NEG_SLOPE * x;
}
__device__ __forceinline__ int clampN(int v) {
    return v < 0 ? 0 : (v >= NN ? NN - 1 : v);
}
__device__ __forceinline__ int edge_src(const void* ei, int i) {
    return clampN(g_is64 ? (int)((const long long*)ei)[i] : ((const int*)ei)[i]);
}
__device__ __forceinline__ int edge_dst(const void* ei, int i) {
    return clampN(g_is64 ? (int)((const long long*)ei)[EE + i] : ((const int*)ei)[EE + i]);
}

// ---------------- dtype detect: int64 edge buffer has zero hi-words ----------
__global__ void k_detect(const int* __restrict__ ei32) {
    int all_zero = 1;
#pragma unroll
    for (int i = 0; i < 8; i++)
        if (ei32[2 * i + 1] != 0) all_zero = 0;
    g_is64 = all_zero;
}

// ---------------- CSR build --------------------------------------------------
__global__ void k_zero() {
    int i = blockIdx.x * blockDim.x + threadIdx.x;
    if (i < NN) g_deg[i] = 0;
}
__global__ void k_hist(const void* __restrict__ ei) {
    int i = blockIdx.x * blockDim.x + threadIdx.x;
    if (i >= EE) return;
    atomicAdd(&g_deg[edge_dst(ei, i)], 1);
}
__global__ void k_scan() {
    __shared__ int sh[SCAN_T];
    int t = threadIdx.x;
    const int CH = (NN + SCAN_T - 1) / SCAN_T;   // 98
    int beg = t * CH;
    int end = beg + CH < NN ? beg + CH : NN;
    int sum = 0;
    for (int i = beg; i < end; i++) sum += g_deg[i];
    sh[t] = sum;
    __syncthreads();
    // Hillis-Steele inclusive scan
    for (int off = 1; off < SCAN_T; off <<= 1) {
        int v = (t >= off) ? sh[t - off] : 0;
        __syncthreads();
        sh[t] += v;
        __syncthreads();
    }
    int run = (t == 0) ? 0 : sh[t - 1];
    for (int i = beg; i < end; i++) {
        g_roff[i] = run;
        g_cur[i] = run;
        run += g_deg[i];
    }
    if (t == SCAN_T - 1) g_roff[NN] = run;
}
__global__ void k_scatter(const void* __restrict__ ei) {
    int i = blockIdx.x * blockDim.x + threadIdx.x;
    if (i >= EE) return;
    int s = edge_src(ei, i);
    int d = edge_dst(ei, i);
    int pos = atomicAdd(&g_cur[d], 1);
    g_csrc[pos] = s;
}

// ---------------- GEMM1: C[M,128] = A[M,128] @ W1 ; fused att1 epilogue ------
__global__ void k_gemm1(const float* __restrict__ A, const float* __restrict__ W,
                        float* __restrict__ C,
                        const float* __restrict__ att_src, const float* __restrict__ att_dst,
                        int M) {
    __shared__ float As[64][16];
    __shared__ float Bs[16][128];
    int tid = threadIdx.x;
    int row0 = blockIdx.x * 64;
    int tr = tid >> 4;
    int tc = tid & 15;
    float acc[4][8];
#pragma unroll
    for (int i = 0; i < 4; i++)
#pragma unroll
        for (int j = 0; j < 8; j++) acc[i][j] = 0.f;

    for (int k0 = 0; k0 < 128; k0 += 16) {
        {
            int r = tid >> 2, kk = (tid & 3) * 4;
            float4 av = make_float4(0.f, 0.f, 0.f, 0.f);
            if (row0 + r < M)
                av = *(const float4*)&A[(size_t)(row0 + r) * 128 + k0 + kk];
            *(float4*)&As[r][kk] = av;
        }
#pragma unroll
        for (int s = 0; s < 2; s++) {
            int p = tid * 4 + s * 1024;
            int bk = p >> 7, bj = p & 127;
            *(float4*)&Bs[bk][bj] = *(const float4*)&W[(size_t)(k0 + bk) * 128 + bj];
        }
        __syncthreads();
#pragma unroll
        for (int kk = 0; kk < 16; kk++) {
            float a[4], b[8];
#pragma unroll
            for (int i = 0; i < 4; i++) a[i] = As[tr * 4 + i][kk];
#pragma unroll
            for (int j = 0; j < 8; j++) b[j] = Bs[kk][tc * 8 + j];
#pragma unroll
            for (int i = 0; i < 4; i++)
#pragma unroll
                for (int j = 0; j < 8; j++) acc[i][j] = fmaf(a[i], b[j], acc[i][j]);
        }
        __syncthreads();
    }
    // store C
#pragma unroll
    for (int i = 0; i < 4; i++) {
        int r = row0 + tr * 4 + i;
        if (r < M) {
            *(float4*)&C[(size_t)r * 128 + tc * 8]     = make_float4(acc[i][0], acc[i][1], acc[i][2], acc[i][3]);
            *(float4*)&C[(size_t)r * 128 + tc * 8 + 4] = make_float4(acc[i][4], acc[i][5], acc[i][6], acc[i][7]);
        }
    }
    // fused att1: per row, per head hd = tc>>2; reduce over 4 threads (tc&3)
    float avs[8], avd[8];
#pragma unroll
    for (int j = 0; j < 8; j++) {
        avs[j] = att_src[tc * 8 + j];
        avd[j] = att_dst[tc * 8 + j];
    }
    int hd = tc >> 2;
#pragma unroll
    for (int i = 0; i < 4; i++) {
        float s = 0.f, d = 0.f;
#pragma unroll
        for (int j = 0; j < 8; j++) {
            s = fmaf(acc[i][j], avs[j], s);
            d = fmaf(acc[i][j], avd[j], d);
        }
        s += __shfl_xor_sync(~0u, s, 1); s += __shfl_xor_sync(~0u, s, 2);
        d += __shfl_xor_sync(~0u, d, 1); d += __shfl_xor_sync(~0u, d, 2);
        int r = row0 + tr * 4 + i;
        if ((tc & 3) == 0 && r < M) {
            g_as1[r * 4 + hd] = s;
            g_ad1[r * 4 + hd] = d;
        }
    }
}

// ---------------- GEMM2: C[M,64] = elu(A)[M,128] @ W2 ; fused att2 epilogue --
__global__ void k_gemm2(const float* __restrict__ A,
                        const float* __restrict__ W, float* __restrict__ C,
                        const float* __restrict__ att_src, const float* __restrict__ att_dst,
                        int M) {
    __shared__ float As[64][16];
    __shared__ float Bs[16][64];
    int tid = threadIdx.x;
    int row0 = blockIdx.x * 64;
    int tr = tid >> 4;
    int tc = tid & 15;
    float acc[4][4];
#pragma unroll
    for (int i = 0; i < 4; i++)
#pragma unroll
        for (int j = 0; j < 4; j++) acc[i][j] = 0.f;

    for (int k0 = 0; k0 < 128; k0 += 16) {
        {
            int r = tid >> 2, kk = (tid & 3) * 4;
            float4 av = make_float4(0.f, 0.f, 0.f, 0.f);
            if (row0 + r < M) {
                float4 v = *(const float4*)&A[(size_t)(row0 + r) * 128 + k0 + kk];
                av.x = v.x > 0.f ? v.x : expm1f(v.x);
                av.y = v.y > 0.f ? v.y : expm1f(v.y);
                av.z = v.z > 0.f ? v.z : expm1f(v.z);
                av.w = v.w > 0.f ? v.w : expm1f(v.w);
            }
            *(float4*)&As[r][kk] = av;
        }
        {
            int p = tid * 4;
            int bk = p >> 6, bj = p & 63;
            *(float4*)&Bs[bk][bj] = *(const float4*)&W[(size_t)(k0 + bk) * 64 + bj];
        }
        __syncthreads();
#pragma unroll
        for (int kk = 0; kk < 16; kk++) {
            float a[4], b[4];
#pragma unroll
            for (int i = 0; i < 4; i++) a[i] = As[tr * 4 + i][kk];
#pragma unroll
            for (int j = 0; j < 4; j++) b[j] = Bs[kk][tc * 4 + j];
#pragma unroll
            for (int i = 0; i < 4; i++)
#pragma unroll
                for (int j = 0; j < 4; j++) acc[i][j] = fmaf(a[i], b[j], acc[i][j]);
        }
        __syncthreads();
    }
#pragma unroll
    for (int i = 0; i < 4; i++) {
        int r = row0 + tr * 4 + i;
        if (r < M)
            *(float4*)&C[(size_t)r * 64 + tc * 4] = make_float4(acc[i][0], acc[i][1], acc[i][2], acc[i][3]);
    }
    // fused att2: reduce over all 16 tc threads (lanes aligned in half-warps)
    float avs[4], avd[4];
#pragma unroll
    for (int j = 0; j < 4; j++) {
        avs[j] = att_src[tc * 4 + j];
        avd[j] = att_dst[tc * 4 + j];
    }
#pragma unroll
    for (int i = 0; i < 4; i++) {
        float s = 0.f, d = 0.f;
#pragma unroll
        for (int j = 0; j < 4; j++) {
            s = fmaf(acc[i][j], avs[j], s);
            d = fmaf(acc[i][j], avd[j], d);
        }
#pragma unroll
        for (int off = 1; off < 16; off <<= 1) {
            s += __shfl_xor_sync(~0u, s, off);
            d += __shfl_xor_sync(~0u, d, off);
        }
        int r = row0 + tr * 4 + i;
        if (tc == 0 && r < M) {
            g_as2[r] = s;
            g_ad2[r] = d;
        }
    }
}

// ---------------- layer1 gather: one warp per dst node -----------------------
// Accumulates self-loop + CSR neighbors in registers; fused normalize + b1.
__global__ void k_gather1(const float* __restrict__ b1) {
    int w = blockIdx.x * 8 + (threadIdx.x >> 5);
    int lane = threadIdx.x & 31;
    if (w >= NN) return;
    int h = lane & 3;                 // head used for exp computation
    int src_lane = lane >> 3;         // lane holding exp of MY head (lane>>3)
    float my_ad = g_ad1[w * 4 + h];
    float my_as = g_as1[w * 4 + h];
    float e_self = __expf(lrelu(my_as + my_ad));
    float den = e_self;
    float a_self = __shfl_sync(~0u, e_self, src_lane);
    float4 hv = *(const float4*)&g_h1[(size_t)w * 128 + lane * 4];
    float4 acc = make_float4(hv.x * a_self, hv.y * a_self, hv.z * a_self, hv.w * a_self);

    int beg = g_roff[w], end = g_roff[w + 1];
    int i = beg;
    for (; i + 1 < end; i += 2) {
        int s0 = g_csrc[i], s1 = g_csrc[i + 1];
        float e0 = __expf(lrelu(g_as1[s0 * 4 + h] + my_ad));
        float e1 = __expf(lrelu(g_as1[s1 * 4 + h] + my_ad));
        den += e0 + e1;
        float a0 = __shfl_sync(~0u, e0, src_lane);
        float a1 = __shfl_sync(~0u, e1, src_lane);
        float4 h0 = *(const float4*)&g_h1[(size_t)s0 * 128 + lane * 4];
        float4 h1 = *(const float4*)&g_h1[(size_t)s1 * 128 + lane * 4];
        acc.x += h0.x * a0 + h1.x * a1;
        acc.y += h0.y * a0 + h1.y * a1;
        acc.z += h0.z * a0 + h1.z * a1;
        acc.w += h0.w * a0 + h1.w * a1;
    }
    if (i < end) {
        int s0 = g_csrc[i];
        float e0 = __expf(lrelu(g_as1[s0 * 4 + h] + my_ad));
        den += e0;
        float a0 = __shfl_sync(~0u, e0, src_lane);
        float4 h0 = *(const float4*)&g_h1[(size_t)s0 * 128 + lane * 4];
        acc.x += h0.x * a0; acc.y += h0.y * a0;
        acc.z += h0.z * a0; acc.w += h0.w * a0;
    }
    float dtot = __shfl_sync(~0u, den, src_lane);   // all lanes of a head hold same den
    float inv = __frcp_rn(dtot + 1e-16f);
    float4 bb = *(const float4*)&b1[lane * 4];
    float4 o = make_float4(acc.x * inv + bb.x, acc.y * inv + bb.y,
                           acc.z * inv + bb.z, acc.w * inv + bb.w);
    *(float4*)&g_o1[(size_t)w * 128 + lane * 4] = o;
}

// ---------------- layer2 gather: one warp per dst node, 2 edges in flight ----
__global__ void k_gather2(const float* __restrict__ b2, float* __restrict__ out) {
    int w = blockIdx.x * 8 + (threadIdx.x >> 5);
    int lane = threadIdx.x & 31;
    if (w >= NN) return;
    int half = lane >> 4, sl = lane & 15;
    float my_ad = g_ad2[w];
    float my_as = g_as2[w];
    float den = 0.f;
    float4 acc = make_float4(0.f, 0.f, 0.f, 0.f);
    if (half == 0) {
        float e_self = __expf(lrelu(my_as + my_ad));
        den = e_self;
        float4 hv = *(const float4*)&g_h2[(size_t)w * 64 + sl * 4];
        acc = make_float4(hv.x * e_self, hv.y * e_self, hv.z * e_self, hv.w * e_self);
    }
    int beg = g_roff[w], end = g_roff[w + 1];
    for (int i = beg + half; i < end; i += 2) {
        int s = g_csrc[i];
        float e = __expf(lrelu(g_as2[s] + my_ad));
        den += e;
        float4 hv = *(const float4*)&g_h2[(size_t)s * 64 + sl * 4];
        acc.x += hv.x * e; acc.y += hv.y * e;
        acc.z += hv.z * e; acc.w += hv.w * e;
    }
    acc.x += __shfl_xor_sync(~0u, acc.x, 16);
    acc.y += __shfl_xor_sync(~0u, acc.y, 16);
    acc.z += __shfl_xor_sync(~0u, acc.z, 16);
    acc.w += __shfl_xor_sync(~0u, acc.w, 16);
    den += __shfl_xor_sync(~0u, den, 16);
    if (half == 0) {
        float inv = __frcp_rn(den + 1e-16f);
        float4 bb = *(const float4*)&b2[sl * 4];
        float4 o = make_float4(acc.x * inv + bb.x, acc.y * inv + bb.y,
                               acc.z * inv + bb.z, acc.w * inv + bb.w);
        *(float4*)&out[(size_t)w * 64 + sl * 4] = o;
    }
}

// ---------------- launch ----------------------------------------------------
extern "C" void kernel_launch(void* const* d_in, const int* in_sizes, int n_in,
                              void* d_out, int out_size) {
    const float* x    = (const float*)d_in[0];
    const void*  ei   = d_in[1];
    const float* W1   = (const float*)d_in[2];
    const float* as1  = (const float*)d_in[3];
    const float* ad1  = (const float*)d_in[4];
    const float* b1   = (const float*)d_in[5];
    const float* W2   = (const float*)d_in[6];
    const float* as2  = (const float*)d_in[7];
    const float* ad2  = (const float*)d_in[8];
    const float* b2   = (const float*)d_in[9];
    float* out = (float*)d_out;

    float* p_h1;  cudaGetSymbolAddress((void**)&p_h1, g_h1);
    float* p_o1;  cudaGetSymbolAddress((void**)&p_o1, g_o1);
    float* p_h2;  cudaGetSymbolAddress((void**)&p_h2, g_h2);

    k_detect<<<1, 1>>>((const int*)ei);
    k_zero<<<(NN + 255) / 256, 256>>>();
    k_hist<<<(EE + 255) / 256, 256>>>(ei);
    k_scan<<<1, SCAN_T>>>();
    k_scatter<<<(EE + 255) / 256, 256>>>(ei);
    k_gemm1<<<(NN + 63) / 64, 256>>>(x, W1, p_h1, as1, ad1, NN);
    k_gather1<<<(NN + 7) / 8, 256>>>(b1);
    k_gemm2<<<(NN + 63) / 64, 256>>>(p_o1, W2, p_h2, as2, ad2, NN);
    k_gather2<<<(NN + 7) / 8, 256>>>(b2, out);
}

// round 5
// speedup vs baseline: 2.5699x; 1.4073x over previous
#include <cuda_runtime.h>
#include <math.h>

#define NN 100000
#define EE 1600000
#define HC 128         // heads*hidden = 4*32
#define F2 64          // out channels
#define NEG_SLOPE 0.2f
#define NB ((NN + 255) / 256)   // 391 scan blocks

// ---------------- scratch (device globals; no allocation allowed) ----------
__device__ float g_h1[NN * HC];        // x @ W1
__device__ float g_o1[NN * HC];        // layer1 output (normalized + b1)
__device__ float g_h2[NN * F2];        // elu(o1) @ W2
__device__ float g_as1[NN * 4], g_ad1[NN * 4];
__device__ float g_as2[NN], g_ad2[NN];
__device__ int   g_deg[NN];
__device__ int   g_roff[NN + 1];
__device__ int   g_cur[NN];
__device__ int   g_bsum[NB];
__device__ int   g_boff[NB];
__device__ int   g_csrc[EE];           // CSR by dst: source node per slot
__device__ int   g_is64;

// ---------------- helpers ---------------------------------------------------
__device__ __forceinline__ float lrelu(float x) {
    return x > 0.f ? x : NEG_SLOPE * x;
}
__device__ __forceinline__ int clampN(int v) {
    return v < 0 ? 0 : (v >= NN ? NN - 1 : v);
}
__device__ __forceinline__ int edge_src(const void* ei, int i) {
    return clampN(g_is64 ? (int)((const long long*)ei)[i] : ((const int*)ei)[i]);
}
__device__ __forceinline__ int edge_dst(const void* ei, int i) {
    return clampN(g_is64 ? (int)((const long long*)ei)[EE + i] : ((const int*)ei)[EE + i]);
}

// ---------------- dtype detect: int64 edge buffer has zero hi-words ----------
__global__ void k_detect(const int* __restrict__ ei32) {
    int all_zero = 1;
#pragma unroll
    for (int i = 0; i < 8; i++)
        if (ei32[2 * i + 1] != 0) all_zero = 0;
    g_is64 = all_zero;
}

// ---------------- CSR build --------------------------------------------------
__global__ void k_zero() {
    int i = blockIdx.x * blockDim.x + threadIdx.x;
    if (i < NN) g_deg[i] = 0;
}
__global__ void k_hist(const void* __restrict__ ei) {
    int i = blockIdx.x * blockDim.x + threadIdx.x;
    if (i >= EE) return;
    atomicAdd(&g_deg[edge_dst(ei, i)], 1);
}
// phase 1: per-block sums of 256 degrees
__global__ void k_scan1() {
    __shared__ int sh[256];
    int b = blockIdx.x, t = threadIdx.x;
    int i = b * 256 + t;
    sh[t] = (i < NN) ? g_deg[i] : 0;
    __syncthreads();
#pragma unroll
    for (int off = 128; off; off >>= 1) {
        if (t < off) sh[t] += sh[t + off];
        __syncthreads();
    }
    if (t == 0) g_bsum[b] = sh[0];
}
// phase 2: scan block sums (single small block)
__global__ void k_scan2() {
    __shared__ int sh[512];
    int t = threadIdx.x;
    int v = (t < NB) ? g_bsum[t] : 0;
    sh[t] = v;
    __syncthreads();
#pragma unroll
    for (int off = 1; off < 512; off <<= 1) {
        int x = (t >= off) ? sh[t - off] : 0;
        __syncthreads();
        sh[t] += x;
        __syncthreads();
    }
    if (t < NB) g_boff[t] = sh[t] - v;   // exclusive
}
// phase 3: in-block scan + offset -> row offsets
__global__ void k_scan3() {
    __shared__ int sh[256];
    int b = blockIdx.x, t = threadIdx.x;
    int i = b * 256 + t;
    int v = (i < NN) ? g_deg[i] : 0;
    sh[t] = v;
    __syncthreads();
#pragma unroll
    for (int off = 1; off < 256; off <<= 1) {
        int x = (t >= off) ? sh[t - off] : 0;
        __syncthreads();
        sh[t] += x;
        __syncthreads();
    }
    int excl = g_boff[b] + sh[t] - v;
    if (i < NN) {
        g_roff[i] = excl;
        g_cur[i]  = excl;
        if (i == NN - 1) g_roff[NN] = excl + v;
    }
}
__global__ void k_scatter(const void* __restrict__ ei) {
    int i = blockIdx.x * blockDim.x + threadIdx.x;
    if (i >= EE) return;
    int s = edge_src(ei, i);
    int d = edge_dst(ei, i);
    int pos = atomicAdd(&g_cur[d], 1);
    g_csrc[pos] = s;
}

// ---------------- GEMM1: C[M,128] = A[M,128] @ W1 ; fused att1 epilogue ------
__global__ void k_gemm1(const float* __restrict__ A, const float* __restrict__ W,
                        float* __restrict__ C,
                        const float* __restrict__ att_src, const float* __restrict__ att_dst,
                        int M) {
    __shared__ float As[64][16];
    __shared__ float Bs[16][128];
    int tid = threadIdx.x;
    int row0 = blockIdx.x * 64;
    int tr = tid >> 4;
    int tc = tid & 15;
    float acc[4][8];
#pragma unroll
    for (int i = 0; i < 4; i++)
#pragma unroll
        for (int j = 0; j < 8; j++) acc[i][j] = 0.f;

    for (int k0 = 0; k0 < 128; k0 += 16) {
        {
            int r = tid >> 2, kk = (tid & 3) * 4;
            float4 av = make_float4(0.f, 0.f, 0.f, 0.f);
            if (row0 + r < M)
                av = *(const float4*)&A[(size_t)(row0 + r) * 128 + k0 + kk];
            *(float4*)&As[r][kk] = av;
        }
#pragma unroll
        for (int s = 0; s < 2; s++) {
            int p = tid * 4 + s * 1024;
            int bk = p >> 7, bj = p & 127;
            *(float4*)&Bs[bk][bj] = *(const float4*)&W[(size_t)(k0 + bk) * 128 + bj];
        }
        __syncthreads();
#pragma unroll
        for (int kk = 0; kk < 16; kk++) {
            float a[4], b[8];
#pragma unroll
            for (int i = 0; i < 4; i++) a[i] = As[tr * 4 + i][kk];
#pragma unroll
            for (int j = 0; j < 8; j++) b[j] = Bs[kk][tc * 8 + j];
#pragma unroll
            for (int i = 0; i < 4; i++)
#pragma unroll
                for (int j = 0; j < 8; j++) acc[i][j] = fmaf(a[i], b[j], acc[i][j]);
        }
        __syncthreads();
    }
#pragma unroll
    for (int i = 0; i < 4; i++) {
        int r = row0 + tr * 4 + i;
        if (r < M) {
            *(float4*)&C[(size_t)r * 128 + tc * 8]     = make_float4(acc[i][0], acc[i][1], acc[i][2], acc[i][3]);
            *(float4*)&C[(size_t)r * 128 + tc * 8 + 4] = make_float4(acc[i][4], acc[i][5], acc[i][6], acc[i][7]);
        }
    }
    // fused att1: per row, per head hd = tc>>2; reduce over 4 threads (tc&3)
    float avs[8], avd[8];
#pragma unroll
    for (int j = 0; j < 8; j++) {
        avs[j] = att_src[tc * 8 + j];
        avd[j] = att_dst[tc * 8 + j];
    }
    int hd = tc >> 2;
#pragma unroll
    for (int i = 0; i < 4; i++) {
        float s = 0.f, d = 0.f;
#pragma unroll
        for (int j = 0; j < 8; j++) {
            s = fmaf(acc[i][j], avs[j], s);
            d = fmaf(acc[i][j], avd[j], d);
        }
        s += __shfl_xor_sync(~0u, s, 1); s += __shfl_xor_sync(~0u, s, 2);
        d += __shfl_xor_sync(~0u, d, 1); d += __shfl_xor_sync(~0u, d, 2);
        int r = row0 + tr * 4 + i;
        if ((tc & 3) == 0 && r < M) {
            g_as1[r * 4 + hd] = s;
            g_ad1[r * 4 + hd] = d;
        }
    }
}

// ---------------- GEMM2: C[M,64] = elu(A)[M,128] @ W2 ; fused att2 epilogue --
__global__ void k_gemm2(const float* __restrict__ A,
                        const float* __restrict__ W, float* __restrict__ C,
                        const float* __restrict__ att_src, const float* __restrict__ att_dst,
                        int M) {
    __shared__ float As[64][16];
    __shared__ float Bs[16][64];
    int tid = threadIdx.x;
    int row0 = blockIdx.x * 64;
    int tr = tid >> 4;
    int tc = tid & 15;
    float acc[4][4];
#pragma unroll
    for (int i = 0; i < 4; i++)
#pragma unroll
        for (int j = 0; j < 4; j++) acc[i][j] = 0.f;

    for (int k0 = 0; k0 < 128; k0 += 16) {
        {
            int r = tid >> 2, kk = (tid & 3) * 4;
            float4 av = make_float4(0.f, 0.f, 0.f, 0.f);
            if (row0 + r < M) {
                float4 v = *(const float4*)&A[(size_t)(row0 + r) * 128 + k0 + kk];
                av.x = v.x > 0.f ? v.x : expm1f(v.x);
                av.y = v.y > 0.f ? v.y : expm1f(v.y);
                av.z = v.z > 0.f ? v.z : expm1f(v.z);
                av.w = v.w > 0.f ? v.w : expm1f(v.w);
            }
            *(float4*)&As[r][kk] = av;
        }
        {
            int p = tid * 4;
            int bk = p >> 6, bj = p & 63;
            *(float4*)&Bs[bk][bj] = *(const float4*)&W[(size_t)(k0 + bk) * 64 + bj];
        }
        __syncthreads();
#pragma unroll
        for (int kk = 0; kk < 16; kk++) {
            float a[4], b[4];
#pragma unroll
            for (int i = 0; i < 4; i++) a[i] = As[tr * 4 + i][kk];
#pragma unroll
            for (int j = 0; j < 4; j++) b[j] = Bs[kk][tc * 4 + j];
#pragma unroll
            for (int i = 0; i < 4; i++)
#pragma unroll
                for (int j = 0; j < 4; j++) acc[i][j] = fmaf(a[i], b[j], acc[i][j]);
        }
        __syncthreads();
    }
#pragma unroll
    for (int i = 0; i < 4; i++) {
        int r = row0 + tr * 4 + i;
        if (r < M)
            *(float4*)&C[(size_t)r * 64 + tc * 4] = make_float4(acc[i][0], acc[i][1], acc[i][2], acc[i][3]);
    }
    // fused att2: reduce over all 16 tc threads
    float avs[4], avd[4];
#pragma unroll
    for (int j = 0; j < 4; j++) {
        avs[j] = att_src[tc * 4 + j];
        avd[j] = att_dst[tc * 4 + j];
    }
#pragma unroll
    for (int i = 0; i < 4; i++) {
        float s = 0.f, d = 0.f;
#pragma unroll
        for (int j = 0; j < 4; j++) {
            s = fmaf(acc[i][j], avs[j], s);
            d = fmaf(acc[i][j], avd[j], d);
        }
#pragma unroll
        for (int off = 1; off < 16; off <<= 1) {
            s += __shfl_xor_sync(~0u, s, off);
            d += __shfl_xor_sync(~0u, d, off);
        }
        int r = row0 + tr * 4 + i;
        if (tc == 0 && r < M) {
            g_as2[r] = s;
            g_ad2[r] = d;
        }
    }
}

// ---------------- layer1 gather: one warp per dst node -----------------------
__global__ void k_gather1(const float* __restrict__ b1) {
    int w = blockIdx.x * 8 + (threadIdx.x >> 5);
    int lane = threadIdx.x & 31;
    if (w >= NN) return;
    int h = lane & 3;                 // head used for exp computation
    int src_lane = lane >> 3;         // lane holding exp of MY head
    float my_ad = g_ad1[w * 4 + h];
    float my_as = g_as1[w * 4 + h];
    float e_self = __expf(lrelu(my_as + my_ad));
    float den = e_self;
    float a_self = __shfl_sync(~0u, e_self, src_lane);
    float4 hv = *(const float4*)&g_h1[(size_t)w * 128 + lane * 4];
    float4 acc = make_float4(hv.x * a_self, hv.y * a_self, hv.z * a_self, hv.w * a_self);

    int beg = g_roff[w], end = g_roff[w + 1];
    int i = beg;
    for (; i + 1 < end; i += 2) {
        int s0 = g_csrc[i], s1 = g_csrc[i + 1];
        float e0 = __expf(lrelu(g_as1[s0 * 4 + h] + my_ad));
        float e1 = __expf(lrelu(g_as1[s1 * 4 + h] + my_ad));
        den += e0 + e1;
        float a0 = __shfl_sync(~0u, e0, src_lane);
        float a1 = __shfl_sync(~0u, e1, src_lane);
        float4 h0 = *(const float4*)&g_h1[(size_t)s0 * 128 + lane * 4];
        float4 h1 = *(const float4*)&g_h1[(size_t)s1 * 128 + lane * 4];
        acc.x += h0.x * a0 + h1.x * a1;
        acc.y += h0.y * a0 + h1.y * a1;
        acc.z += h0.z * a0 + h1.z * a1;
        acc.w += h0.w * a0 + h1.w * a1;
    }
    if (i < end) {
        int s0 = g_csrc[i];
        float e0 = __expf(lrelu(g_as1[s0 * 4 + h] + my_ad));
        den += e0;
        float a0 = __shfl_sync(~0u, e0, src_lane);
        float4 h0 = *(const float4*)&g_h1[(size_t)s0 * 128 + lane * 4];
        acc.x += h0.x * a0; acc.y += h0.y * a0;
        acc.z += h0.z * a0; acc.w += h0.w * a0;
    }
    float dtot = __shfl_sync(~0u, den, src_lane);
    float inv = __frcp_rn(dtot + 1e-16f);
    float4 bb = *(const float4*)&b1[lane * 4];
    float4 o = make_float4(acc.x * inv + bb.x, acc.y * inv + bb.y,
                           acc.z * inv + bb.z, acc.w * inv + bb.w);
    *(float4*)&g_o1[(size_t)w * 128 + lane * 4] = o;
}

// ---------------- layer2 gather: one warp per dst node, 2 edges in flight ----
__global__ void k_gather2(const float* __restrict__ b2, float* __restrict__ out) {
    int w = blockIdx.x * 8 + (threadIdx.x >> 5);
    int lane = threadIdx.x & 31;
    if (w >= NN) return;
    int half = lane >> 4, sl = lane & 15;
    float my_ad = g_ad2[w];
    float my_as = g_as2[w];
    float den = 0.f;
    float4 acc = make_float4(0.f, 0.f, 0.f, 0.f);
    if (half == 0) {
        float e_self = __expf(lrelu(my_as + my_ad));
        den = e_self;
        float4 hv = *(const float4*)&g_h2[(size_t)w * 64 + sl * 4];
        acc = make_float4(hv.x * e_self, hv.y * e_self, hv.z * e_self, hv.w * e_self);
    }
    int beg = g_roff[w], end = g_roff[w + 1];
    for (int i = beg + half; i < end; i += 2) {
        int s = g_csrc[i];
        float e = __expf(lrelu(g_as2[s] + my_ad));
        den += e;
        float4 hv = *(const float4*)&g_h2[(size_t)s * 64 + sl * 4];
        acc.x += hv.x * e; acc.y += hv.y * e;
        acc.z += hv.z * e; acc.w += hv.w * e;
    }
    acc.x += __shfl_xor_sync(~0u, acc.x, 16);
    acc.y += __shfl_xor_sync(~0u, acc.y, 16);
    acc.z += __shfl_xor_sync(~0u, acc.z, 16);
    acc.w += __shfl_xor_sync(~0u, acc.w, 16);
    den += __shfl_xor_sync(~0u, den, 16);
    if (half == 0) {
        float inv = __frcp_rn(den + 1e-16f);
        float4 bb = *(const float4*)&b2[sl * 4];
        float4 o = make_float4(acc.x * inv + bb.x, acc.y * inv + bb.y,
                               acc.z * inv + bb.z, acc.w * inv + bb.w);
        *(float4*)&out[(size_t)w * 64 + sl * 4] = o;
    }
}

// ---------------- launch ----------------------------------------------------
extern "C" void kernel_launch(void* const* d_in, const int* in_sizes, int n_in,
                              void* d_out, int out_size) {
    const float* x    = (const float*)d_in[0];
    const void*  ei   = d_in[1];
    const float* W1   = (const float*)d_in[2];
    const float* as1  = (const float*)d_in[3];
    const float* ad1  = (const float*)d_in[4];
    const float* b1   = (const float*)d_in[5];
    const float* W2   = (const float*)d_in[6];
    const float* as2  = (const float*)d_in[7];
    const float* ad2  = (const float*)d_in[8];
    const float* b2   = (const float*)d_in[9];
    float* out = (float*)d_out;

    float* p_h1;  cudaGetSymbolAddress((void**)&p_h1, g_h1);
    float* p_o1;  cudaGetSymbolAddress((void**)&p_o1, g_o1);
    float* p_h2;  cudaGetSymbolAddress((void**)&p_h2, g_h2);

    k_detect<<<1, 1>>>((const int*)ei);
    k_zero<<<(NN + 255) / 256, 256>>>();
    k_hist<<<(EE + 255) / 256, 256>>>(ei);
    k_scan1<<<NB, 256>>>();
    k_scan2<<<1, 512>>>();
    k_scan3<<<NB, 256>>>();
    k_scatter<<<(EE + 255) / 256, 256>>>(ei);
    k_gemm1<<<(NN + 63) / 64, 256>>>(x, W1, p_h1, as1, ad1, NN);
    k_gather1<<<(NN + 7) / 8, 256>>>(b1);
    k_gemm2<<<(NN + 63) / 64, 256>>>(p_o1, W2, p_h2, as2, ad2, NN);
    k_gather2<<<(NN + 7) / 8, 256>>>(b2, out);
}

// round 6
// speedup vs baseline: 3.3632x; 1.3087x over previous
#include <cuda_runtime.h>
#include <math.h>

#define NN 100000
#define EE 1600000
#define HC 128         // heads*hidden = 4*32
#define F2 64          // out channels
#define NEG_SLOPE 0.2f
#define NB ((NN + 255) / 256)   // 391 scan blocks

// ---------------- scratch (device globals; no allocation allowed) ----------
__device__ float g_h1[NN * HC];        // x @ W1
__device__ float g_o1[NN * HC];        // layer1 output (normalized + b1)
__device__ float g_h2[NN * F2];        // elu(o1) @ W2
__device__ float g_as1[NN * 4], g_ad1[NN * 4];
__device__ float g_as2[NN], g_ad2[NN];
__device__ int   g_deg[NN];
__device__ int   g_roff[NN + 1];
__device__ int   g_cur[NN];
__device__ int   g_bsum[NB];
__device__ int   g_boff[NB];
__device__ int   g_csrc[EE];           // CSR by dst: source node per slot
__device__ int   g_is64;

// ---------------- helpers ---------------------------------------------------
__device__ __forceinline__ float lrelu(float x) {
    return x > 0.f ? x : NEG_SLOPE * x;
}
__device__ __forceinline__ int clampN(int v) {
    return v < 0 ? 0 : (v >= NN ? NN - 1 : v);
}
__device__ __forceinline__ int edge_src(const void* ei, int i) {
    return clampN(g_is64 ? (int)((const long long*)ei)[i] : ((const int*)ei)[i]);
}
__device__ __forceinline__ int edge_dst(const void* ei, int i) {
    return clampN(g_is64 ? (int)((const long long*)ei)[EE + i] : ((const int*)ei)[EE + i]);
}
__device__ __forceinline__ float to_tf32(float x) {
    float r; asm("cvt.rna.tf32.f32 %0, %1;" : "=f"(r) : "f"(x)); return r;
}
__device__ __forceinline__ void mma_tf32(float* c, unsigned a0, unsigned a1,
                                         unsigned a2, unsigned a3,
                                         unsigned b0, unsigned b1) {
    asm volatile(
        "mma.sync.aligned.m16n8k8.row.col.f32.tf32.tf32.f32 "
        "{%0,%1,%2,%3}, {%4,%5,%6,%7}, {%8,%9}, {%0,%1,%2,%3};"
        : "+f"(c[0]), "+f"(c[1]), "+f"(c[2]), "+f"(c[3])
        : "r"(a0), "r"(a1), "r"(a2), "r"(a3), "r"(b0), "r"(b1));
}

// ---------------- dtype detect: int64 edge buffer has zero hi-words ----------
__global__ void k_detect(const int* __restrict__ ei32) {
    int all_zero = 1;
#pragma unroll
    for (int i = 0; i < 8; i++)
        if (ei32[2 * i + 1] != 0) all_zero = 0;
    g_is64 = all_zero;
}

// ---------------- CSR build --------------------------------------------------
__global__ void k_zero() {
    int i = blockIdx.x * blockDim.x + threadIdx.x;
    if (i < NN) g_deg[i] = 0;
}
__global__ void k_hist(const void* __restrict__ ei) {
    int i = blockIdx.x * blockDim.x + threadIdx.x;
    if (i >= EE) return;
    atomicAdd(&g_deg[edge_dst(ei, i)], 1);
}
__global__ void k_scan1() {
    __shared__ int sh[256];
    int b = blockIdx.x, t = threadIdx.x;
    int i = b * 256 + t;
    sh[t] = (i < NN) ? g_deg[i] : 0;
    __syncthreads();
#pragma unroll
    for (int off = 128; off; off >>= 1) {
        if (t < off) sh[t] += sh[t + off];
        __syncthreads();
    }
    if (t == 0) g_bsum[b] = sh[0];
}
__global__ void k_scan2() {
    __shared__ int sh[512];
    int t = threadIdx.x;
    int v = (t < NB) ? g_bsum[t] : 0;
    sh[t] = v;
    __syncthreads();
#pragma unroll
    for (int off = 1; off < 512; off <<= 1) {
        int x = (t >= off) ? sh[t - off] : 0;
        __syncthreads();
        sh[t] += x;
        __syncthreads();
    }
    if (t < NB) g_boff[t] = sh[t] - v;   // exclusive
}
__global__ void k_scan3() {
    __shared__ int sh[256];
    int b = blockIdx.x, t = threadIdx.x;
    int i = b * 256 + t;
    int v = (i < NN) ? g_deg[i] : 0;
    sh[t] = v;
    __syncthreads();
#pragma unroll
    for (int off = 1; off < 256; off <<= 1) {
        int x = (t >= off) ? sh[t - off] : 0;
        __syncthreads();
        sh[t] += x;
        __syncthreads();
    }
    int excl = g_boff[b] + sh[t] - v;
    if (i < NN) {
        g_roff[i] = excl;
        g_cur[i]  = excl;
        if (i == NN - 1) g_roff[NN] = excl + v;
    }
}
__global__ void k_scatter(const void* __restrict__ ei) {
    int i = blockIdx.x * blockDim.x + threadIdx.x;
    if (i >= EE) return;
    int s = edge_src(ei, i);
    int d = edge_dst(ei, i);
    int pos = atomicAdd(&g_cur[d], 1);
    g_csrc[pos] = s;
}

// ---------------- GEMM1 (tf32 mma): C[M,128] = A[M,128] @ W1[128,128] --------
// 256 thr = 8 warps (4x2). Warp tile 16x64. K chunked by 32.
__global__ void k_gemm1(const float* __restrict__ A, const float* __restrict__ W,
                        float* __restrict__ C, int M) {
    __shared__ float As[64][36];
    __shared__ float Bs[32][132];
    int tid = threadIdx.x;
    int wid = tid >> 5, lane = tid & 31;
    int wm = wid >> 1, wn = wid & 1;
    int g = lane >> 2, t = lane & 3;
    int row0 = blockIdx.x * 64;
    float c[8][4];
#pragma unroll
    for (int i = 0; i < 8; i++)
#pragma unroll
        for (int j = 0; j < 4; j++) c[i][j] = 0.f;

    for (int k0 = 0; k0 < 128; k0 += 32) {
        // stage A 64x32 (tf32-rounded)
#pragma unroll
        for (int s = 0; s < 2; s++) {
            int f = tid + s * 256;           // float4 id (512)
            int r = f >> 3, c4 = (f & 7) * 4;
            float4 v = make_float4(0.f, 0.f, 0.f, 0.f);
            if (row0 + r < M) v = *(const float4*)&A[(size_t)(row0 + r) * 128 + k0 + c4];
            v.x = to_tf32(v.x); v.y = to_tf32(v.y);
            v.z = to_tf32(v.z); v.w = to_tf32(v.w);
            *(float4*)&As[r][c4] = v;
        }
        // stage B 32x128 (tf32-rounded)
#pragma unroll
        for (int s = 0; s < 4; s++) {
            int f = tid + s * 256;           // float4 id (1024)
            int r = f >> 5, c4 = (f & 31) * 4;
            float4 v = *(const float4*)&W[(size_t)(k0 + r) * 128 + c4];
            v.x = to_tf32(v.x); v.y = to_tf32(v.y);
            v.z = to_tf32(v.z); v.w = to_tf32(v.w);
            *(float4*)&Bs[r][c4] = v;
        }
        __syncthreads();
#pragma unroll
        for (int kk = 0; kk < 32; kk += 8) {
            int ar = wm * 16;
            unsigned a0 = __float_as_uint(As[ar + g][kk + t]);
            unsigned a1 = __float_as_uint(As[ar + g + 8][kk + t]);
            unsigned a2 = __float_as_uint(As[ar + g][kk + t + 4]);
            unsigned a3 = __float_as_uint(As[ar + g + 8][kk + t + 4]);
#pragma unroll
            for (int nt = 0; nt < 8; nt++) {
                int n0 = wn * 64 + nt * 8;
                unsigned b0 = __float_as_uint(Bs[kk + t][n0 + g]);
                unsigned b1 = __float_as_uint(Bs[kk + t + 4][n0 + g]);
                mma_tf32(c[nt], a0, a1, a2, a3, b0, b1);
            }
        }
        __syncthreads();
    }
#pragma unroll
    for (int nt = 0; nt < 8; nt++) {
        int col = wn * 64 + nt * 8 + t * 2;
        int r1 = row0 + wm * 16 + g;
        int r2 = r1 + 8;
        if (r1 < M) *(float2*)&C[(size_t)r1 * 128 + col] = make_float2(c[nt][0], c[nt][1]);
        if (r2 < M) *(float2*)&C[(size_t)r2 * 128 + col] = make_float2(c[nt][2], c[nt][3]);
    }
}

// ---------------- GEMM2 (tf32 mma): C[M,64] = elu(A)[M,128] @ W2[128,64] -----
// 256 thr = 8 warps (4x2). Warp tile 16x32. K chunked by 32.
__global__ void k_gemm2(const float* __restrict__ A, const float* __restrict__ W,
                        float* __restrict__ C, int M) {
    __shared__ float As[64][36];
    __shared__ float Bs[32][68];
    int tid = threadIdx.x;
    int wid = tid >> 5, lane = tid & 31;
    int wm = wid >> 1, wn = wid & 1;
    int g = lane >> 2, t = lane & 3;
    int row0 = blockIdx.x * 64;
    float c[4][4];
#pragma unroll
    for (int i = 0; i < 4; i++)
#pragma unroll
        for (int j = 0; j < 4; j++) c[i][j] = 0.f;

    for (int k0 = 0; k0 < 128; k0 += 32) {
        // stage A 64x32 with fused ELU (tf32-rounded)
#pragma unroll
        for (int s = 0; s < 2; s++) {
            int f = tid + s * 256;
            int r = f >> 3, c4 = (f & 7) * 4;
            float4 v = make_float4(0.f, 0.f, 0.f, 0.f);
            if (row0 + r < M) {
                float4 u = *(const float4*)&A[(size_t)(row0 + r) * 128 + k0 + c4];
                v.x = u.x > 0.f ? u.x : expm1f(u.x);
                v.y = u.y > 0.f ? u.y : expm1f(u.y);
                v.z = u.z > 0.f ? u.z : expm1f(u.z);
                v.w = u.w > 0.f ? u.w : expm1f(u.w);
            }
            v.x = to_tf32(v.x); v.y = to_tf32(v.y);
            v.z = to_tf32(v.z); v.w = to_tf32(v.w);
            *(float4*)&As[r][c4] = v;
        }
        // stage B 32x64
#pragma unroll
        for (int s = 0; s < 2; s++) {
            int f = tid + s * 256;           // float4 id (512)
            int r = f >> 4, c4 = (f & 15) * 4;
            float4 v = *(const float4*)&W[(size_t)(k0 + r) * 64 + c4];
            v.x = to_tf32(v.x); v.y = to_tf32(v.y);
            v.z = to_tf32(v.z); v.w = to_tf32(v.w);
            *(float4*)&Bs[r][c4] = v;
        }
        __syncthreads();
#pragma unroll
        for (int kk = 0; kk < 32; kk += 8) {
            int ar = wm * 16;
            unsigned a0 = __float_as_uint(As[ar + g][kk + t]);
            unsigned a1 = __float_as_uint(As[ar + g + 8][kk + t]);
            unsigned a2 = __float_as_uint(As[ar + g][kk + t + 4]);
            unsigned a3 = __float_as_uint(As[ar + g + 8][kk + t + 4]);
#pragma unroll
            for (int nt = 0; nt < 4; nt++) {
                int n0 = wn * 32 + nt * 8;
                unsigned b0 = __float_as_uint(Bs[kk + t][n0 + g]);
                unsigned b1 = __float_as_uint(Bs[kk + t + 4][n0 + g]);
                mma_tf32(c[nt], a0, a1, a2, a3, b0, b1);
            }
        }
        __syncthreads();
    }
#pragma unroll
    for (int nt = 0; nt < 4; nt++) {
        int col = wn * 32 + nt * 8 + t * 2;
        int r1 = row0 + wm * 16 + g;
        int r2 = r1 + 8;
        if (r1 < M) *(float2*)&C[(size_t)r1 * 64 + col] = make_float2(c[nt][0], c[nt][1]);
        if (r2 < M) *(float2*)&C[(size_t)r2 * 64 + col] = make_float2(c[nt][2], c[nt][3]);
    }
}

// ---------------- attention coefficients (layer 1): warp per node ------------
__global__ void k_attc1(const float* __restrict__ att_src, const float* __restrict__ att_dst) {
    int w = blockIdx.x * 8 + (threadIdx.x >> 5);
    int lane = threadIdx.x & 31;
    if (w >= NN) return;
    float4 hv = *(const float4*)&g_h1[(size_t)w * 128 + lane * 4];
    float4 av = *(const float4*)&att_src[lane * 4];
    float4 dv = *(const float4*)&att_dst[lane * 4];
    float s = hv.x * av.x + hv.y * av.y + hv.z * av.z + hv.w * av.w;
    float d = hv.x * dv.x + hv.y * dv.y + hv.z * dv.z + hv.w * dv.w;
    // reduce within 8-lane group (head = lane>>3)
    s += __shfl_xor_sync(~0u, s, 1); d += __shfl_xor_sync(~0u, d, 1);
    s += __shfl_xor_sync(~0u, s, 2); d += __shfl_xor_sync(~0u, d, 2);
    s += __shfl_xor_sync(~0u, s, 4); d += __shfl_xor_sync(~0u, d, 4);
    // head h sum resides in lanes 8h..8h+7; lanes 0..3 fetch heads 0..3
    float sh = __shfl_sync(~0u, s, (lane & 3) << 3);
    float dh = __shfl_sync(~0u, d, (lane & 3) << 3);
    if (lane < 4) {
        g_as1[w * 4 + lane] = sh;
        g_ad1[w * 4 + lane] = dh;
    }
}

// ---------------- attention coefficients (layer 2): warp per node ------------
__global__ void k_attc2(const float* __restrict__ att_src, const float* __restrict__ att_dst) {
    int w = blockIdx.x * 8 + (threadIdx.x >> 5);
    int lane = threadIdx.x & 31;
    if (w >= NN) return;
    float2 hv = *(const float2*)&g_h2[(size_t)w * 64 + lane * 2];
    float2 av = *(const float2*)&att_src[lane * 2];
    float2 dv = *(const float2*)&att_dst[lane * 2];
    float s = hv.x * av.x + hv.y * av.y;
    float d = hv.x * dv.x + hv.y * dv.y;
#pragma unroll
    for (int off = 16; off; off >>= 1) {
        s += __shfl_xor_sync(~0u, s, off);
        d += __shfl_xor_sync(~0u, d, off);
    }
    if (lane == 0) {
        g_as2[w] = s;
        g_ad2[w] = d;
    }
}

// ---------------- layer1 gather: one warp per dst node -----------------------
__global__ void k_gather1(const float* __restrict__ b1) {
    int w = blockIdx.x * 8 + (threadIdx.x >> 5);
    int lane = threadIdx.x & 31;
    if (w >= NN) return;
    int h = lane & 3;                 // head used for exp computation
    int src_lane = lane >> 3;         // lane holding exp of MY head
    float my_ad = g_ad1[w * 4 + h];
    float my_as = g_as1[w * 4 + h];
    float e_self = __expf(lrelu(my_as + my_ad));
    float den = e_self;
    float a_self = __shfl_sync(~0u, e_self, src_lane);
    float4 hv = *(const float4*)&g_h1[(size_t)w * 128 + lane * 4];
    float4 acc = make_float4(hv.x * a_self, hv.y * a_self, hv.z * a_self, hv.w * a_self);

    int beg = g_roff[w], end = g_roff[w + 1];
    int i = beg;
    for (; i + 1 < end; i += 2) {
        int s0 = g_csrc[i], s1 = g_csrc[i + 1];
        float e0 = __expf(lrelu(g_as1[s0 * 4 + h] + my_ad));
        float e1 = __expf(lrelu(g_as1[s1 * 4 + h] + my_ad));
        den += e0 + e1;
        float a0 = __shfl_sync(~0u, e0, src_lane);
        float a1 = __shfl_sync(~0u, e1, src_lane);
        float4 h0 = *(const float4*)&g_h1[(size_t)s0 * 128 + lane * 4];
        float4 h1 = *(const float4*)&g_h1[(size_t)s1 * 128 + lane * 4];
        acc.x += h0.x * a0 + h1.x * a1;
        acc.y += h0.y * a0 + h1.y * a1;
        acc.z += h0.z * a0 + h1.z * a1;
        acc.w += h0.w * a0 + h1.w * a1;
    }
    if (i < end) {
        int s0 = g_csrc[i];
        float e0 = __expf(lrelu(g_as1[s0 * 4 + h] + my_ad));
        den += e0;
        float a0 = __shfl_sync(~0u, e0, src_lane);
        float4 h0 = *(const float4*)&g_h1[(size_t)s0 * 128 + lane * 4];
        acc.x += h0.x * a0; acc.y += h0.y * a0;
        acc.z += h0.z * a0; acc.w += h0.w * a0;
    }
    float dtot = __shfl_sync(~0u, den, src_lane);
    float inv = __frcp_rn(dtot + 1e-16f);
    float4 bb = *(const float4*)&b1[lane * 4];
    float4 o = make_float4(acc.x * inv + bb.x, acc.y * inv + bb.y,
                           acc.z * inv + bb.z, acc.w * inv + bb.w);
    *(float4*)&g_o1[(size_t)w * 128 + lane * 4] = o;
}

// ---------------- layer2 gather: one warp per dst node, 2 edges in flight ----
__global__ void k_gather2(const float* __restrict__ b2, float* __restrict__ out) {
    int w = blockIdx.x * 8 + (threadIdx.x >> 5);
    int lane = threadIdx.x & 31;
    if (w >= NN) return;
    int half = lane >> 4, sl = lane & 15;
    float my_ad = g_ad2[w];
    float my_as = g_as2[w];
    float den = 0.f;
    float4 acc = make_float4(0.f, 0.f, 0.f, 0.f);
    if (half == 0) {
        float e_self = __expf(lrelu(my_as + my_ad));
        den = e_self;
        float4 hv = *(const float4*)&g_h2[(size_t)w * 64 + sl * 4];
        acc = make_float4(hv.x * e_self, hv.y * e_self, hv.z * e_self, hv.w * e_self);
    }
    int beg = g_roff[w], end = g_roff[w + 1];
    for (int i = beg + half; i < end; i += 2) {
        int s = g_csrc[i];
        float e = __expf(lrelu(g_as2[s] + my_ad));
        den += e;
        float4 hv = *(const float4*)&g_h2[(size_t)s * 64 + sl * 4];
        acc.x += hv.x * e; acc.y += hv.y * e;
        acc.z += hv.z * e; acc.w += hv.w * e;
    }
    acc.x += __shfl_xor_sync(~0u, acc.x, 16);
    acc.y += __shfl_xor_sync(~0u, acc.y, 16);
    acc.z += __shfl_xor_sync(~0u, acc.z, 16);
    acc.w += __shfl_xor_sync(~0u, acc.w, 16);
    den += __shfl_xor_sync(~0u, den, 16);
    if (half == 0) {
        float inv = __frcp_rn(den + 1e-16f);
        float4 bb = *(const float4*)&b2[sl * 4];
        float4 o = make_float4(acc.x * inv + bb.x, acc.y * inv + bb.y,
                               acc.z * inv + bb.z, acc.w * inv + bb.w);
        *(float4*)&out[(size_t)w * 64 + sl * 4] = o;
    }
}

// ---------------- launch ----------------------------------------------------
extern "C" void kernel_launch(void* const* d_in, const int* in_sizes, int n_in,
                              void* d_out, int out_size) {
    const float* x    = (const float*)d_in[0];
    const void*  ei   = d_in[1];
    const float* W1   = (const float*)d_in[2];
    const float* as1  = (const float*)d_in[3];
    const float* ad1  = (const float*)d_in[4];
    const float* b1   = (const float*)d_in[5];
    const float* W2   = (const float*)d_in[6];
    const float* as2  = (const float*)d_in[7];
    const float* ad2  = (const float*)d_in[8];
    const float* b2   = (const float*)d_in[9];
    float* out = (float*)d_out;

    float* p_h1;  cudaGetSymbolAddress((void**)&p_h1, g_h1);
    float* p_o1;  cudaGetSymbolAddress((void**)&p_o1, g_o1);
    float* p_h2;  cudaGetSymbolAddress((void**)&p_h2, g_h2);

    k_detect<<<1, 1>>>((const int*)ei);
    k_zero<<<(NN + 255) / 256, 256>>>();
    k_hist<<<(EE + 255) / 256, 256>>>(ei);
    k_scan1<<<NB, 256>>>();
    k_scan2<<<1, 512>>>();
    k_scan3<<<NB, 256>>>();
    k_scatter<<<(EE + 255) / 256, 256>>>(ei);
    k_gemm1<<<(NN + 63) / 64, 256>>>(x, W1, p_h1, NN);
    k_attc1<<<(NN + 7) / 8, 256>>>(as1, ad1);
    k_gather1<<<(NN + 7) / 8, 256>>>(b1);
    k_gemm2<<<(NN + 63) / 64, 256>>>(p_o1, W2, p_h2, NN);
    k_attc2<<<(NN + 7) / 8, 256>>>(as2, ad2);
    k_gather2<<<(NN + 7) / 8, 256>>>(b2, out);
}

// round 7
// speedup vs baseline: 3.7400x; 1.1120x over previous
#include <cuda_runtime.h>
#include <math.h>

#define NN 100000
#define EE 1600000
#define HC 128         // heads*hidden = 4*32
#define F2 64          // out channels
#define NEG_SLOPE 0.2f
#define NB ((NN + 255) / 256)   // 391 scan blocks

// ---------------- scratch (device globals; no allocation allowed) ----------
__device__ float g_h1[NN * HC];        // x @ W1
__device__ float g_o1[NN * HC];        // layer1 output (normalized + b1)
__device__ float g_h2[NN * F2];        // elu(o1) @ W2
__device__ float g_as1[NN * 4], g_ad1[NN * 4];
__device__ float g_as2[NN], g_ad2[NN];
__device__ int   g_deg[NN];
__device__ int   g_roff[NN + 1];
__device__ int   g_cur[NN];
__device__ int   g_bsum[NB];
__device__ int   g_boff[NB];
__device__ int   g_csrc[EE];           // CSR by dst: source node per slot
__device__ int   g_is64;

// ---------------- helpers ---------------------------------------------------
__device__ __forceinline__ float lrelu(float x) {
    return x > 0.f ? x : NEG_SLOPE * x;
}
__device__ __forceinline__ int clampN(int v) {
    return v < 0 ? 0 : (v >= NN ? NN - 1 : v);
}
__device__ __forceinline__ int edge_src(const void* ei, int i) {
    return clampN(g_is64 ? (int)((const long long*)ei)[i] : ((const int*)ei)[i]);
}
__device__ __forceinline__ int edge_dst(const void* ei, int i) {
    return clampN(g_is64 ? (int)((const long long*)ei)[EE + i] : ((const int*)ei)[EE + i]);
}
__device__ __forceinline__ float to_tf32(float x) {
    float r; asm("cvt.rna.tf32.f32 %0, %1;" : "=f"(r) : "f"(x)); return r;
}
__device__ __forceinline__ void mma_tf32(float* c, unsigned a0, unsigned a1,
                                         unsigned a2, unsigned a3,
                                         unsigned b0, unsigned b1) {
    asm volatile(
        "mma.sync.aligned.m16n8k8.row.col.f32.tf32.tf32.f32 "
        "{%0,%1,%2,%3}, {%4,%5,%6,%7}, {%8,%9}, {%0,%1,%2,%3};"
        : "+f"(c[0]), "+f"(c[1]), "+f"(c[2]), "+f"(c[3])
        : "r"(a0), "r"(a1), "r"(a2), "r"(a3), "r"(b0), "r"(b1));
}

// ---------------- dtype detect: int64 edge buffer has zero hi-words ----------
__global__ void k_detect(const int* __restrict__ ei32) {
    int all_zero = 1;
#pragma unroll
    for (int i = 0; i < 8; i++)
        if (ei32[2 * i + 1] != 0) all_zero = 0;
    g_is64 = all_zero;
}

// ---------------- CSR build --------------------------------------------------
__global__ void k_zero() {
    int i = blockIdx.x * blockDim.x + threadIdx.x;
    if (i < NN) g_deg[i] = 0;
}
__global__ void k_hist(const void* __restrict__ ei) {
    int i = blockIdx.x * blockDim.x + threadIdx.x;
    if (i >= EE) return;
    atomicAdd(&g_deg[edge_dst(ei, i)], 1);
}
__global__ void k_scan1() {
    __shared__ int sh[256];
    int b = blockIdx.x, t = threadIdx.x;
    int i = b * 256 + t;
    sh[t] = (i < NN) ? g_deg[i] : 0;
    __syncthreads();
#pragma unroll
    for (int off = 128; off; off >>= 1) {
        if (t < off) sh[t] += sh[t + off];
        __syncthreads();
    }
    if (t == 0) g_bsum[b] = sh[0];
}
__global__ void k_scan2() {
    __shared__ int sh[512];
    int t = threadIdx.x;
    int v = (t < NB) ? g_bsum[t] : 0;
    sh[t] = v;
    __syncthreads();
#pragma unroll
    for (int off = 1; off < 512; off <<= 1) {
        int x = (t >= off) ? sh[t - off] : 0;
        __syncthreads();
        sh[t] += x;
        __syncthreads();
    }
    if (t < NB) g_boff[t] = sh[t] - v;   // exclusive
}
__global__ void k_scan3() {
    __shared__ int sh[256];
    int b = blockIdx.x, t = threadIdx.x;
    int i = b * 256 + t;
    int v = (i < NN) ? g_deg[i] : 0;
    sh[t] = v;
    __syncthreads();
#pragma unroll
    for (int off = 1; off < 256; off <<= 1) {
        int x = (t >= off) ? sh[t - off] : 0;
        __syncthreads();
        sh[t] += x;
        __syncthreads();
    }
    int excl = g_boff[b] + sh[t] - v;
    if (i < NN) {
        g_roff[i] = excl;
        g_cur[i]  = excl;
        if (i == NN - 1) g_roff[NN] = excl + v;
    }
}
__global__ void k_scatter(const void* __restrict__ ei) {
    int i = blockIdx.x * blockDim.x + threadIdx.x;
    if (i >= EE) return;
    int s = edge_src(ei, i);
    int d = edge_dst(ei, i);
    int pos = atomicAdd(&g_cur[d], 1);
    g_csrc[pos] = s;
}

// ---------------- GEMM1 (tf32 mma) + fused att1 epilogue ---------------------
// 256 thr = 8 warps (4x2). Warp tile 16x64. Warp (wm,wn) owns rows wm*16+g(+8)
// and heads {2wn, 2wn+1} disjointly -> quad shfl reduce, no smem.
__global__ void k_gemm1(const float* __restrict__ A, const float* __restrict__ W,
                        float* __restrict__ C,
                        const float* __restrict__ att_src, const float* __restrict__ att_dst,
                        int M) {
    __shared__ float As[64][36];
    __shared__ float Bs[32][132];
    int tid = threadIdx.x;
    int wid = tid >> 5, lane = tid & 31;
    int wm = wid >> 1, wn = wid & 1;
    int g = lane >> 2, t = lane & 3;
    int row0 = blockIdx.x * 64;
    float c[8][4];
#pragma unroll
    for (int i = 0; i < 8; i++)
#pragma unroll
        for (int j = 0; j < 4; j++) c[i][j] = 0.f;

    for (int k0 = 0; k0 < 128; k0 += 32) {
#pragma unroll
        for (int s = 0; s < 2; s++) {
            int f = tid + s * 256;
            int r = f >> 3, c4 = (f & 7) * 4;
            float4 v = make_float4(0.f, 0.f, 0.f, 0.f);
            if (row0 + r < M) v = *(const float4*)&A[(size_t)(row0 + r) * 128 + k0 + c4];
            v.x = to_tf32(v.x); v.y = to_tf32(v.y);
            v.z = to_tf32(v.z); v.w = to_tf32(v.w);
            *(float4*)&As[r][c4] = v;
        }
#pragma unroll
        for (int s = 0; s < 4; s++) {
            int f = tid + s * 256;
            int r = f >> 5, c4 = (f & 31) * 4;
            float4 v = *(const float4*)&W[(size_t)(k0 + r) * 128 + c4];
            v.x = to_tf32(v.x); v.y = to_tf32(v.y);
            v.z = to_tf32(v.z); v.w = to_tf32(v.w);
            *(float4*)&Bs[r][c4] = v;
        }
        __syncthreads();
#pragma unroll
        for (int kk = 0; kk < 32; kk += 8) {
            int ar = wm * 16;
            unsigned a0 = __float_as_uint(As[ar + g][kk + t]);
            unsigned a1 = __float_as_uint(As[ar + g + 8][kk + t]);
            unsigned a2 = __float_as_uint(As[ar + g][kk + t + 4]);
            unsigned a3 = __float_as_uint(As[ar + g + 8][kk + t + 4]);
#pragma unroll
            for (int nt = 0; nt < 8; nt++) {
                int n0 = wn * 64 + nt * 8;
                unsigned b0 = __float_as_uint(Bs[kk + t][n0 + g]);
                unsigned b1 = __float_as_uint(Bs[kk + t + 4][n0 + g]);
                mma_tf32(c[nt], a0, a1, a2, a3, b0, b1);
            }
        }
        __syncthreads();
    }
    int r1 = row0 + wm * 16 + g;
    int r2 = r1 + 8;
#pragma unroll
    for (int nt = 0; nt < 8; nt++) {
        int col = wn * 64 + nt * 8 + t * 2;
        if (r1 < M) *(float2*)&C[(size_t)r1 * 128 + col] = make_float2(c[nt][0], c[nt][1]);
        if (r2 < M) *(float2*)&C[(size_t)r2 * 128 + col] = make_float2(c[nt][2], c[nt][3]);
    }
    // fused att1: heads a=2wn (nt 0..3), b=2wn+1 (nt 4..7)
    float s1a = 0.f, s1b = 0.f, d1a = 0.f, d1b = 0.f;   // row r1
    float s2a = 0.f, s2b = 0.f, d2a = 0.f, d2b = 0.f;   // row r2
#pragma unroll
    for (int nt = 0; nt < 8; nt++) {
        int col = wn * 64 + nt * 8 + t * 2;
        float av0 = att_src[col], av1 = att_src[col + 1];
        float dv0 = att_dst[col], dv1 = att_dst[col + 1];
        float ps1 = c[nt][0] * av0 + c[nt][1] * av1;
        float pd1 = c[nt][0] * dv0 + c[nt][1] * dv1;
        float ps2 = c[nt][2] * av0 + c[nt][3] * av1;
        float pd2 = c[nt][2] * dv0 + c[nt][3] * dv1;
        if (nt < 4) { s1a += ps1; d1a += pd1; s2a += ps2; d2a += pd2; }
        else        { s1b += ps1; d1b += pd1; s2b += ps2; d2b += pd2; }
    }
#pragma unroll
    for (int off = 1; off < 4; off <<= 1) {
        s1a += __shfl_xor_sync(~0u, s1a, off); s1b += __shfl_xor_sync(~0u, s1b, off);
        d1a += __shfl_xor_sync(~0u, d1a, off); d1b += __shfl_xor_sync(~0u, d1b, off);
        s2a += __shfl_xor_sync(~0u, s2a, off); s2b += __shfl_xor_sync(~0u, s2b, off);
        d2a += __shfl_xor_sync(~0u, d2a, off); d2b += __shfl_xor_sync(~0u, d2b, off);
    }
    if (t == 0) {
        int ha = 2 * wn, hb = 2 * wn + 1;
        if (r1 < M) {
            g_as1[r1 * 4 + ha] = s1a; g_as1[r1 * 4 + hb] = s1b;
            g_ad1[r1 * 4 + ha] = d1a; g_ad1[r1 * 4 + hb] = d1b;
        }
        if (r2 < M) {
            g_as1[r2 * 4 + ha] = s2a; g_as1[r2 * 4 + hb] = s2b;
            g_ad1[r2 * 4 + ha] = d2a; g_ad1[r2 * 4 + hb] = d2b;
        }
    }
}

// ---------------- GEMM2 (tf32 mma) + fused att2 epilogue ---------------------
// 256 thr = 8 warps (4x2). Warp tile 16x32. att2 spans both wn warps -> smem.
__global__ void k_gemm2(const float* __restrict__ A, const float* __restrict__ W,
                        float* __restrict__ C,
                        const float* __restrict__ att_src, const float* __restrict__ att_dst,
                        int M) {
    __shared__ float As[64][36];
    __shared__ float Bs[32][68];
    __shared__ float sp[64][2], dp[64][2];
    int tid = threadIdx.x;
    int wid = tid >> 5, lane = tid & 31;
    int wm = wid >> 1, wn = wid & 1;
    int g = lane >> 2, t = lane & 3;
    int row0 = blockIdx.x * 64;
    float c[4][4];
#pragma unroll
    for (int i = 0; i < 4; i++)
#pragma unroll
        for (int j = 0; j < 4; j++) c[i][j] = 0.f;

    for (int k0 = 0; k0 < 128; k0 += 32) {
#pragma unroll
        for (int s = 0; s < 2; s++) {
            int f = tid + s * 256;
            int r = f >> 3, c4 = (f & 7) * 4;
            float4 v = make_float4(0.f, 0.f, 0.f, 0.f);
            if (row0 + r < M) {
                float4 u = *(const float4*)&A[(size_t)(row0 + r) * 128 + k0 + c4];
                v.x = u.x > 0.f ? u.x : expm1f(u.x);
                v.y = u.y > 0.f ? u.y : expm1f(u.y);
                v.z = u.z > 0.f ? u.z : expm1f(u.z);
                v.w = u.w > 0.f ? u.w : expm1f(u.w);
            }
            v.x = to_tf32(v.x); v.y = to_tf32(v.y);
            v.z = to_tf32(v.z); v.w = to_tf32(v.w);
            *(float4*)&As[r][c4] = v;
        }
#pragma unroll
        for (int s = 0; s < 2; s++) {
            int f = tid + s * 256;
            int r = f >> 4, c4 = (f & 15) * 4;
            float4 v = *(const float4*)&W[(size_t)(k0 + r) * 64 + c4];
            v.x = to_tf32(v.x); v.y = to_tf32(v.y);
            v.z = to_tf32(v.z); v.w = to_tf32(v.w);
            *(float4*)&Bs[r][c4] = v;
        }
        __syncthreads();
#pragma unroll
        for (int kk = 0; kk < 32; kk += 8) {
            int ar = wm * 16;
            unsigned a0 = __float_as_uint(As[ar + g][kk + t]);
            unsigned a1 = __float_as_uint(As[ar + g + 8][kk + t]);
            unsigned a2 = __float_as_uint(As[ar + g][kk + t + 4]);
            unsigned a3 = __float_as_uint(As[ar + g + 8][kk + t + 4]);
#pragma unroll
            for (int nt = 0; nt < 4; nt++) {
                int n0 = wn * 32 + nt * 8;
                unsigned b0 = __float_as_uint(Bs[kk + t][n0 + g]);
                unsigned b1 = __float_as_uint(Bs[kk + t + 4][n0 + g]);
                mma_tf32(c[nt], a0, a1, a2, a3, b0, b1);
            }
        }
        __syncthreads();
    }
    int r1 = row0 + wm * 16 + g;
    int r2 = r1 + 8;
    float s1 = 0.f, d1 = 0.f, s2 = 0.f, d2 = 0.f;
#pragma unroll
    for (int nt = 0; nt < 4; nt++) {
        int col = wn * 32 + nt * 8 + t * 2;
        if (r1 < M) *(float2*)&C[(size_t)r1 * 64 + col] = make_float2(c[nt][0], c[nt][1]);
        if (r2 < M) *(float2*)&C[(size_t)r2 * 64 + col] = make_float2(c[nt][2], c[nt][3]);
        float av0 = att_src[col], av1 = att_src[col + 1];
        float dv0 = att_dst[col], dv1 = att_dst[col + 1];
        s1 += c[nt][0] * av0 + c[nt][1] * av1;
        d1 += c[nt][0] * dv0 + c[nt][1] * dv1;
        s2 += c[nt][2] * av0 + c[nt][3] * av1;
        d2 += c[nt][2] * dv0 + c[nt][3] * dv1;
    }
#pragma unroll
    for (int off = 1; off < 4; off <<= 1) {
        s1 += __shfl_xor_sync(~0u, s1, off); d1 += __shfl_xor_sync(~0u, d1, off);
        s2 += __shfl_xor_sync(~0u, s2, off); d2 += __shfl_xor_sync(~0u, d2, off);
    }
    if (t == 0) {
        int rl1 = wm * 16 + g, rl2 = rl1 + 8;
        sp[rl1][wn] = s1; dp[rl1][wn] = d1;
        sp[rl2][wn] = s2; dp[rl2][wn] = d2;
    }
    __syncthreads();
    if (tid < 64 && row0 + tid < M) {
        g_as2[row0 + tid] = sp[tid][0] + sp[tid][1];
        g_ad2[row0 + tid] = dp[tid][0] + dp[tid][1];
    }
}

// ---------------- layer1 gather: warp/node, per-lane own-head exp, unroll 4 --
__global__ void k_gather1(const float* __restrict__ b1) {
    int w = blockIdx.x * 8 + (threadIdx.x >> 5);
    int lane = threadIdx.x & 31;
    if (w >= NN) return;
    int h = lane >> 3;                     // my aggregation head
    float my_ad = g_ad1[w * 4 + h];
    float e_self = __expf(lrelu(g_as1[w * 4 + h] + my_ad));
    float den = e_self;
    float4 hv = *(const float4*)&g_h1[(size_t)w * 128 + lane * 4];
    float4 acc = make_float4(hv.x * e_self, hv.y * e_self, hv.z * e_self, hv.w * e_self);

    int beg = g_roff[w], end = g_roff[w + 1];
    int i = beg;
    for (; i + 3 < end; i += 4) {
        int s0 = g_csrc[i],     s1 = g_csrc[i + 1];
        int s2 = g_csrc[i + 2], s3 = g_csrc[i + 3];
        float e0 = __expf(lrelu(g_as1[s0 * 4 + h] + my_ad));
        float e1 = __expf(lrelu(g_as1[s1 * 4 + h] + my_ad));
        float e2 = __expf(lrelu(g_as1[s2 * 4 + h] + my_ad));
        float e3 = __expf(lrelu(g_as1[s3 * 4 + h] + my_ad));
        den += (e0 + e1) + (e2 + e3);
        float4 h0 = *(const float4*)&g_h1[(size_t)s0 * 128 + lane * 4];
        float4 h1 = *(const float4*)&g_h1[(size_t)s1 * 128 + lane * 4];
        float4 h2 = *(const float4*)&g_h1[(size_t)s2 * 128 + lane * 4];
        float4 h3 = *(const float4*)&g_h1[(size_t)s3 * 128 + lane * 4];
        acc.x += (h0.x * e0 + h1.x * e1) + (h2.x * e2 + h3.x * e3);
        acc.y += (h0.y * e0 + h1.y * e1) + (h2.y * e2 + h3.y * e3);
        acc.z += (h0.z * e0 + h1.z * e1) + (h2.z * e2 + h3.z * e3);
        acc.w += (h0.w * e0 + h1.w * e1) + (h2.w * e2 + h3.w * e3);
    }
    for (; i < end; i++) {
        int s0 = g_csrc[i];
        float e0 = __expf(lrelu(g_as1[s0 * 4 + h] + my_ad));
        den += e0;
        float4 h0 = *(const float4*)&g_h1[(size_t)s0 * 128 + lane * 4];
        acc.x += h0.x * e0; acc.y += h0.y * e0;
        acc.z += h0.z * e0; acc.w += h0.w * e0;
    }
    float inv = __frcp_rn(den + 1e-16f);
    float4 bb = *(const float4*)&b1[lane * 4];
    float4 o = make_float4(acc.x * inv + bb.x, acc.y * inv + bb.y,
                           acc.z * inv + bb.z, acc.w * inv + bb.w);
    *(float4*)&g_o1[(size_t)w * 128 + lane * 4] = o;
}

// ---------------- layer2 gather: warp/node, 2 half-warps x unroll 2 ----------
__global__ void k_gather2(const float* __restrict__ b2, float* __restrict__ out) {
    int w = blockIdx.x * 8 + (threadIdx.x >> 5);
    int lane = threadIdx.x & 31;
    if (w >= NN) return;
    int half = lane >> 4, sl = lane & 15;
    float my_ad = g_ad2[w];
    float den = 0.f;
    float4 acc = make_float4(0.f, 0.f, 0.f, 0.f);
    if (half == 0) {
        float e_self = __expf(lrelu(g_as2[w] + my_ad));
        den = e_self;
        float4 hv = *(const float4*)&g_h2[(size_t)w * 64 + sl * 4];
        acc = make_float4(hv.x * e_self, hv.y * e_self, hv.z * e_self, hv.w * e_self);
    }
    int beg = g_roff[w], end = g_roff[w + 1];
    int i = beg + half;
    for (; i + 2 < end; i += 4) {
        int s0 = g_csrc[i], s1 = g_csrc[i + 2];
        float e0 = __expf(lrelu(g_as2[s0] + my_ad));
        float e1 = __expf(lrelu(g_as2[s1] + my_ad));
        den += e0 + e1;
        float4 h0 = *(const float4*)&g_h2[(size_t)s0 * 64 + sl * 4];
        float4 h1 = *(const float4*)&g_h2[(size_t)s1 * 64 + sl * 4];
        acc.x += h0.x * e0 + h1.x * e1;
        acc.y += h0.y * e0 + h1.y * e1;
        acc.z += h0.z * e0 + h1.z * e1;
        acc.w += h0.w * e0 + h1.w * e1;
    }
    for (; i < end; i += 2) {
        int s0 = g_csrc[i];
        float e0 = __expf(lrelu(g_as2[s0] + my_ad));
        den += e0;
        float4 h0 = *(const float4*)&g_h2[(size_t)s0 * 64 + sl * 4];
        acc.x += h0.x * e0; acc.y += h0.y * e0;
        acc.z += h0.z * e0; acc.w += h0.w * e0;
    }
    acc.x += __shfl_xor_sync(~0u, acc.x, 16);
    acc.y += __shfl_xor_sync(~0u, acc.y, 16);
    acc.z += __shfl_xor_sync(~0u, acc.z, 16);
    acc.w += __shfl_xor_sync(~0u, acc.w, 16);
    den += __shfl_xor_sync(~0u, den, 16);
    if (half == 0) {
        float inv = __frcp_rn(den + 1e-16f);
        float4 bb = *(const float4*)&b2[sl * 4];
        float4 o = make_float4(acc.x * inv + bb.x, acc.y * inv + bb.y,
                               acc.z * inv + bb.z, acc.w * inv + bb.w);
        *(float4*)&out[(size_t)w * 64 + sl * 4] = o;
    }
}

// ---------------- launch ----------------------------------------------------
extern "C" void kernel_launch(void* const* d_in, const int* in_sizes, int n_in,
                              void* d_out, int out_size) {
    const float* x    = (const float*)d_in[0];
    const void*  ei   = d_in[1];
    const float* W1   = (const float*)d_in[2];
    const float* as1  = (const float*)d_in[3];
    const float* ad1  = (const float*)d_in[4];
    const float* b1   = (const float*)d_in[5];
    const float* W2   = (const float*)d_in[6];
    const float* as2  = (const float*)d_in[7];
    const float* ad2  = (const float*)d_in[8];
    const float* b2   = (const float*)d_in[9];
    float* out = (float*)d_out;

    float* p_h1;  cudaGetSymbolAddress((void**)&p_h1, g_h1);
    float* p_o1;  cudaGetSymbolAddress((void**)&p_o1, g_o1);
    float* p_h2;  cudaGetSymbolAddress((void**)&p_h2, g_h2);

    k_detect<<<1, 1>>>((const int*)ei);
    k_zero<<<(NN + 255) / 256, 256>>>();
    k_hist<<<(EE + 255) / 256, 256>>>(ei);
    k_scan1<<<NB, 256>>>();
    k_scan2<<<1, 512>>>();
    k_scan3<<<NB, 256>>>();
    k_scatter<<<(EE + 255) / 256, 256>>>(ei);
    k_gemm1<<<(NN + 63) / 64, 256>>>(x, W1, p_h1, as1, ad1, NN);
    k_gather1<<<(NN + 7) / 8, 256>>>(b1);
    k_gemm2<<<(NN + 63) / 64, 256>>>(p_o1, W2, p_h2, as2, ad2, NN);
    k_gather2<<<(NN + 7) / 8, 256>>>(b2, out);
}

// round 8
// speedup vs baseline: 3.9923x; 1.0675x over previous
#include <cuda_runtime.h>
#include <cuda_fp16.h>
#include <math.h>

#define NN 100000
#define EE 1600000
#define HC 128         // heads*hidden = 4*32
#define F2 64          // out channels
#define NEG_SLOPE 0.2f
#define NB ((NN + 255) / 256)   // 391 scan blocks

// ---------------- scratch (device globals; no allocation allowed) ----------
__device__ __half g_h1[NN * HC];       // x @ W1            (fp16 storage)
__device__ __half g_o1[NN * HC];       // layer1 output     (fp16 storage)
__device__ __half g_h2[NN * F2];       // elu(o1) @ W2      (fp16 storage)
__device__ float  g_as1[NN * 4], g_ad1[NN * 4];
__device__ float  g_as2[NN], g_ad2[NN];
__device__ int    g_deg[NN];
__device__ int    g_roff[NN + 1];
__device__ int    g_cur[NN];
__device__ int    g_bsum[NB];
__device__ int    g_boff[NB];
__device__ int    g_csrc[EE];          // CSR by dst: source node per slot
__device__ int    g_is64;

// ---------------- helpers ---------------------------------------------------
__device__ __forceinline__ float lrelu(float x) {
    return x > 0.f ? x : NEG_SLOPE * x;
}
__device__ __forceinline__ int clampN(int v) {
    return v < 0 ? 0 : (v >= NN ? NN - 1 : v);
}
__device__ __forceinline__ int edge_src(const void* ei, int i) {
    return clampN(g_is64 ? (int)((const long long*)ei)[i] : ((const int*)ei)[i]);
}
__device__ __forceinline__ int edge_dst(const void* ei, int i) {
    return clampN(g_is64 ? (int)((const long long*)ei)[EE + i] : ((const int*)ei)[EE + i]);
}
__device__ __forceinline__ float to_tf32(float x) {
    float r; asm("cvt.rna.tf32.f32 %0, %1;" : "=f"(r) : "f"(x)); return r;
}
__device__ __forceinline__ void mma_tf32(float* c, unsigned a0, unsigned a1,
                                         unsigned a2, unsigned a3,
                                         unsigned b0, unsigned b1) {
    asm volatile(
        "mma.sync.aligned.m16n8k8.row.col.f32.tf32.tf32.f32 "
        "{%0,%1,%2,%3}, {%4,%5,%6,%7}, {%8,%9}, {%0,%1,%2,%3};"
        : "+f"(c[0]), "+f"(c[1]), "+f"(c[2]), "+f"(c[3])
        : "r"(a0), "r"(a1), "r"(a2), "r"(a3), "r"(b0), "r"(b1));
}
// load 4 consecutive halfs (8B aligned) -> float4
__device__ __forceinline__ float4 ldh4(const __half* p) {
    uint2 u = *(const uint2*)p;
    float2 a = __half22float2(*(__half2*)&u.x);
    float2 b = __half22float2(*(__half2*)&u.y);
    return make_float4(a.x, a.y, b.x, b.y);
}
// store float4 -> 4 consecutive halfs (8B aligned)
__device__ __forceinline__ void sth4(__half* p, float4 v) {
    uint2 u;
    *(__half2*)&u.x = __floats2half2_rn(v.x, v.y);
    *(__half2*)&u.y = __floats2half2_rn(v.z, v.w);
    *(uint2*)p = u;
}

// ---------------- dtype detect + degree zero (fused) -------------------------
__global__ void k_detect(const int* __restrict__ ei32) {
    int i = blockIdx.x * blockDim.x + threadIdx.x;
    if (i < NN) g_deg[i] = 0;
    if (i == 0) {
        int all_zero = 1;
#pragma unroll
        for (int k = 0; k < 8; k++)
            if (ei32[2 * k + 1] != 0) all_zero = 0;
        g_is64 = all_zero;
    }
}

// ---------------- CSR build --------------------------------------------------
__global__ void k_hist(const void* __restrict__ ei) {
    int i = blockIdx.x * blockDim.x + threadIdx.x;
    if (i >= EE) return;
    atomicAdd(&g_deg[edge_dst(ei, i)], 1);
}
__global__ void k_scan1() {
    __shared__ int sh[256];
    int b = blockIdx.x, t = threadIdx.x;
    int i = b * 256 + t;
    sh[t] = (i < NN) ? g_deg[i] : 0;
    __syncthreads();
#pragma unroll
    for (int off = 128; off; off >>= 1) {
        if (t < off) sh[t] += sh[t + off];
        __syncthreads();
    }
    if (t == 0) g_bsum[b] = sh[0];
}
__global__ void k_scan2() {
    __shared__ int sh[512];
    int t = threadIdx.x;
    int v = (t < NB) ? g_bsum[t] : 0;
    sh[t] = v;
    __syncthreads();
#pragma unroll
    for (int off = 1; off < 512; off <<= 1) {
        int x = (t >= off) ? sh[t - off] : 0;
        __syncthreads();
        sh[t] += x;
        __syncthreads();
    }
    if (t < NB) g_boff[t] = sh[t] - v;   // exclusive
}
__global__ void k_scan3() {
    __shared__ int sh[256];
    int b = blockIdx.x, t = threadIdx.x;
    int i = b * 256 + t;
    int v = (i < NN) ? g_deg[i] : 0;
    sh[t] = v;
    __syncthreads();
#pragma unroll
    for (int off = 1; off < 256; off <<= 1) {
        int x = (t >= off) ? sh[t - off] : 0;
        __syncthreads();
        sh[t] += x;
        __syncthreads();
    }
    int excl = g_boff[b] + sh[t] - v;
    if (i < NN) {
        g_roff[i] = excl;
        g_cur[i]  = excl;
        if (i == NN - 1) g_roff[NN] = excl + v;
    }
}
__global__ void k_scatter(const void* __restrict__ ei) {
    int i = blockIdx.x * blockDim.x + threadIdx.x;
    if (i >= EE) return;
    int s = edge_src(ei, i);
    int d = edge_dst(ei, i);
    int pos = atomicAdd(&g_cur[d], 1);
    g_csrc[pos] = s;
}

// ---------------- GEMM1 (tf32 mma) + fused att1 epilogue, fp16 C -------------
__global__ void k_gemm1(const float* __restrict__ A, const float* __restrict__ W,
                        __half* __restrict__ C,
                        const float* __restrict__ att_src, const float* __restrict__ att_dst,
                        int M) {
    __shared__ float As[64][36];
    __shared__ float Bs[32][132];
    int tid = threadIdx.x;
    int wid = tid >> 5, lane = tid & 31;
    int wm = wid >> 1, wn = wid & 1;
    int g = lane >> 2, t = lane & 3;
    int row0 = blockIdx.x * 64;
    float c[8][4];
#pragma unroll
    for (int i = 0; i < 8; i++)
#pragma unroll
        for (int j = 0; j < 4; j++) c[i][j] = 0.f;

    for (int k0 = 0; k0 < 128; k0 += 32) {
#pragma unroll
        for (int s = 0; s < 2; s++) {
            int f = tid + s * 256;
            int r = f >> 3, c4 = (f & 7) * 4;
            float4 v = make_float4(0.f, 0.f, 0.f, 0.f);
            if (row0 + r < M) v = *(const float4*)&A[(size_t)(row0 + r) * 128 + k0 + c4];
            v.x = to_tf32(v.x); v.y = to_tf32(v.y);
            v.z = to_tf32(v.z); v.w = to_tf32(v.w);
            *(float4*)&As[r][c4] = v;
        }
#pragma unroll
        for (int s = 0; s < 4; s++) {
            int f = tid + s * 256;
            int r = f >> 5, c4 = (f & 31) * 4;
            float4 v = *(const float4*)&W[(size_t)(k0 + r) * 128 + c4];
            v.x = to_tf32(v.x); v.y = to_tf32(v.y);
            v.z = to_tf32(v.z); v.w = to_tf32(v.w);
            *(float4*)&Bs[r][c4] = v;
        }
        __syncthreads();
#pragma unroll
        for (int kk = 0; kk < 32; kk += 8) {
            int ar = wm * 16;
            unsigned a0 = __float_as_uint(As[ar + g][kk + t]);
            unsigned a1 = __float_as_uint(As[ar + g + 8][kk + t]);
            unsigned a2 = __float_as_uint(As[ar + g][kk + t + 4]);
            unsigned a3 = __float_as_uint(As[ar + g + 8][kk + t + 4]);
#pragma unroll
            for (int nt = 0; nt < 8; nt++) {
                int n0 = wn * 64 + nt * 8;
                unsigned b0 = __float_as_uint(Bs[kk + t][n0 + g]);
                unsigned b1 = __float_as_uint(Bs[kk + t + 4][n0 + g]);
                mma_tf32(c[nt], a0, a1, a2, a3, b0, b1);
            }
        }
        __syncthreads();
    }
    int r1 = row0 + wm * 16 + g;
    int r2 = r1 + 8;
#pragma unroll
    for (int nt = 0; nt < 8; nt++) {
        int col = wn * 64 + nt * 8 + t * 2;
        if (r1 < M) *(__half2*)&C[(size_t)r1 * 128 + col] = __floats2half2_rn(c[nt][0], c[nt][1]);
        if (r2 < M) *(__half2*)&C[(size_t)r2 * 128 + col] = __floats2half2_rn(c[nt][2], c[nt][3]);
    }
    // fused att1: heads a=2wn (nt 0..3), b=2wn+1 (nt 4..7)
    float s1a = 0.f, s1b = 0.f, d1a = 0.f, d1b = 0.f;
    float s2a = 0.f, s2b = 0.f, d2a = 0.f, d2b = 0.f;
#pragma unroll
    for (int nt = 0; nt < 8; nt++) {
        int col = wn * 64 + nt * 8 + t * 2;
        float av0 = att_src[col], av1 = att_src[col + 1];
        float dv0 = att_dst[col], dv1 = att_dst[col + 1];
        float ps1 = c[nt][0] * av0 + c[nt][1] * av1;
        float pd1 = c[nt][0] * dv0 + c[nt][1] * dv1;
        float ps2 = c[nt][2] * av0 + c[nt][3] * av1;
        float pd2 = c[nt][2] * dv0 + c[nt][3] * dv1;
        if (nt < 4) { s1a += ps1; d1a += pd1; s2a += ps2; d2a += pd2; }
        else        { s1b += ps1; d1b += pd1; s2b += ps2; d2b += pd2; }
    }
#pragma unroll
    for (int off = 1; off < 4; off <<= 1) {
        s1a += __shfl_xor_sync(~0u, s1a, off); s1b += __shfl_xor_sync(~0u, s1b, off);
        d1a += __shfl_xor_sync(~0u, d1a, off); d1b += __shfl_xor_sync(~0u, d1b, off);
        s2a += __shfl_xor_sync(~0u, s2a, off); s2b += __shfl_xor_sync(~0u, s2b, off);
        d2a += __shfl_xor_sync(~0u, d2a, off); d2b += __shfl_xor_sync(~0u, d2b, off);
    }
    if (t == 0) {
        int ha = 2 * wn, hb = 2 * wn + 1;
        if (r1 < M) {
            g_as1[r1 * 4 + ha] = s1a; g_as1[r1 * 4 + hb] = s1b;
            g_ad1[r1 * 4 + ha] = d1a; g_ad1[r1 * 4 + hb] = d1b;
        }
        if (r2 < M) {
            g_as1[r2 * 4 + ha] = s2a; g_as1[r2 * 4 + hb] = s2b;
            g_ad1[r2 * 4 + ha] = d2a; g_ad1[r2 * 4 + hb] = d2b;
        }
    }
}

// ---------------- GEMM2 (tf32 mma, fp16 A/C) + fused att2 epilogue -----------
__global__ void k_gemm2(const __half* __restrict__ A, const float* __restrict__ W,
                        __half* __restrict__ C,
                        const float* __restrict__ att_src, const float* __restrict__ att_dst,
                        int M) {
    __shared__ float As[64][36];
    __shared__ float Bs[32][68];
    __shared__ float sp[64][2], dp[64][2];
    int tid = threadIdx.x;
    int wid = tid >> 5, lane = tid & 31;
    int wm = wid >> 1, wn = wid & 1;
    int g = lane >> 2, t = lane & 3;
    int row0 = blockIdx.x * 64;
    float c[4][4];
#pragma unroll
    for (int i = 0; i < 4; i++)
#pragma unroll
        for (int j = 0; j < 4; j++) c[i][j] = 0.f;

    for (int k0 = 0; k0 < 128; k0 += 32) {
#pragma unroll
        for (int s = 0; s < 2; s++) {
            int f = tid + s * 256;
            int r = f >> 3, c4 = (f & 7) * 4;
            float4 v = make_float4(0.f, 0.f, 0.f, 0.f);
            if (row0 + r < M) {
                float4 u = ldh4(&A[(size_t)(row0 + r) * 128 + k0 + c4]);
                v.x = u.x > 0.f ? u.x : expm1f(u.x);
                v.y = u.y > 0.f ? u.y : expm1f(u.y);
                v.z = u.z > 0.f ? u.z : expm1f(u.z);
                v.w = u.w > 0.f ? u.w : expm1f(u.w);
            }
            v.x = to_tf32(v.x); v.y = to_tf32(v.y);
            v.z = to_tf32(v.z); v.w = to_tf32(v.w);
            *(float4*)&As[r][c4] = v;
        }
#pragma unroll
        for (int s = 0; s < 2; s++) {
            int f = tid + s * 256;
            int r = f >> 4, c4 = (f & 15) * 4;
            float4 v = *(const float4*)&W[(size_t)(k0 + r) * 64 + c4];
            v.x = to_tf32(v.x); v.y = to_tf32(v.y);
            v.z = to_tf32(v.z); v.w = to_tf32(v.w);
            *(float4*)&Bs[r][c4] = v;
        }
        __syncthreads();
#pragma unroll
        for (int kk = 0; kk < 32; kk += 8) {
            int ar = wm * 16;
            unsigned a0 = __float_as_uint(As[ar + g][kk + t]);
            unsigned a1 = __float_as_uint(As[ar + g + 8][kk + t]);
            unsigned a2 = __float_as_uint(As[ar + g][kk + t + 4]);
            unsigned a3 = __float_as_uint(As[ar + g + 8][kk + t + 4]);
#pragma unroll
            for (int nt = 0; nt < 4; nt++) {
                int n0 = wn * 32 + nt * 8;
                unsigned b0 = __float_as_uint(Bs[kk + t][n0 + g]);
                unsigned b1 = __float_as_uint(Bs[kk + t + 4][n0 + g]);
                mma_tf32(c[nt], a0, a1, a2, a3, b0, b1);
            }
        }
        __syncthreads();
    }
    int r1 = row0 + wm * 16 + g;
    int r2 = r1 + 8;
    float s1 = 0.f, d1 = 0.f, s2 = 0.f, d2 = 0.f;
#pragma unroll
    for (int nt = 0; nt < 4; nt++) {
        int col = wn * 32 + nt * 8 + t * 2;
        if (r1 < M) *(__half2*)&C[(size_t)r1 * 64 + col] = __floats2half2_rn(c[nt][0], c[nt][1]);
        if (r2 < M) *(__half2*)&C[(size_t)r2 * 64 + col] = __floats2half2_rn(c[nt][2], c[nt][3]);
        float av0 = att_src[col], av1 = att_src[col + 1];
        float dv0 = att_dst[col], dv1 = att_dst[col + 1];
        s1 += c[nt][0] * av0 + c[nt][1] * av1;
        d1 += c[nt][0] * dv0 + c[nt][1] * dv1;
        s2 += c[nt][2] * av0 + c[nt][3] * av1;
        d2 += c[nt][2] * dv0 + c[nt][3] * dv1;
    }
#pragma unroll
    for (int off = 1; off < 4; off <<= 1) {
        s1 += __shfl_xor_sync(~0u, s1, off); d1 += __shfl_xor_sync(~0u, d1, off);
        s2 += __shfl_xor_sync(~0u, s2, off); d2 += __shfl_xor_sync(~0u, d2, off);
    }
    if (t == 0) {
        int rl1 = wm * 16 + g, rl2 = rl1 + 8;
        sp[rl1][wn] = s1; dp[rl1][wn] = d1;
        sp[rl2][wn] = s2; dp[rl2][wn] = d2;
    }
    __syncthreads();
    if (tid < 64 && row0 + tid < M) {
        g_as2[row0 + tid] = sp[tid][0] + sp[tid][1];
        g_ad2[row0 + tid] = dp[tid][0] + dp[tid][1];
    }
}

// ---------------- layer1 gather: warp/node, fp16 rows, unroll 4 --------------
__global__ void k_gather1(const float* __restrict__ b1) {
    int w = blockIdx.x * 8 + (threadIdx.x >> 5);
    int lane = threadIdx.x & 31;
    if (w >= NN) return;
    int h = lane >> 3;                     // my aggregation head
    float my_ad = g_ad1[w * 4 + h];
    float e_self = __expf(lrelu(g_as1[w * 4 + h] + my_ad));
    float den = e_self;
    float4 hv = ldh4(&g_h1[(size_t)w * 128 + lane * 4]);
    float4 acc = make_float4(hv.x * e_self, hv.y * e_self, hv.z * e_self, hv.w * e_self);

    int beg = g_roff[w], end = g_roff[w + 1];
    int i = beg;
    for (; i + 3 < end; i += 4) {
        int s0 = g_csrc[i],     s1 = g_csrc[i + 1];
        int s2 = g_csrc[i + 2], s3 = g_csrc[i + 3];
        float e0 = __expf(lrelu(g_as1[s0 * 4 + h] + my_ad));
        float e1 = __expf(lrelu(g_as1[s1 * 4 + h] + my_ad));
        float e2 = __expf(lrelu(g_as1[s2 * 4 + h] + my_ad));
        float e3 = __expf(lrelu(g_as1[s3 * 4 + h] + my_ad));
        den += (e0 + e1) + (e2 + e3);
        float4 h0 = ldh4(&g_h1[(size_t)s0 * 128 + lane * 4]);
        float4 h1 = ldh4(&g_h1[(size_t)s1 * 128 + lane * 4]);
        float4 h2 = ldh4(&g_h1[(size_t)s2 * 128 + lane * 4]);
        float4 h3 = ldh4(&g_h1[(size_t)s3 * 128 + lane * 4]);
        acc.x += (h0.x * e0 + h1.x * e1) + (h2.x * e2 + h3.x * e3);
        acc.y += (h0.y * e0 + h1.y * e1) + (h2.y * e2 + h3.y * e3);
        acc.z += (h0.z * e0 + h1.z * e1) + (h2.z * e2 + h3.z * e3);
        acc.w += (h0.w * e0 + h1.w * e1) + (h2.w * e2 + h3.w * e3);
    }
    for (; i < end; i++) {
        int s0 = g_csrc[i];
        float e0 = __expf(lrelu(g_as1[s0 * 4 + h] + my_ad));
        den += e0;
        float4 h0 = ldh4(&g_h1[(size_t)s0 * 128 + lane * 4]);
        acc.x += h0.x * e0; acc.y += h0.y * e0;
        acc.z += h0.z * e0; acc.w += h0.w * e0;
    }
    float inv = __frcp_rn(den + 1e-16f);
    float4 bb = *(const float4*)&b1[lane * 4];
    float4 o = make_float4(acc.x * inv + bb.x, acc.y * inv + bb.y,
                           acc.z * inv + bb.z, acc.w * inv + bb.w);
    sth4(&g_o1[(size_t)w * 128 + lane * 4], o);
}

// ---------------- layer2 gather: warp/node, 2 half-warps, fp16 rows ----------
__global__ void k_gather2(const float* __restrict__ b2, float* __restrict__ out) {
    int w = blockIdx.x * 8 + (threadIdx.x >> 5);
    int lane = threadIdx.x & 31;
    if (w >= NN) return;
    int half = lane >> 4, sl = lane & 15;
    float my_ad = g_ad2[w];
    float den = 0.f;
    float4 acc = make_float4(0.f, 0.f, 0.f, 0.f);
    if (half == 0) {
        float e_self = __expf(lrelu(g_as2[w] + my_ad));
        den = e_self;
        float4 hv = ldh4(&g_h2[(size_t)w * 64 + sl * 4]);
        acc = make_float4(hv.x * e_self, hv.y * e_self, hv.z * e_self, hv.w * e_self);
    }
    int beg = g_roff[w], end = g_roff[w + 1];
    int i = beg + half;
    for (; i + 2 < end; i += 4) {
        int s0 = g_csrc[i], s1 = g_csrc[i + 2];
        float e0 = __expf(lrelu(g_as2[s0] + my_ad));
        float e1 = __expf(lrelu(g_as2[s1] + my_ad));
        den += e0 + e1;
        float4 h0 = ldh4(&g_h2[(size_t)s0 * 64 + sl * 4]);
        float4 h1 = ldh4(&g_h2[(size_t)s1 * 64 + sl * 4]);
        acc.x += h0.x * e0 + h1.x * e1;
        acc.y += h0.y * e0 + h1.y * e1;
        acc.z += h0.z * e0 + h1.z * e1;
        acc.w += h0.w * e0 + h1.w * e1;
    }
    for (; i < end; i += 2) {
        int s0 = g_csrc[i];
        float e0 = __expf(lrelu(g_as2[s0] + my_ad));
        den += e0;
        float4 h0 = ldh4(&g_h2[(size_t)s0 * 64 + sl * 4]);
        acc.x += h0.x * e0; acc.y += h0.y * e0;
        acc.z += h0.z * e0; acc.w += h0.w * e0;
    }
    acc.x += __shfl_xor_sync(~0u, acc.x, 16);
    acc.y += __shfl_xor_sync(~0u, acc.y, 16);
    acc.z += __shfl_xor_sync(~0u, acc.z, 16);
    acc.w += __shfl_xor_sync(~0u, acc.w, 16);
    den += __shfl_xor_sync(~0u, den, 16);
    if (half == 0) {
        float inv = __frcp_rn(den + 1e-16f);
        float4 bb = *(const float4*)&b2[sl * 4];
        float4 o = make_float4(acc.x * inv + bb.x, acc.y * inv + bb.y,
                               acc.z * inv + bb.z, acc.w * inv + bb.w);
        *(float4*)&out[(size_t)w * 64 + sl * 4] = o;
    }
}

// ---------------- launch ----------------------------------------------------
extern "C" void kernel_launch(void* const* d_in, const int* in_sizes, int n_in,
                              void* d_out, int out_size) {
    const float* x    = (const float*)d_in[0];
    const void*  ei   = d_in[1];
    const float* W1   = (const float*)d_in[2];
    const float* as1  = (const float*)d_in[3];
    const float* ad1  = (const float*)d_in[4];
    const float* b1   = (const float*)d_in[5];
    const float* W2   = (const float*)d_in[6];
    const float* as2  = (const float*)d_in[7];
    const float* ad2  = (const float*)d_in[8];
    const float* b2   = (const float*)d_in[9];
    float* out = (float*)d_out;

    __half* p_h1;  cudaGetSymbolAddress((void**)&p_h1, g_h1);
    __half* p_o1;  cudaGetSymbolAddress((void**)&p_o1, g_o1);
    __half* p_h2;  cudaGetSymbolAddress((void**)&p_h2, g_h2);

    k_detect<<<(NN + 255) / 256, 256>>>((const int*)ei);
    k_hist<<<(EE + 255) / 256, 256>>>(ei);
    k_scan1<<<NB, 256>>>();
    k_scan2<<<1, 512>>>();
    k_scan3<<<NB, 256>>>();
    k_scatter<<<(EE + 255) / 256, 256>>>(ei);
    k_gemm1<<<(NN + 63) / 64, 256>>>(x, W1, p_h1, as1, ad1, NN);
    k_gather1<<<(NN + 7) / 8, 256>>>(b1);
    k_gemm2<<<(NN + 63) / 64, 256>>>(p_o1, W2, p_h2, as2, ad2, NN);
    k_gather2<<<(NN + 7) / 8, 256>>>(b2, out);
}

// round 9
// speedup vs baseline: 4.1423x; 1.0376x over previous
#include <cuda_runtime.h>
#include <cuda_fp16.h>
#include <math.h>

#define NN 100000
#define EE 1600000
#define HC 128         // heads*hidden = 4*32
#define F2 64          // out channels
#define NEG_SLOPE 0.2f
#define NB ((NN + 255) / 256)   // 391 scan blocks

// ---------------- scratch (device globals; no allocation allowed) ----------
__device__ __half g_h1[NN * HC];       // x @ W1            (fp16 storage)
__device__ __half g_o1[NN * HC];       // layer1 output     (fp16 storage)
__device__ __half g_h2[NN * F2];       // elu(o1) @ W2      (fp16 storage)
__device__ float  g_as1[NN * 4], g_ad1[NN * 4];
__device__ float  g_as2[NN], g_ad2[NN];
__device__ int    g_esrc[EE], g_edst[EE];   // int32 edge copy
__device__ int    g_deg[NN];
__device__ int    g_roff[NN + 1];
__device__ int    g_cur[NN];
__device__ int    g_bsum[NB];
__device__ int    g_boff[NB];
__device__ int    g_csrc[EE];          // CSR by dst: source node per slot
__device__ int    g_is64;

// ---------------- helpers ---------------------------------------------------
__device__ __forceinline__ float lrelu(float x) {
    return x > 0.f ? x : NEG_SLOPE * x;
}
__device__ __forceinline__ int clampN(int v) {
    return v < 0 ? 0 : (v >= NN ? NN - 1 : v);
}
__device__ __forceinline__ float to_tf32(float x) {
    float r; asm("cvt.rna.tf32.f32 %0, %1;" : "=f"(r) : "f"(x)); return r;
}
__device__ __forceinline__ void mma_tf32(float* c, unsigned a0, unsigned a1,
                                         unsigned a2, unsigned a3,
                                         unsigned b0, unsigned b1) {
    asm volatile(
        "mma.sync.aligned.m16n8k8.row.col.f32.tf32.tf32.f32 "
        "{%0,%1,%2,%3}, {%4,%5,%6,%7}, {%8,%9}, {%0,%1,%2,%3};"
        : "+f"(c[0]), "+f"(c[1]), "+f"(c[2]), "+f"(c[3])
        : "r"(a0), "r"(a1), "r"(a2), "r"(a3), "r"(b0), "r"(b1));
}
__device__ __forceinline__ float4 ldh4(const __half* p) {
    uint2 u = *(const uint2*)p;
    float2 a = __half22float2(*(__half2*)&u.x);
    float2 b = __half22float2(*(__half2*)&u.y);
    return make_float4(a.x, a.y, b.x, b.y);
}
__device__ __forceinline__ void sth4(__half* p, float4 v) {
    uint2 u;
    *(__half2*)&u.x = __floats2half2_rn(v.x, v.y);
    *(__half2*)&u.y = __floats2half2_rn(v.z, v.w);
    *(uint2*)p = u;
}

// ---------------- dtype detect + degree zero (fused) -------------------------
__global__ void k_detect(const int* __restrict__ ei32) {
    int i = blockIdx.x * blockDim.x + threadIdx.x;
    if (i < NN) g_deg[i] = 0;
    if (i == 0) {
        int all_zero = 1;
#pragma unroll
        for (int k = 0; k < 8; k++)
            if (ei32[2 * k + 1] != 0) all_zero = 0;
        g_is64 = all_zero;
    }
}

// ---------------- edge convert (int64/int32 -> int32) + histogram ------------
__global__ void k_prep(const void* __restrict__ ei) {
    int i = blockIdx.x * blockDim.x + threadIdx.x;
    if (i >= EE) return;
    int s, d;
    if (g_is64) {
        const long long* p = (const long long*)ei;
        s = (int)p[i]; d = (int)p[EE + i];
    } else {
        const int* p = (const int*)ei;
        s = p[i]; d = p[EE + i];
    }
    s = clampN(s); d = clampN(d);
    g_esrc[i] = s;
    g_edst[i] = d;
    atomicAdd(&g_deg[d], 1);
}

// ---------------- CSR scan + scatter -----------------------------------------
__global__ void k_scan1() {
    __shared__ int sh[256];
    int b = blockIdx.x, t = threadIdx.x;
    int i = b * 256 + t;
    sh[t] = (i < NN) ? g_deg[i] : 0;
    __syncthreads();
#pragma unroll
    for (int off = 128; off; off >>= 1) {
        if (t < off) sh[t] += sh[t + off];
        __syncthreads();
    }
    if (t == 0) g_bsum[b] = sh[0];
}
__global__ void k_scan2() {
    __shared__ int sh[512];
    int t = threadIdx.x;
    int v = (t < NB) ? g_bsum[t] : 0;
    sh[t] = v;
    __syncthreads();
#pragma unroll
    for (int off = 1; off < 512; off <<= 1) {
        int x = (t >= off) ? sh[t - off] : 0;
        __syncthreads();
        sh[t] += x;
        __syncthreads();
    }
    if (t < NB) g_boff[t] = sh[t] - v;   // exclusive
}
__global__ void k_scan3() {
    __shared__ int sh[256];
    int b = blockIdx.x, t = threadIdx.x;
    int i = b * 256 + t;
    int v = (i < NN) ? g_deg[i] : 0;
    sh[t] = v;
    __syncthreads();
#pragma unroll
    for (int off = 1; off < 256; off <<= 1) {
        int x = (t >= off) ? sh[t - off] : 0;
        __syncthreads();
        sh[t] += x;
        __syncthreads();
    }
    int excl = g_boff[b] + sh[t] - v;
    if (i < NN) {
        g_roff[i] = excl;
        g_cur[i]  = excl;
        if (i == NN - 1) g_roff[NN] = excl + v;
    }
}
__global__ void k_scatter() {
    int i = blockIdx.x * blockDim.x + threadIdx.x;
    if (i >= EE) return;
    int s = g_esrc[i];
    int d = g_edst[i];
    int pos = atomicAdd(&g_cur[d], 1);
    g_csrc[pos] = s;
}

// ---------------- GEMM1 (tf32 mma) + fused att1 epilogue, fp16 C -------------
__global__ void k_gemm1(const float* __restrict__ A, const float* __restrict__ W,
                        __half* __restrict__ C,
                        const float* __restrict__ att_src, const float* __restrict__ att_dst,
                        int M) {
    __shared__ float As[64][36];
    __shared__ float Bs[32][132];
    int tid = threadIdx.x;
    int wid = tid >> 5, lane = tid & 31;
    int wm = wid >> 1, wn = wid & 1;
    int g = lane >> 2, t = lane & 3;
    int row0 = blockIdx.x * 64;
    float c[8][4];
#pragma unroll
    for (int i = 0; i < 8; i++)
#pragma unroll
        for (int j = 0; j < 4; j++) c[i][j] = 0.f;

    for (int k0 = 0; k0 < 128; k0 += 32) {
#pragma unroll
        for (int s = 0; s < 2; s++) {
            int f = tid + s * 256;
            int r = f >> 3, c4 = (f & 7) * 4;
            float4 v = make_float4(0.f, 0.f, 0.f, 0.f);
            if (row0 + r < M) v = *(const float4*)&A[(size_t)(row0 + r) * 128 + k0 + c4];
            v.x = to_tf32(v.x); v.y = to_tf32(v.y);
            v.z = to_tf32(v.z); v.w = to_tf32(v.w);
            *(float4*)&As[r][c4] = v;
        }
#pragma unroll
        for (int s = 0; s < 4; s++) {
            int f = tid + s * 256;
            int r = f >> 5, c4 = (f & 31) * 4;
            float4 v = *(const float4*)&W[(size_t)(k0 + r) * 128 + c4];
            v.x = to_tf32(v.x); v.y = to_tf32(v.y);
            v.z = to_tf32(v.z); v.w = to_tf32(v.w);
            *(float4*)&Bs[r][c4] = v;
        }
        __syncthreads();
#pragma unroll
        for (int kk = 0; kk < 32; kk += 8) {
            int ar = wm * 16;
            unsigned a0 = __float_as_uint(As[ar + g][kk + t]);
            unsigned a1 = __float_as_uint(As[ar + g + 8][kk + t]);
            unsigned a2 = __float_as_uint(As[ar + g][kk + t + 4]);
            unsigned a3 = __float_as_uint(As[ar + g + 8][kk + t + 4]);
#pragma unroll
            for (int nt = 0; nt < 8; nt++) {
                int n0 = wn * 64 + nt * 8;
                unsigned b0 = __float_as_uint(Bs[kk + t][n0 + g]);
                unsigned b1 = __float_as_uint(Bs[kk + t + 4][n0 + g]);
                mma_tf32(c[nt], a0, a1, a2, a3, b0, b1);
            }
        }
        __syncthreads();
    }
    int r1 = row0 + wm * 16 + g;
    int r2 = r1 + 8;
#pragma unroll
    for (int nt = 0; nt < 8; nt++) {
        int col = wn * 64 + nt * 8 + t * 2;
        if (r1 < M) *(__half2*)&C[(size_t)r1 * 128 + col] = __floats2half2_rn(c[nt][0], c[nt][1]);
        if (r2 < M) *(__half2*)&C[(size_t)r2 * 128 + col] = __floats2half2_rn(c[nt][2], c[nt][3]);
    }
    float s1a = 0.f, s1b = 0.f, d1a = 0.f, d1b = 0.f;
    float s2a = 0.f, s2b = 0.f, d2a = 0.f, d2b = 0.f;
#pragma unroll
    for (int nt = 0; nt < 8; nt++) {
        int col = wn * 64 + nt * 8 + t * 2;
        float av0 = att_src[col], av1 = att_src[col + 1];
        float dv0 = att_dst[col], dv1 = att_dst[col + 1];
        float ps1 = c[nt][0] * av0 + c[nt][1] * av1;
        float pd1 = c[nt][0] * dv0 + c[nt][1] * dv1;
        float ps2 = c[nt][2] * av0 + c[nt][3] * av1;
        float pd2 = c[nt][2] * dv0 + c[nt][3] * dv1;
        if (nt < 4) { s1a += ps1; d1a += pd1; s2a += ps2; d2a += pd2; }
        else        { s1b += ps1; d1b += pd1; s2b += ps2; d2b += pd2; }
    }
#pragma unroll
    for (int off = 1; off < 4; off <<= 1) {
        s1a += __shfl_xor_sync(~0u, s1a, off); s1b += __shfl_xor_sync(~0u, s1b, off);
        d1a += __shfl_xor_sync(~0u, d1a, off); d1b += __shfl_xor_sync(~0u, d1b, off);
        s2a += __shfl_xor_sync(~0u, s2a, off); s2b += __shfl_xor_sync(~0u, s2b, off);
        d2a += __shfl_xor_sync(~0u, d2a, off); d2b += __shfl_xor_sync(~0u, d2b, off);
    }
    if (t == 0) {
        int ha = 2 * wn, hb = 2 * wn + 1;
        if (r1 < M) {
            g_as1[r1 * 4 + ha] = s1a; g_as1[r1 * 4 + hb] = s1b;
            g_ad1[r1 * 4 + ha] = d1a; g_ad1[r1 * 4 + hb] = d1b;
        }
        if (r2 < M) {
            g_as1[r2 * 4 + ha] = s2a; g_as1[r2 * 4 + hb] = s2b;
            g_ad1[r2 * 4 + ha] = d2a; g_ad1[r2 * 4 + hb] = d2b;
        }
    }
}

// ---------------- GEMM2 (tf32 mma, fp16 A/C) + fused att2 epilogue -----------
__global__ void k_gemm2(const __half* __restrict__ A, const float* __restrict__ W,
                        __half* __restrict__ C,
                        const float* __restrict__ att_src, const float* __restrict__ att_dst,
                        int M) {
    __shared__ float As[64][36];
    __shared__ float Bs[32][68];
    __shared__ float sp[64][2], dp[64][2];
    int tid = threadIdx.x;
    int wid = tid >> 5, lane = tid & 31;
    int wm = wid >> 1, wn = wid & 1;
    int g = lane >> 2, t = lane & 3;
    int row0 = blockIdx.x * 64;
    float c[4][4];
#pragma unroll
    for (int i = 0; i < 4; i++)
#pragma unroll
        for (int j = 0; j < 4; j++) c[i][j] = 0.f;

    for (int k0 = 0; k0 < 128; k0 += 32) {
#pragma unroll
        for (int s = 0; s < 2; s++) {
            int f = tid + s * 256;
            int r = f >> 3, c4 = (f & 7) * 4;
            float4 v = make_float4(0.f, 0.f, 0.f, 0.f);
            if (row0 + r < M) {
                float4 u = ldh4(&A[(size_t)(row0 + r) * 128 + k0 + c4]);
                v.x = u.x > 0.f ? u.x : expm1f(u.x);
                v.y = u.y > 0.f ? u.y : expm1f(u.y);
                v.z = u.z > 0.f ? u.z : expm1f(u.z);
                v.w = u.w > 0.f ? u.w : expm1f(u.w);
            }
            v.x = to_tf32(v.x); v.y = to_tf32(v.y);
            v.z = to_tf32(v.z); v.w = to_tf32(v.w);
            *(float4*)&As[r][c4] = v;
        }
#pragma unroll
        for (int s = 0; s < 2; s++) {
            int f = tid + s * 256;
            int r = f >> 4, c4 = (f & 15) * 4;
            float4 v = *(const float4*)&W[(size_t)(k0 + r) * 64 + c4];
            v.x = to_tf32(v.x); v.y = to_tf32(v.y);
            v.z = to_tf32(v.z); v.w = to_tf32(v.w);
            *(float4*)&Bs[r][c4] = v;
        }
        __syncthreads();
#pragma unroll
        for (int kk = 0; kk < 32; kk += 8) {
            int ar = wm * 16;
            unsigned a0 = __float_as_uint(As[ar + g][kk + t]);
            unsigned a1 = __float_as_uint(As[ar + g + 8][kk + t]);
            unsigned a2 = __float_as_uint(As[ar + g][kk + t + 4]);
            unsigned a3 = __float_as_uint(As[ar + g + 8][kk + t + 4]);
#pragma unroll
            for (int nt = 0; nt < 4; nt++) {
                int n0 = wn * 32 + nt * 8;
                unsigned b0 = __float_as_uint(Bs[kk + t][n0 + g]);
                unsigned b1 = __float_as_uint(Bs[kk + t + 4][n0 + g]);
                mma_tf32(c[nt], a0, a1, a2, a3, b0, b1);
            }
        }
        __syncthreads();
    }
    int r1 = row0 + wm * 16 + g;
    int r2 = r1 + 8;
    float s1 = 0.f, d1 = 0.f, s2 = 0.f, d2 = 0.f;
#pragma unroll
    for (int nt = 0; nt < 4; nt++) {
        int col = wn * 32 + nt * 8 + t * 2;
        if (r1 < M) *(__half2*)&C[(size_t)r1 * 64 + col] = __floats2half2_rn(c[nt][0], c[nt][1]);
        if (r2 < M) *(__half2*)&C[(size_t)r2 * 64 + col] = __floats2half2_rn(c[nt][2], c[nt][3]);
        float av0 = att_src[col], av1 = att_src[col + 1];
        float dv0 = att_dst[col], dv1 = att_dst[col + 1];
        s1 += c[nt][0] * av0 + c[nt][1] * av1;
        d1 += c[nt][0] * dv0 + c[nt][1] * dv1;
        s2 += c[nt][2] * av0 + c[nt][3] * av1;
        d2 += c[nt][2] * dv0 + c[nt][3] * dv1;
    }
#pragma unroll
    for (int off = 1; off < 4; off <<= 1) {
        s1 += __shfl_xor_sync(~0u, s1, off); d1 += __shfl_xor_sync(~0u, d1, off);
        s2 += __shfl_xor_sync(~0u, s2, off); d2 += __shfl_xor_sync(~0u, d2, off);
    }
    if (t == 0) {
        int rl1 = wm * 16 + g, rl2 = rl1 + 8;
        sp[rl1][wn] = s1; dp[rl1][wn] = d1;
        sp[rl2][wn] = s2; dp[rl2][wn] = d2;
    }
    __syncthreads();
    if (tid < 64 && row0 + tid < M) {
        g_as2[row0 + tid] = sp[tid][0] + sp[tid][1];
        g_ad2[row0 + tid] = dp[tid][0] + dp[tid][1];
    }
}

// ---------------- layer1 gather: warp/node, fp16 rows, unroll 4 --------------
__global__ void k_gather1(const float* __restrict__ b1) {
    int w = blockIdx.x * 8 + (threadIdx.x >> 5);
    int lane = threadIdx.x & 31;
    if (w >= NN) return;
    int h = lane >> 3;
    float my_ad = g_ad1[w * 4 + h];
    float e_self = __expf(lrelu(g_as1[w * 4 + h] + my_ad));
    float den = e_self;
    float4 hv = ldh4(&g_h1[(size_t)w * 128 + lane * 4]);
    float4 acc = make_float4(hv.x * e_self, hv.y * e_self, hv.z * e_self, hv.w * e_self);

    int beg = g_roff[w], end = g_roff[w + 1];
    int i = beg;
    for (; i + 3 < end; i += 4) {
        int s0 = g_csrc[i],     s1 = g_csrc[i + 1];
        int s2 = g_csrc[i + 2], s3 = g_csrc[i + 3];
        float e0 = __expf(lrelu(g_as1[s0 * 4 + h] + my_ad));
        float e1 = __expf(lrelu(g_as1[s1 * 4 + h] + my_ad));
        float e2 = __expf(lrelu(g_as1[s2 * 4 + h] + my_ad));
        float e3 = __expf(lrelu(g_as1[s3 * 4 + h] + my_ad));
        den += (e0 + e1) + (e2 + e3);
        float4 h0 = ldh4(&g_h1[(size_t)s0 * 128 + lane * 4]);
        float4 h1 = ldh4(&g_h1[(size_t)s1 * 128 + lane * 4]);
        float4 h2 = ldh4(&g_h1[(size_t)s2 * 128 + lane * 4]);
        float4 h3 = ldh4(&g_h1[(size_t)s3 * 128 + lane * 4]);
        acc.x += (h0.x * e0 + h1.x * e1) + (h2.x * e2 + h3.x * e3);
        acc.y += (h0.y * e0 + h1.y * e1) + (h2.y * e2 + h3.y * e3);
        acc.z += (h0.z * e0 + h1.z * e1) + (h2.z * e2 + h3.z * e3);
        acc.w += (h0.w * e0 + h1.w * e1) + (h2.w * e2 + h3.w * e3);
    }
    for (; i < end; i++) {
        int s0 = g_csrc[i];
        float e0 = __expf(lrelu(g_as1[s0 * 4 + h] + my_ad));
        den += e0;
        float4 h0 = ldh4(&g_h1[(size_t)s0 * 128 + lane * 4]);
        acc.x += h0.x * e0; acc.y += h0.y * e0;
        acc.z += h0.z * e0; acc.w += h0.w * e0;
    }
    float inv = __frcp_rn(den + 1e-16f);
    float4 bb = *(const float4*)&b1[lane * 4];
    float4 o = make_float4(acc.x * inv + bb.x, acc.y * inv + bb.y,
                           acc.z * inv + bb.z, acc.w * inv + bb.w);
    sth4(&g_o1[(size_t)w * 128 + lane * 4], o);
}

// ---------------- layer2 gather: warp/node, 2 half-warps, fp16 rows ----------
__global__ void k_gather2(const float* __restrict__ b2, float* __restrict__ out) {
    int w = blockIdx.x * 8 + (threadIdx.x >> 5);
    int lane = threadIdx.x & 31;
    if (w >= NN) return;
    int half = lane >> 4, sl = lane & 15;
    float my_ad = g_ad2[w];
    float den = 0.f;
    float4 acc = make_float4(0.f, 0.f, 0.f, 0.f);
    if (half == 0) {
        float e_self = __expf(lrelu(g_as2[w] + my_ad));
        den = e_self;
        float4 hv = ldh4(&g_h2[(size_t)w * 64 + sl * 4]);
        acc = make_float4(hv.x * e_self, hv.y * e_self, hv.z * e_self, hv.w * e_self);
    }
    int beg = g_roff[w], end = g_roff[w + 1];
    int i = beg + half;
    for (; i + 2 < end; i += 4) {
        int s0 = g_csrc[i], s1 = g_csrc[i + 2];
        float e0 = __expf(lrelu(g_as2[s0] + my_ad));
        float e1 = __expf(lrelu(g_as2[s1] + my_ad));
        den += e0 + e1;
        float4 h0 = ldh4(&g_h2[(size_t)s0 * 64 + sl * 4]);
        float4 h1 = ldh4(&g_h2[(size_t)s1 * 64 + sl * 4]);
        acc.x += h0.x * e0 + h1.x * e1;
        acc.y += h0.y * e0 + h1.y * e1;
        acc.z += h0.z * e0 + h1.z * e1;
        acc.w += h0.w * e0 + h1.w * e1;
    }
    for (; i < end; i += 2) {
        int s0 = g_csrc[i];
        float e0 = __expf(lrelu(g_as2[s0] + my_ad));
        den += e0;
        float4 h0 = ldh4(&g_h2[(size_t)s0 * 64 + sl * 4]);
        acc.x += h0.x * e0; acc.y += h0.y * e0;
        acc.z += h0.z * e0; acc.w += h0.w * e0;
    }
    acc.x += __shfl_xor_sync(~0u, acc.x, 16);
    acc.y += __shfl_xor_sync(~0u, acc.y, 16);
    acc.z += __shfl_xor_sync(~0u, acc.z, 16);
    acc.w += __shfl_xor_sync(~0u, acc.w, 16);
    den += __shfl_xor_sync(~0u, den, 16);
    if (half == 0) {
        float inv = __frcp_rn(den + 1e-16f);
        float4 bb = *(const float4*)&b2[sl * 4];
        float4 o = make_float4(acc.x * inv + bb.x, acc.y * inv + bb.y,
                               acc.z * inv + bb.z, acc.w * inv + bb.w);
        *(float4*)&out[(size_t)w * 64 + sl * 4] = o;
    }
}

// ---------------- launch: fork CSR build parallel to GEMM1 -------------------
extern "C" void kernel_launch(void* const* d_in, const int* in_sizes, int n_in,
                              void* d_out, int out_size) {
    const float* x    = (const float*)d_in[0];
    const void*  ei   = d_in[1];
    const float* W1   = (const float*)d_in[2];
    const float* as1  = (const float*)d_in[3];
    const float* ad1  = (const float*)d_in[4];
    const float* b1   = (const float*)d_in[5];
    const float* W2   = (const float*)d_in[6];
    const float* as2  = (const float*)d_in[7];
    const float* ad2  = (const float*)d_in[8];
    const float* b2   = (const float*)d_in[9];
    float* out = (float*)d_out;

    __half* p_h1;  cudaGetSymbolAddress((void**)&p_h1, g_h1);
    __half* p_o1;  cudaGetSymbolAddress((void**)&p_o1, g_o1);
    __half* p_h2;  cudaGetSymbolAddress((void**)&p_h2, g_h2);

    // one-time host objects (no device allocation; identical launches per call)
    static cudaStream_t s2 = nullptr;
    static cudaEvent_t evF = nullptr, evJ = nullptr;
    if (!s2) {
        cudaStreamCreate(&s2);
        cudaEventCreateWithFlags(&evF, cudaEventDisableTiming);
        cudaEventCreateWithFlags(&evJ, cudaEventDisableTiming);
    }

    // fork: side stream builds CSR while main stream does GEMM1
    cudaEventRecord(evF, 0);
    cudaStreamWaitEvent(s2, evF, 0);

    k_detect <<<(NN + 255) / 256, 256, 0, s2>>>((const int*)ei);
    k_prep   <<<(EE + 255) / 256, 256, 0, s2>>>(ei);
    k_scan1  <<<NB, 256, 0, s2>>>();
    k_scan2  <<<1, 512, 0, s2>>>();
    k_scan3  <<<NB, 256, 0, s2>>>();
    k_scatter<<<(EE + 255) / 256, 256, 0, s2>>>();

    k_gemm1<<<(NN + 63) / 64, 256>>>(x, W1, p_h1, as1, ad1, NN);

    // join
    cudaEventRecord(evJ, s2);
    cudaStreamWaitEvent(0, evJ, 0);

    k_gather1<<<(NN + 7) / 8, 256>>>(b1);
    k_gemm2<<<(NN + 63) / 64, 256>>>(p_o1, W2, p_h2, as2, ad2, NN);
    k_gather2<<<(NN + 7) / 8, 256>>>(b2, out);
}

// round 10
// speedup vs baseline: 4.1429x; 1.0001x over previous
#include <cuda_runtime.h>
#include <cuda_fp16.h>
#include <math.h>

#define NN 100000
#define EE 1600000
#define HC 128         // heads*hidden = 4*32
#define F2 64          // out channels
#define NEG_SLOPE 0.2f
#define NB ((NN + 255) / 256)   // 391 scan blocks

// ---------------- scratch (device globals; no allocation allowed) ----------
__device__ __half g_h1[NN * HC];       // x @ W1            (fp16 storage)
__device__ __half g_o1[NN * HC];       // layer1 output     (fp16 storage)
__device__ __half g_h2[NN * F2];       // elu(o1) @ W2      (fp16 storage)
__device__ float  g_as1[NN * 4], g_ad1[NN * 4];
__device__ float  g_as2[NN], g_ad2[NN];
__device__ int    g_esrc[EE], g_edst[EE];   // int32 edge copy
__device__ int    g_deg[NN];
__device__ int    g_roff[NN + 1];
__device__ int    g_cur[NN];
__device__ int    g_bsum[NB];
__device__ int    g_boff[NB];
__device__ int    g_csrc[EE];          // CSR by dst: source node per slot
__device__ int    g_is64;

// ---------------- helpers ---------------------------------------------------
__device__ __forceinline__ float lrelu(float x) {
    return x > 0.f ? x : NEG_SLOPE * x;
}
__device__ __forceinline__ int clampN(int v) {
    return v < 0 ? 0 : (v >= NN ? NN - 1 : v);
}
__device__ __forceinline__ float to_tf32(float x) {
    float r; asm("cvt.rna.tf32.f32 %0, %1;" : "=f"(r) : "f"(x)); return r;
}
__device__ __forceinline__ void mma_tf32(float* c, unsigned a0, unsigned a1,
                                         unsigned a2, unsigned a3,
                                         unsigned b0, unsigned b1) {
    asm volatile(
        "mma.sync.aligned.m16n8k8.row.col.f32.tf32.tf32.f32 "
        "{%0,%1,%2,%3}, {%4,%5,%6,%7}, {%8,%9}, {%0,%1,%2,%3};"
        : "+f"(c[0]), "+f"(c[1]), "+f"(c[2]), "+f"(c[3])
        : "r"(a0), "r"(a1), "r"(a2), "r"(a3), "r"(b0), "r"(b1));
}
__device__ __forceinline__ float4 ldh4(const __half* p) {
    uint2 u = *(const uint2*)p;
    float2 a = __half22float2(*(__half2*)&u.x);
    float2 b = __half22float2(*(__half2*)&u.y);
    return make_float4(a.x, a.y, b.x, b.y);
}
// load 8 consecutive halfs (16B aligned) -> 8 floats
__device__ __forceinline__ void ldh8(const __half* p, float* f) {
    uint4 u = *(const uint4*)p;
    float2 a = __half22float2(*(__half2*)&u.x);
    float2 b = __half22float2(*(__half2*)&u.y);
    float2 c = __half22float2(*(__half2*)&u.z);
    float2 d = __half22float2(*(__half2*)&u.w);
    f[0] = a.x; f[1] = a.y; f[2] = b.x; f[3] = b.y;
    f[4] = c.x; f[5] = c.y; f[6] = d.x; f[7] = d.y;
}
// store 8 floats -> 8 consecutive halfs (16B aligned)
__device__ __forceinline__ void sth8(__half* p, const float* f) {
    uint4 u;
    *(__half2*)&u.x = __floats2half2_rn(f[0], f[1]);
    *(__half2*)&u.y = __floats2half2_rn(f[2], f[3]);
    *(__half2*)&u.z = __floats2half2_rn(f[4], f[5]);
    *(__half2*)&u.w = __floats2half2_rn(f[6], f[7]);
    *(uint4*)p = u;
}

// ---------------- dtype detect + degree zero (fused) -------------------------
__global__ void k_detect(const int* __restrict__ ei32) {
    int i = blockIdx.x * blockDim.x + threadIdx.x;
    if (i < NN) g_deg[i] = 0;
    if (i == 0) {
        int all_zero = 1;
#pragma unroll
        for (int k = 0; k < 8; k++)
            if (ei32[2 * k + 1] != 0) all_zero = 0;
        g_is64 = all_zero;
    }
}

// ---------------- edge convert (int64/int32 -> int32) + histogram ------------
__global__ void k_prep(const void* __restrict__ ei) {
    int i = blockIdx.x * blockDim.x + threadIdx.x;
    if (i >= EE) return;
    int s, d;
    if (g_is64) {
        const long long* p = (const long long*)ei;
        s = (int)p[i]; d = (int)p[EE + i];
    } else {
        const int* p = (const int*)ei;
        s = p[i]; d = p[EE + i];
    }
    s = clampN(s); d = clampN(d);
    g_esrc[i] = s;
    g_edst[i] = d;
    atomicAdd(&g_deg[d], 1);
}

// ---------------- CSR scan + scatter -----------------------------------------
__global__ void k_scan1() {
    __shared__ int sh[256];
    int b = blockIdx.x, t = threadIdx.x;
    int i = b * 256 + t;
    sh[t] = (i < NN) ? g_deg[i] : 0;
    __syncthreads();
#pragma unroll
    for (int off = 128; off; off >>= 1) {
        if (t < off) sh[t] += sh[t + off];
        __syncthreads();
    }
    if (t == 0) g_bsum[b] = sh[0];
}
__global__ void k_scan2() {
    __shared__ int sh[512];
    int t = threadIdx.x;
    int v = (t < NB) ? g_bsum[t] : 0;
    sh[t] = v;
    __syncthreads();
#pragma unroll
    for (int off = 1; off < 512; off <<= 1) {
        int x = (t >= off) ? sh[t - off] : 0;
        __syncthreads();
        sh[t] += x;
        __syncthreads();
    }
    if (t < NB) g_boff[t] = sh[t] - v;   // exclusive
}
__global__ void k_scan3() {
    __shared__ int sh[256];
    int b = blockIdx.x, t = threadIdx.x;
    int i = b * 256 + t;
    int v = (i < NN) ? g_deg[i] : 0;
    sh[t] = v;
    __syncthreads();
#pragma unroll
    for (int off = 1; off < 256; off <<= 1) {
        int x = (t >= off) ? sh[t - off] : 0;
        __syncthreads();
        sh[t] += x;
        __syncthreads();
    }
    int excl = g_boff[b] + sh[t] - v;
    if (i < NN) {
        g_roff[i] = excl;
        g_cur[i]  = excl;
        if (i == NN - 1) g_roff[NN] = excl + v;
    }
}
__global__ void k_scatter() {
    int i = blockIdx.x * blockDim.x + threadIdx.x;
    if (i >= EE) return;
    int s = g_esrc[i];
    int d = g_edst[i];
    int pos = atomicAdd(&g_cur[d], 1);
    g_csrc[pos] = s;
}

// ---------------- GEMM1 (tf32 mma) + fused att1 epilogue, fp16 C -------------
__global__ void k_gemm1(const float* __restrict__ A, const float* __restrict__ W,
                        __half* __restrict__ C,
                        const float* __restrict__ att_src, const float* __restrict__ att_dst,
                        int M) {
    __shared__ float As[64][36];
    __shared__ float Bs[32][132];
    int tid = threadIdx.x;
    int wid = tid >> 5, lane = tid & 31;
    int wm = wid >> 1, wn = wid & 1;
    int g = lane >> 2, t = lane & 3;
    int row0 = blockIdx.x * 64;
    float c[8][4];
#pragma unroll
    for (int i = 0; i < 8; i++)
#pragma unroll
        for (int j = 0; j < 4; j++) c[i][j] = 0.f;

    for (int k0 = 0; k0 < 128; k0 += 32) {
#pragma unroll
        for (int s = 0; s < 2; s++) {
            int f = tid + s * 256;
            int r = f >> 3, c4 = (f & 7) * 4;
            float4 v = make_float4(0.f, 0.f, 0.f, 0.f);
            if (row0 + r < M) v = *(const float4*)&A[(size_t)(row0 + r) * 128 + k0 + c4];
            v.x = to_tf32(v.x); v.y = to_tf32(v.y);
            v.z = to_tf32(v.z); v.w = to_tf32(v.w);
            *(float4*)&As[r][c4] = v;
        }
#pragma unroll
        for (int s = 0; s < 4; s++) {
            int f = tid + s * 256;
            int r = f >> 5, c4 = (f & 31) * 4;
            float4 v = *(const float4*)&W[(size_t)(k0 + r) * 128 + c4];
            v.x = to_tf32(v.x); v.y = to_tf32(v.y);
            v.z = to_tf32(v.z); v.w = to_tf32(v.w);
            *(float4*)&Bs[r][c4] = v;
        }
        __syncthreads();
#pragma unroll
        for (int kk = 0; kk < 32; kk += 8) {
            int ar = wm * 16;
            unsigned a0 = __float_as_uint(As[ar + g][kk + t]);
            unsigned a1 = __float_as_uint(As[ar + g + 8][kk + t]);
            unsigned a2 = __float_as_uint(As[ar + g][kk + t + 4]);
            unsigned a3 = __float_as_uint(As[ar + g + 8][kk + t + 4]);
#pragma unroll
            for (int nt = 0; nt < 8; nt++) {
                int n0 = wn * 64 + nt * 8;
                unsigned b0 = __float_as_uint(Bs[kk + t][n0 + g]);
                unsigned b1 = __float_as_uint(Bs[kk + t + 4][n0 + g]);
                mma_tf32(c[nt], a0, a1, a2, a3, b0, b1);
            }
        }
        __syncthreads();
    }
    int r1 = row0 + wm * 16 + g;
    int r2 = r1 + 8;
#pragma unroll
    for (int nt = 0; nt < 8; nt++) {
        int col = wn * 64 + nt * 8 + t * 2;
        if (r1 < M) *(__half2*)&C[(size_t)r1 * 128 + col] = __floats2half2_rn(c[nt][0], c[nt][1]);
        if (r2 < M) *(__half2*)&C[(size_t)r2 * 128 + col] = __floats2half2_rn(c[nt][2], c[nt][3]);
    }
    float s1a = 0.f, s1b = 0.f, d1a = 0.f, d1b = 0.f;
    float s2a = 0.f, s2b = 0.f, d2a = 0.f, d2b = 0.f;
#pragma unroll
    for (int nt = 0; nt < 8; nt++) {
        int col = wn * 64 + nt * 8 + t * 2;
        float av0 = att_src[col], av1 = att_src[col + 1];
        float dv0 = att_dst[col], dv1 = att_dst[col + 1];
        float ps1 = c[nt][0] * av0 + c[nt][1] * av1;
        float pd1 = c[nt][0] * dv0 + c[nt][1] * dv1;
        float ps2 = c[nt][2] * av0 + c[nt][3] * av1;
        float pd2 = c[nt][2] * dv0 + c[nt][3] * dv1;
        if (nt < 4) { s1a += ps1; d1a += pd1; s2a += ps2; d2a += pd2; }
        else        { s1b += ps1; d1b += pd1; s2b += ps2; d2b += pd2; }
    }
#pragma unroll
    for (int off = 1; off < 4; off <<= 1) {
        s1a += __shfl_xor_sync(~0u, s1a, off); s1b += __shfl_xor_sync(~0u, s1b, off);
        d1a += __shfl_xor_sync(~0u, d1a, off); d1b += __shfl_xor_sync(~0u, d1b, off);
        s2a += __shfl_xor_sync(~0u, s2a, off); s2b += __shfl_xor_sync(~0u, s2b, off);
        d2a += __shfl_xor_sync(~0u, d2a, off); d2b += __shfl_xor_sync(~0u, d2b, off);
    }
    if (t == 0) {
        int ha = 2 * wn, hb = 2 * wn + 1;
        if (r1 < M) {
            g_as1[r1 * 4 + ha] = s1a; g_as1[r1 * 4 + hb] = s1b;
            g_ad1[r1 * 4 + ha] = d1a; g_ad1[r1 * 4 + hb] = d1b;
        }
        if (r2 < M) {
            g_as1[r2 * 4 + ha] = s2a; g_as1[r2 * 4 + hb] = s2b;
            g_ad1[r2 * 4 + ha] = d2a; g_ad1[r2 * 4 + hb] = d2b;
        }
    }
}

// ---------------- GEMM2 (tf32 mma, fp16 A/C) + fused att2 epilogue -----------
__global__ void k_gemm2(const __half* __restrict__ A, const float* __restrict__ W,
                        __half* __restrict__ C,
                        const float* __restrict__ att_src, const float* __restrict__ att_dst,
                        int M) {
    __shared__ float As[64][36];
    __shared__ float Bs[32][68];
    __shared__ float sp[64][2], dp[64][2];
    int tid = threadIdx.x;
    int wid = tid >> 5, lane = tid & 31;
    int wm = wid >> 1, wn = wid & 1;
    int g = lane >> 2, t = lane & 3;
    int row0 = blockIdx.x * 64;
    float c[4][4];
#pragma unroll
    for (int i = 0; i < 4; i++)
#pragma unroll
        for (int j = 0; j < 4; j++) c[i][j] = 0.f;

    for (int k0 = 0; k0 < 128; k0 += 32) {
#pragma unroll
        for (int s = 0; s < 2; s++) {
            int f = tid + s * 256;
            int r = f >> 3, c4 = (f & 7) * 4;
            float4 v = make_float4(0.f, 0.f, 0.f, 0.f);
            if (row0 + r < M) {
                float4 u = ldh4(&A[(size_t)(row0 + r) * 128 + k0 + c4]);
                v.x = u.x > 0.f ? u.x : expm1f(u.x);
                v.y = u.y > 0.f ? u.y : expm1f(u.y);
                v.z = u.z > 0.f ? u.z : expm1f(u.z);
                v.w = u.w > 0.f ? u.w : expm1f(u.w);
            }
            v.x = to_tf32(v.x); v.y = to_tf32(v.y);
            v.z = to_tf32(v.z); v.w = to_tf32(v.w);
            *(float4*)&As[r][c4] = v;
        }
#pragma unroll
        for (int s = 0; s < 2; s++) {
            int f = tid + s * 256;
            int r = f >> 4, c4 = (f & 15) * 4;
            float4 v = *(const float4*)&W[(size_t)(k0 + r) * 64 + c4];
            v.x = to_tf32(v.x); v.y = to_tf32(v.y);
            v.z = to_tf32(v.z); v.w = to_tf32(v.w);
            *(float4*)&Bs[r][c4] = v;
        }
        __syncthreads();
#pragma unroll
        for (int kk = 0; kk < 32; kk += 8) {
            int ar = wm * 16;
            unsigned a0 = __float_as_uint(As[ar + g][kk + t]);
            unsigned a1 = __float_as_uint(As[ar + g + 8][kk + t]);
            unsigned a2 = __float_as_uint(As[ar + g][kk + t + 4]);
            unsigned a3 = __float_as_uint(As[ar + g + 8][kk + t + 4]);
#pragma unroll
            for (int nt = 0; nt < 4; nt++) {
                int n0 = wn * 32 + nt * 8;
                unsigned b0 = __float_as_uint(Bs[kk + t][n0 + g]);
                unsigned b1 = __float_as_uint(Bs[kk + t + 4][n0 + g]);
                mma_tf32(c[nt], a0, a1, a2, a3, b0, b1);
            }
        }
        __syncthreads();
    }
    int r1 = row0 + wm * 16 + g;
    int r2 = r1 + 8;
    float s1 = 0.f, d1 = 0.f, s2 = 0.f, d2 = 0.f;
#pragma unroll
    for (int nt = 0; nt < 4; nt++) {
        int col = wn * 32 + nt * 8 + t * 2;
        if (r1 < M) *(__half2*)&C[(size_t)r1 * 64 + col] = __floats2half2_rn(c[nt][0], c[nt][1]);
        if (r2 < M) *(__half2*)&C[(size_t)r2 * 64 + col] = __floats2half2_rn(c[nt][2], c[nt][3]);
        float av0 = att_src[col], av1 = att_src[col + 1];
        float dv0 = att_dst[col], dv1 = att_dst[col + 1];
        s1 += c[nt][0] * av0 + c[nt][1] * av1;
        d1 += c[nt][0] * dv0 + c[nt][1] * dv1;
        s2 += c[nt][2] * av0 + c[nt][3] * av1;
        d2 += c[nt][2] * dv0 + c[nt][3] * dv1;
    }
#pragma unroll
    for (int off = 1; off < 4; off <<= 1) {
        s1 += __shfl_xor_sync(~0u, s1, off); d1 += __shfl_xor_sync(~0u, d1, off);
        s2 += __shfl_xor_sync(~0u, s2, off); d2 += __shfl_xor_sync(~0u, d2, off);
    }
    if (t == 0) {
        int rl1 = wm * 16 + g, rl2 = rl1 + 8;
        sp[rl1][wn] = s1; dp[rl1][wn] = d1;
        sp[rl2][wn] = s2; dp[rl2][wn] = d2;
    }
    __syncthreads();
    if (tid < 64 && row0 + tid < M) {
        g_as2[row0 + tid] = sp[tid][0] + sp[tid][1];
        g_ad2[row0 + tid] = dp[tid][0] + dp[tid][1];
    }
}

// ---------------- layer1 gather v2: warp/node, 2 edges in flight, LDG.128 ----
// 16 lanes x 16B cover one 256B fp16 row; half-warps process alternate edges.
__global__ void k_gather1(const float* __restrict__ b1) {
    int w = blockIdx.x * 8 + (threadIdx.x >> 5);
    int lane = threadIdx.x & 31;
    if (w >= NN) return;
    int half = lane >> 4;          // which edge of the pair
    int sl = lane & 15;            // covers halfs sl*8 .. sl*8+7
    int h = sl >> 2;               // head (4 lanes per head)
    float my_ad = g_ad1[w * 4 + h];
    float den = 0.f;
    float acc[8];
#pragma unroll
    for (int j = 0; j < 8; j++) acc[j] = 0.f;
    if (half == 0) {
        float e_self = __expf(lrelu(g_as1[w * 4 + h] + my_ad));
        den = e_self;
        float hv[8];
        ldh8(&g_h1[(size_t)w * 128 + sl * 8], hv);
#pragma unroll
        for (int j = 0; j < 8; j++) acc[j] = hv[j] * e_self;
    }
    int beg = g_roff[w], end = g_roff[w + 1];
    int i = beg + half;
    for (; i + 2 < end; i += 4) {
        int s0 = g_csrc[i], s1 = g_csrc[i + 2];
        float e0 = __expf(lrelu(g_as1[s0 * 4 + h] + my_ad));
        float e1 = __expf(lrelu(g_as1[s1 * 4 + h] + my_ad));
        den += e0 + e1;
        float h0[8], h1[8];
        ldh8(&g_h1[(size_t)s0 * 128 + sl * 8], h0);
        ldh8(&g_h1[(size_t)s1 * 128 + sl * 8], h1);
#pragma unroll
        for (int j = 0; j < 8; j++) acc[j] += h0[j] * e0 + h1[j] * e1;
    }
    for (; i < end; i += 2) {
        int s0 = g_csrc[i];
        float e0 = __expf(lrelu(g_as1[s0 * 4 + h] + my_ad));
        den += e0;
        float h0[8];
        ldh8(&g_h1[(size_t)s0 * 128 + sl * 8], h0);
#pragma unroll
        for (int j = 0; j < 8; j++) acc[j] += h0[j] * e0;
    }
    // combine the two half-warps (same sl, different edges)
#pragma unroll
    for (int j = 0; j < 8; j++) acc[j] += __shfl_xor_sync(~0u, acc[j], 16);
    den += __shfl_xor_sync(~0u, den, 16);
    if (half == 0) {
        float inv = __frcp_rn(den + 1e-16f);
        float4 bb0 = *(const float4*)&b1[sl * 8];
        float4 bb1 = *(const float4*)&b1[sl * 8 + 4];
        float o[8];
        o[0] = acc[0] * inv + bb0.x; o[1] = acc[1] * inv + bb0.y;
        o[2] = acc[2] * inv + bb0.z; o[3] = acc[3] * inv + bb0.w;
        o[4] = acc[4] * inv + bb1.x; o[5] = acc[5] * inv + bb1.y;
        o[6] = acc[6] * inv + bb1.z; o[7] = acc[7] * inv + bb1.w;
        sth8(&g_o1[(size_t)w * 128 + sl * 8], o);
    }
}

// ---------------- layer2 gather v2: warp/node, 4 edges in flight, LDG.128 ----
// 8 lanes x 16B cover one 128B fp16 row; quads process alternate edges.
__global__ void k_gather2(const float* __restrict__ b2, float* __restrict__ out) {
    int w = blockIdx.x * 8 + (threadIdx.x >> 5);
    int lane = threadIdx.x & 31;
    if (w >= NN) return;
    int q = lane >> 3;             // edge slot 0..3
    int sl = lane & 7;             // covers halfs sl*8 .. sl*8+7
    float my_ad = g_ad2[w];
    float den = 0.f;
    float acc[8];
#pragma unroll
    for (int j = 0; j < 8; j++) acc[j] = 0.f;
    if (q == 0) {
        float e_self = __expf(lrelu(g_as2[w] + my_ad));
        den = e_self;
        float hv[8];
        ldh8(&g_h2[(size_t)w * 64 + sl * 8], hv);
#pragma unroll
        for (int j = 0; j < 8; j++) acc[j] = hv[j] * e_self;
    }
    int beg = g_roff[w], end = g_roff[w + 1];
    int i = beg + q;
    for (; i + 4 < end; i += 8) {
        int s0 = g_csrc[i], s1 = g_csrc[i + 4];
        float e0 = __expf(lrelu(g_as2[s0] + my_ad));
        float e1 = __expf(lrelu(g_as2[s1] + my_ad));
        den += e0 + e1;
        float h0[8], h1[8];
        ldh8(&g_h2[(size_t)s0 * 64 + sl * 8], h0);
        ldh8(&g_h2[(size_t)s1 * 64 + sl * 8], h1);
#pragma unroll
        for (int j = 0; j < 8; j++) acc[j] += h0[j] * e0 + h1[j] * e1;
    }
    for (; i < end; i += 4) {
        int s0 = g_csrc[i];
        float e0 = __expf(lrelu(g_as2[s0] + my_ad));
        den += e0;
        float h0[8];
        ldh8(&g_h2[(size_t)s0 * 64 + sl * 8], h0);
#pragma unroll
        for (int j = 0; j < 8; j++) acc[j] += h0[j] * e0;
    }
    // combine the 4 quads (same sl, different edges)
#pragma unroll
    for (int j = 0; j < 8; j++) {
        acc[j] += __shfl_xor_sync(~0u, acc[j], 8);
        acc[j] += __shfl_xor_sync(~0u, acc[j], 16);
    }
    den += __shfl_xor_sync(~0u, den, 8);
    den += __shfl_xor_sync(~0u, den, 16);
    if (q == 0) {
        float inv = __frcp_rn(den + 1e-16f);
        float4 bb0 = *(const float4*)&b2[sl * 8];
        float4 bb1 = *(const float4*)&b2[sl * 8 + 4];
        float4 o0 = make_float4(acc[0] * inv + bb0.x, acc[1] * inv + bb0.y,
                                acc[2] * inv + bb0.z, acc[3] * inv + bb0.w);
        float4 o1 = make_float4(acc[4] * inv + bb1.x, acc[5] * inv + bb1.y,
                                acc[6] * inv + bb1.z, acc[7] * inv + bb1.w);
        *(float4*)&out[(size_t)w * 64 + sl * 8]     = o0;
        *(float4*)&out[(size_t)w * 64 + sl * 8 + 4] = o1;
    }
}

// ---------------- launch: fork CSR build parallel to GEMM1 -------------------
extern "C" void kernel_launch(void* const* d_in, const int* in_sizes, int n_in,
                              void* d_out, int out_size) {
    const float* x    = (const float*)d_in[0];
    const void*  ei   = d_in[1];
    const float* W1   = (const float*)d_in[2];
    const float* as1  = (const float*)d_in[3];
    const float* ad1  = (const float*)d_in[4];
    const float* b1   = (const float*)d_in[5];
    const float* W2   = (const float*)d_in[6];
    const float* as2  = (const float*)d_in[7];
    const float* ad2  = (const float*)d_in[8];
    const float* b2   = (const float*)d_in[9];
    float* out = (float*)d_out;

    __half* p_h1;  cudaGetSymbolAddress((void**)&p_h1, g_h1);
    __half* p_o1;  cudaGetSymbolAddress((void**)&p_o1, g_o1);
    __half* p_h2;  cudaGetSymbolAddress((void**)&p_h2, g_h2);

    static cudaStream_t s2 = nullptr;
    static cudaEvent_t evF = nullptr, evJ = nullptr;
    if (!s2) {
        cudaStreamCreate(&s2);
        cudaEventCreateWithFlags(&evF, cudaEventDisableTiming);
        cudaEventCreateWithFlags(&evJ, cudaEventDisableTiming);
    }

    cudaEventRecord(evF, 0);
    cudaStreamWaitEvent(s2, evF, 0);

    k_detect <<<(NN + 255) / 256, 256, 0, s2>>>((const int*)ei);
    k_prep   <<<(EE + 255) / 256, 256, 0, s2>>>(ei);
    k_scan1  <<<NB, 256, 0, s2>>>();
    k_scan2  <<<1, 512, 0, s2>>>();
    k_scan3  <<<NB, 256, 0, s2>>>();
    k_scatter<<<(EE + 255) / 256, 256, 0, s2>>>();

    k_gemm1<<<(NN + 63) / 64, 256>>>(x, W1, p_h1, as1, ad1, NN);

    cudaEventRecord(evJ, s2);
    cudaStreamWaitEvent(0, evJ, 0);

    k_gather1<<<(NN + 7) / 8, 256>>>(b1);
    k_gemm2<<<(NN + 63) / 64, 256>>>(p_o1, W2, p_h2, as2, ad2, NN);
    k_gather2<<<(NN + 7) / 8, 256>>>(b2, out);
}

// round 11
// speedup vs baseline: 4.1968x; 1.0130x over previous
#include <cuda_runtime.h>
#include <cuda_fp16.h>
#include <math.h>

#define NN 100000
#define EE 1600000
#define HC 128         // heads*hidden = 4*32
#define F2 64          // out channels
#define NEG_SLOPE 0.2f
#define NB2 ((NN + 511) / 512)   // 196 scan blocks (512 thr)
#define NH 50048                 // gather1/gemm2 pipeline split (64-aligned)

// ---------------- scratch (device globals; no allocation allowed) ----------
__device__ __half g_h1[NN * HC];       // x @ W1            (fp16 storage)
__device__ __half g_o1[NN * HC];       // layer1 output     (fp16 storage)
__device__ __half g_h2[NN * F2];       // elu(o1) @ W2      (fp16 storage)
__device__ float  g_as1[NN * 4], g_ad1[NN * 4];
__device__ float  g_as2[NN], g_ad2[NN];
__device__ int    g_esrc[EE], g_edst[EE];   // int32 edge copy
__device__ int    g_deg[NN];           // zero at entry (BSS init / gather2 tail)
__device__ int    g_roff[NN + 1];
__device__ int    g_cur[NN];
__device__ int    g_bsum[NB2];
__device__ int    g_boff[NB2];
__device__ int    g_tick;              // scanA ticket (zeroed like g_deg)
__device__ int    g_csrc[EE];          // CSR by dst: source node per slot

// ---------------- helpers ---------------------------------------------------
__device__ __forceinline__ float lrelu(float x) {
    return x > 0.f ? x : NEG_SLOPE * x;
}
__device__ __forceinline__ int clampN(int v) {
    return v < 0 ? 0 : (v >= NN ? NN - 1 : v);
}
__device__ __forceinline__ float to_tf32(float x) {
    float r; asm("cvt.rna.tf32.f32 %0, %1;" : "=f"(r) : "f"(x)); return r;
}
__device__ __forceinline__ void mma_tf32(float* c, unsigned a0, unsigned a1,
                                         unsigned a2, unsigned a3,
                                         unsigned b0, unsigned b1) {
    asm volatile(
        "mma.sync.aligned.m16n8k8.row.col.f32.tf32.tf32.f32 "
        "{%0,%1,%2,%3}, {%4,%5,%6,%7}, {%8,%9}, {%0,%1,%2,%3};"
        : "+f"(c[0]), "+f"(c[1]), "+f"(c[2]), "+f"(c[3])
        : "r"(a0), "r"(a1), "r"(a2), "r"(a3), "r"(b0), "r"(b1));
}
__device__ __forceinline__ float4 ldh4(const __half* p) {
    uint2 u = *(const uint2*)p;
    float2 a = __half22float2(*(__half2*)&u.x);
    float2 b = __half22float2(*(__half2*)&u.y);
    return make_float4(a.x, a.y, b.x, b.y);
}
// nc load of 8 consecutive halfs (16B aligned) -> 8 floats
__device__ __forceinline__ void ldh8nc(const __half* p, float* f) {
    uint4 u = __ldg((const uint4*)p);
    float2 a = __half22float2(*(__half2*)&u.x);
    float2 b = __half22float2(*(__half2*)&u.y);
    float2 c = __half22float2(*(__half2*)&u.z);
    float2 d = __half22float2(*(__half2*)&u.w);
    f[0] = a.x; f[1] = a.y; f[2] = b.x; f[3] = b.y;
    f[4] = c.x; f[5] = c.y; f[6] = d.x; f[7] = d.y;
}
// store 8 floats -> 8 consecutive halfs (16B aligned)
__device__ __forceinline__ void sth8(__half* p, const float* f) {
    uint4 u;
    *(__half2*)&u.x = __floats2half2_rn(f[0], f[1]);
    *(__half2*)&u.y = __floats2half2_rn(f[2], f[3]);
    *(__half2*)&u.z = __floats2half2_rn(f[4], f[5]);
    *(__half2*)&u.w = __floats2half2_rn(f[6], f[7]);
    *(uint4*)p = u;
}

// ---------------- edge convert + histogram (dtype detect inlined) ------------
// g_deg must be zero on entry: BSS-zero at process start, re-zeroed by the
// gather2 tail at the end of every launch.
__global__ void k_prep(const void* __restrict__ ei) {
    int i = blockIdx.x * blockDim.x + threadIdx.x;
    if (i >= EE) return;
    // local int64 detection: hi-words of first 8 int64 indices are all zero
    const int* e32 = (const int*)ei;
    int is64 = 1;
#pragma unroll
    for (int k = 0; k < 8; k++)
        if (e32[2 * k + 1] != 0) is64 = 0;
    int s, d;
    if (is64) {
        const long long* p = (const long long*)ei;
        s = (int)p[i]; d = (int)p[EE + i];
    } else {
        s = e32[i]; d = e32[EE + i];
    }
    s = clampN(s); d = clampN(d);
    g_esrc[i] = s;
    g_edst[i] = d;
    atomicAdd(&g_deg[d], 1);
}

// ---------------- scanA: per-block reduce + last-block scans block sums ------
__global__ void k_scanA() {
    __shared__ int sh[512];
    __shared__ int last;
    int b = blockIdx.x, t = threadIdx.x;
    int i = b * 512 + t;
    sh[t] = (i < NN) ? g_deg[i] : 0;
    __syncthreads();
#pragma unroll
    for (int off = 256; off; off >>= 1) {
        if (t < off) sh[t] += sh[t + off];
        __syncthreads();
    }
    if (t == 0) {
        g_bsum[b] = sh[0];
        __threadfence();
        last = (atomicAdd(&g_tick, 1) == NB2 - 1);
    }
    __syncthreads();
    if (last) {
        int v = (t < NB2) ? g_bsum[t] : 0;
        sh[t] = v;
        __syncthreads();
#pragma unroll
        for (int off = 1; off < 512; off <<= 1) {
            int x = (t >= off) ? sh[t - off] : 0;
            __syncthreads();
            sh[t] += x;
            __syncthreads();
        }
        if (t < NB2) g_boff[t] = sh[t] - v;   // exclusive
    }
}

// ---------------- scan3: in-block scan + offset -> row offsets ---------------
__global__ void k_scan3() {
    __shared__ int sh[512];
    int b = blockIdx.x, t = threadIdx.x;
    int i = b * 512 + t;
    int v = (i < NN) ? g_deg[i] : 0;
    sh[t] = v;
    __syncthreads();
#pragma unroll
    for (int off = 1; off < 512; off <<= 1) {
        int x = (t >= off) ? sh[t - off] : 0;
        __syncthreads();
        sh[t] += x;
        __syncthreads();
    }
    int excl = g_boff[b] + sh[t] - v;
    if (i < NN) {
        g_roff[i] = excl;
        g_cur[i]  = excl;
        if (i == NN - 1) g_roff[NN] = excl + v;
    }
}
__global__ void k_scatter() {
    int i = blockIdx.x * blockDim.x + threadIdx.x;
    if (i >= EE) return;
    int s = g_esrc[i];
    int d = g_edst[i];
    int pos = atomicAdd(&g_cur[d], 1);
    g_csrc[pos] = s;
}

// ---------------- GEMM1 (tf32 mma) + fused att1 epilogue, fp16 C -------------
__global__ void k_gemm1(const float* __restrict__ A, const float* __restrict__ W,
                        __half* __restrict__ C,
                        const float* __restrict__ att_src, const float* __restrict__ att_dst,
                        int M) {
    __shared__ float As[64][36];
    __shared__ float Bs[32][132];
    int tid = threadIdx.x;
    int wid = tid >> 5, lane = tid & 31;
    int wm = wid >> 1, wn = wid & 1;
    int g = lane >> 2, t = lane & 3;
    int row0 = blockIdx.x * 64;
    float c[8][4];
#pragma unroll
    for (int i = 0; i < 8; i++)
#pragma unroll
        for (int j = 0; j < 4; j++) c[i][j] = 0.f;

    for (int k0 = 0; k0 < 128; k0 += 32) {
#pragma unroll
        for (int s = 0; s < 2; s++) {
            int f = tid + s * 256;
            int r = f >> 3, c4 = (f & 7) * 4;
            float4 v = make_float4(0.f, 0.f, 0.f, 0.f);
            if (row0 + r < M) v = *(const float4*)&A[(size_t)(row0 + r) * 128 + k0 + c4];
            v.x = to_tf32(v.x); v.y = to_tf32(v.y);
            v.z = to_tf32(v.z); v.w = to_tf32(v.w);
            *(float4*)&As[r][c4] = v;
        }
#pragma unroll
        for (int s = 0; s < 4; s++) {
            int f = tid + s * 256;
            int r = f >> 5, c4 = (f & 31) * 4;
            float4 v = *(const float4*)&W[(size_t)(k0 + r) * 128 + c4];
            v.x = to_tf32(v.x); v.y = to_tf32(v.y);
            v.z = to_tf32(v.z); v.w = to_tf32(v.w);
            *(float4*)&Bs[r][c4] = v;
        }
        __syncthreads();
#pragma unroll
        for (int kk = 0; kk < 32; kk += 8) {
            int ar = wm * 16;
            unsigned a0 = __float_as_uint(As[ar + g][kk + t]);
            unsigned a1 = __float_as_uint(As[ar + g + 8][kk + t]);
            unsigned a2 = __float_as_uint(As[ar + g][kk + t + 4]);
            unsigned a3 = __float_as_uint(As[ar + g + 8][kk + t + 4]);
#pragma unroll
            for (int nt = 0; nt < 8; nt++) {
                int n0 = wn * 64 + nt * 8;
                unsigned b0 = __float_as_uint(Bs[kk + t][n0 + g]);
                unsigned b1 = __float_as_uint(Bs[kk + t + 4][n0 + g]);
                mma_tf32(c[nt], a0, a1, a2, a3, b0, b1);
            }
        }
        __syncthreads();
    }
    int r1 = row0 + wm * 16 + g;
    int r2 = r1 + 8;
#pragma unroll
    for (int nt = 0; nt < 8; nt++) {
        int col = wn * 64 + nt * 8 + t * 2;
        if (r1 < M) *(__half2*)&C[(size_t)r1 * 128 + col] = __floats2half2_rn(c[nt][0], c[nt][1]);
        if (r2 < M) *(__half2*)&C[(size_t)r2 * 128 + col] = __floats2half2_rn(c[nt][2], c[nt][3]);
    }
    float s1a = 0.f, s1b = 0.f, d1a = 0.f, d1b = 0.f;
    float s2a = 0.f, s2b = 0.f, d2a = 0.f, d2b = 0.f;
#pragma unroll
    for (int nt = 0; nt < 8; nt++) {
        int col = wn * 64 + nt * 8 + t * 2;
        float av0 = att_src[col], av1 = att_src[col + 1];
        float dv0 = att_dst[col], dv1 = att_dst[col + 1];
        float ps1 = c[nt][0] * av0 + c[nt][1] * av1;
        float pd1 = c[nt][0] * dv0 + c[nt][1] * dv1;
        float ps2 = c[nt][2] * av0 + c[nt][3] * av1;
        float pd2 = c[nt][2] * dv0 + c[nt][3] * dv1;
        if (nt < 4) { s1a += ps1; d1a += pd1; s2a += ps2; d2a += pd2; }
        else        { s1b += ps1; d1b += pd1; s2b += ps2; d2b += pd2; }
    }
#pragma unroll
    for (int off = 1; off < 4; off <<= 1) {
        s1a += __shfl_xor_sync(~0u, s1a, off); s1b += __shfl_xor_sync(~0u, s1b, off);
        d1a += __shfl_xor_sync(~0u, d1a, off); d1b += __shfl_xor_sync(~0u, d1b, off);
        s2a += __shfl_xor_sync(~0u, s2a, off); s2b += __shfl_xor_sync(~0u, s2b, off);
        d2a += __shfl_xor_sync(~0u, d2a, off); d2b += __shfl_xor_sync(~0u, d2b, off);
    }
    if (t == 0) {
        int ha = 2 * wn, hb = 2 * wn + 1;
        if (r1 < M) {
            g_as1[r1 * 4 + ha] = s1a; g_as1[r1 * 4 + hb] = s1b;
            g_ad1[r1 * 4 + ha] = d1a; g_ad1[r1 * 4 + hb] = d1b;
        }
        if (r2 < M) {
            g_as1[r2 * 4 + ha] = s2a; g_as1[r2 * 4 + hb] = s2b;
            g_ad1[r2 * 4 + ha] = d2a; g_ad1[r2 * 4 + hb] = d2b;
        }
    }
}

// ---------------- GEMM2 (tf32 mma, fp16 A/C) + fused att2, row-range ---------
__global__ void k_gemm2(const __half* __restrict__ A, const float* __restrict__ W,
                        __half* __restrict__ C,
                        const float* __restrict__ att_src, const float* __restrict__ att_dst,
                        int base, int M) {
    __shared__ float As[64][36];
    __shared__ float Bs[32][68];
    __shared__ float sp[64][2], dp[64][2];
    int tid = threadIdx.x;
    int wid = tid >> 5, lane = tid & 31;
    int wm = wid >> 1, wn = wid & 1;
    int g = lane >> 2, t = lane & 3;
    int row0 = base + blockIdx.x * 64;
    float c[4][4];
#pragma unroll
    for (int i = 0; i < 4; i++)
#pragma unroll
        for (int j = 0; j < 4; j++) c[i][j] = 0.f;

    for (int k0 = 0; k0 < 128; k0 += 32) {
#pragma unroll
        for (int s = 0; s < 2; s++) {
            int f = tid + s * 256;
            int r = f >> 3, c4 = (f & 7) * 4;
            float4 v = make_float4(0.f, 0.f, 0.f, 0.f);
            if (row0 + r < M) {
                float4 u = ldh4(&A[(size_t)(row0 + r) * 128 + k0 + c4]);
                v.x = u.x > 0.f ? u.x : expm1f(u.x);
                v.y = u.y > 0.f ? u.y : expm1f(u.y);
                v.z = u.z > 0.f ? u.z : expm1f(u.z);
                v.w = u.w > 0.f ? u.w : expm1f(u.w);
            }
            v.x = to_tf32(v.x); v.y = to_tf32(v.y);
            v.z = to_tf32(v.z); v.w = to_tf32(v.w);
            *(float4*)&As[r][c4] = v;
        }
#pragma unroll
        for (int s = 0; s < 2; s++) {
            int f = tid + s * 256;
            int r = f >> 4, c4 = (f & 15) * 4;
            float4 v = *(const float4*)&W[(size_t)(k0 + r) * 64 + c4];
            v.x = to_tf32(v.x); v.y = to_tf32(v.y);
            v.z = to_tf32(v.z); v.w = to_tf32(v.w);
            *(float4*)&Bs[r][c4] = v;
        }
        __syncthreads();
#pragma unroll
        for (int kk = 0; kk < 32; kk += 8) {
            int ar = wm * 16;
            unsigned a0 = __float_as_uint(As[ar + g][kk + t]);
            unsigned a1 = __float_as_uint(As[ar + g + 8][kk + t]);
            unsigned a2 = __float_as_uint(As[ar + g][kk + t + 4]);
            unsigned a3 = __float_as_uint(As[ar + g + 8][kk + t + 4]);
#pragma unroll
            for (int nt = 0; nt < 4; nt++) {
                int n0 = wn * 32 + nt * 8;
                unsigned b0 = __float_as_uint(Bs[kk + t][n0 + g]);
                unsigned b1 = __float_as_uint(Bs[kk + t + 4][n0 + g]);
                mma_tf32(c[nt], a0, a1, a2, a3, b0, b1);
            }
        }
        __syncthreads();
    }
    int r1 = row0 + wm * 16 + g;
    int r2 = r1 + 8;
    float s1 = 0.f, d1 = 0.f, s2 = 0.f, d2 = 0.f;
#pragma unroll
    for (int nt = 0; nt < 4; nt++) {
        int col = wn * 32 + nt * 8 + t * 2;
        if (r1 < M) *(__half2*)&C[(size_t)r1 * 64 + col] = __floats2half2_rn(c[nt][0], c[nt][1]);
        if (r2 < M) *(__half2*)&C[(size_t)r2 * 64 + col] = __floats2half2_rn(c[nt][2], c[nt][3]);
        float av0 = att_src[col], av1 = att_src[col + 1];
        float dv0 = att_dst[col], dv1 = att_dst[col + 1];
        s1 += c[nt][0] * av0 + c[nt][1] * av1;
        d1 += c[nt][0] * dv0 + c[nt][1] * dv1;
        s2 += c[nt][2] * av0 + c[nt][3] * av1;
        d2 += c[nt][2] * dv0 + c[nt][3] * dv1;
    }
#pragma unroll
    for (int off = 1; off < 4; off <<= 1) {
        s1 += __shfl_xor_sync(~0u, s1, off); d1 += __shfl_xor_sync(~0u, d1, off);
        s2 += __shfl_xor_sync(~0u, s2, off); d2 += __shfl_xor_sync(~0u, d2, off);
    }
    if (t == 0) {
        int rl1 = wm * 16 + g, rl2 = rl1 + 8;
        sp[rl1][wn] = s1; dp[rl1][wn] = d1;
        sp[rl2][wn] = s2; dp[rl2][wn] = d2;
    }
    __syncthreads();
    if (tid < 64 && row0 + tid < M) {
        g_as2[row0 + tid] = sp[tid][0] + sp[tid][1];
        g_ad2[row0 + tid] = dp[tid][0] + dp[tid][1];
    }
}

// ---------------- layer1 gather (node range): warp/node, LDG.128 nc ----------
__global__ void k_gather1(const float* __restrict__ b1, int base, int count) {
    int w = base + blockIdx.x * 8 + (threadIdx.x >> 5);
    int lane = threadIdx.x & 31;
    if (w >= base + count || w >= NN) return;
    int half = lane >> 4;
    int sl = lane & 15;
    int h = sl >> 2;
    float my_ad = __ldg(&g_ad1[w * 4 + h]);
    float den = 0.f;
    float acc[8];
#pragma unroll
    for (int j = 0; j < 8; j++) acc[j] = 0.f;
    if (half == 0) {
        float e_self = __expf(lrelu(__ldg(&g_as1[w * 4 + h]) + my_ad));
        den = e_self;
        float hv[8];
        ldh8nc(&g_h1[(size_t)w * 128 + sl * 8], hv);
#pragma unroll
        for (int j = 0; j < 8; j++) acc[j] = hv[j] * e_self;
    }
    int beg = g_roff[w], end = g_roff[w + 1];
    int i = beg + half;
    for (; i + 2 < end; i += 4) {
        int s0 = __ldg(&g_csrc[i]), s1 = __ldg(&g_csrc[i + 2]);
        float e0 = __expf(lrelu(__ldg(&g_as1[s0 * 4 + h]) + my_ad));
        float e1 = __expf(lrelu(__ldg(&g_as1[s1 * 4 + h]) + my_ad));
        den += e0 + e1;
        float h0[8], h1[8];
        ldh8nc(&g_h1[(size_t)s0 * 128 + sl * 8], h0);
        ldh8nc(&g_h1[(size_t)s1 * 128 + sl * 8], h1);
#pragma unroll
        for (int j = 0; j < 8; j++) acc[j] += h0[j] * e0 + h1[j] * e1;
    }
    for (; i < end; i += 2) {
        int s0 = __ldg(&g_csrc[i]);
        float e0 = __expf(lrelu(__ldg(&g_as1[s0 * 4 + h]) + my_ad));
        den += e0;
        float h0[8];
        ldh8nc(&g_h1[(size_t)s0 * 128 + sl * 8], h0);
#pragma unroll
        for (int j = 0; j < 8; j++) acc[j] += h0[j] * e0;
    }
#pragma unroll
    for (int j = 0; j < 8; j++) acc[j] += __shfl_xor_sync(~0u, acc[j], 16);
    den += __shfl_xor_sync(~0u, den, 16);
    if (half == 0) {
        float inv = __frcp_rn(den + 1e-16f);
        float4 bb0 = *(const float4*)&b1[sl * 8];
        float4 bb1 = *(const float4*)&b1[sl * 8 + 4];
        float o[8];
        o[0] = acc[0] * inv + bb0.x; o[1] = acc[1] * inv + bb0.y;
        o[2] = acc[2] * inv + bb0.z; o[3] = acc[3] * inv + bb0.w;
        o[4] = acc[4] * inv + bb1.x; o[5] = acc[5] * inv + bb1.y;
        o[6] = acc[6] * inv + bb1.z; o[7] = acc[7] * inv + bb1.w;
        sth8(&g_o1[(size_t)w * 128 + sl * 8], o);
    }
}

// ---------------- layer2 gather + next-replay state reset --------------------
__global__ void k_gather2(const float* __restrict__ b2, float* __restrict__ out) {
    // tail cleanup for the next replay: zero g_deg / g_tick (runs every launch)
    {
        int gidx = blockIdx.x * blockDim.x + threadIdx.x;
        if (gidx < NN) g_deg[gidx] = 0;
        if (gidx == 0) g_tick = 0;
    }
    int w = blockIdx.x * 8 + (threadIdx.x >> 5);
    int lane = threadIdx.x & 31;
    if (w >= NN) return;
    int q = lane >> 3;
    int sl = lane & 7;
    float my_ad = __ldg(&g_ad2[w]);
    float den = 0.f;
    float acc[8];
#pragma unroll
    for (int j = 0; j < 8; j++) acc[j] = 0.f;
    if (q == 0) {
        float e_self = __expf(lrelu(__ldg(&g_as2[w]) + my_ad));
        den = e_self;
        float hv[8];
        ldh8nc(&g_h2[(size_t)w * 64 + sl * 8], hv);
#pragma unroll
        for (int j = 0; j < 8; j++) acc[j] = hv[j] * e_self;
    }
    int beg = g_roff[w], end = g_roff[w + 1];
    int i = beg + q;
    for (; i + 4 < end; i += 8) {
        int s0 = __ldg(&g_csrc[i]), s1 = __ldg(&g_csrc[i + 4]);
        float e0 = __expf(lrelu(__ldg(&g_as2[s0]) + my_ad));
        float e1 = __expf(lrelu(__ldg(&g_as2[s1]) + my_ad));
        den += e0 + e1;
        float h0[8], h1[8];
        ldh8nc(&g_h2[(size_t)s0 * 64 + sl * 8], h0);
        ldh8nc(&g_h2[(size_t)s1 * 64 + sl * 8], h1);
#pragma unroll
        for (int j = 0; j < 8; j++) acc[j] += h0[j] * e0 + h1[j] * e1;
    }
    for (; i < end; i += 4) {
        int s0 = __ldg(&g_csrc[i]);
        float e0 = __expf(lrelu(__ldg(&g_as2[s0]) + my_ad));
        den += e0;
        float h0[8];
        ldh8nc(&g_h2[(size_t)s0 * 64 + sl * 8], h0);
#pragma unroll
        for (int j = 0; j < 8; j++) acc[j] += h0[j] * e0;
    }
#pragma unroll
    for (int j = 0; j < 8; j++) {
        acc[j] += __shfl_xor_sync(~0u, acc[j], 8);
        acc[j] += __shfl_xor_sync(~0u, acc[j], 16);
    }
    den += __shfl_xor_sync(~0u, den, 8);
    den += __shfl_xor_sync(~0u, den, 16);
    if (q == 0) {
        float inv = __frcp_rn(den + 1e-16f);
        float4 bb0 = *(const float4*)&b2[sl * 8];
        float4 bb1 = *(const float4*)&b2[sl * 8 + 4];
        float4 o0 = make_float4(acc[0] * inv + bb0.x, acc[1] * inv + bb0.y,
                                acc[2] * inv + bb0.z, acc[3] * inv + bb0.w);
        float4 o1 = make_float4(acc[4] * inv + bb1.x, acc[5] * inv + bb1.y,
                                acc[6] * inv + bb1.z, acc[7] * inv + bb1.w);
        *(float4*)&out[(size_t)w * 64 + sl * 8]     = o0;
        *(float4*)&out[(size_t)w * 64 + sl * 8 + 4] = o1;
    }
}

// ---------------- launch: CSR ∥ gemm1, then gather1/gemm2 pipelined ----------
extern "C" void kernel_launch(void* const* d_in, const int* in_sizes, int n_in,
                              void* d_out, int out_size) {
    const float* x    = (const float*)d_in[0];
    const void*  ei   = d_in[1];
    const float* W1   = (const float*)d_in[2];
    const float* as1  = (const float*)d_in[3];
    const float* ad1  = (const float*)d_in[4];
    const float* b1   = (const float*)d_in[5];
    const float* W2   = (const float*)d_in[6];
    const float* as2  = (const float*)d_in[7];
    const float* ad2  = (const float*)d_in[8];
    const float* b2   = (const float*)d_in[9];
    float* out = (float*)d_out;

    __half* p_h1;  cudaGetSymbolAddress((void**)&p_h1, g_h1);
    __half* p_o1;  cudaGetSymbolAddress((void**)&p_o1, g_o1);
    __half* p_h2;  cudaGetSymbolAddress((void**)&p_h2, g_h2);

    static cudaStream_t s2 = nullptr;
    static cudaEvent_t evF = nullptr, evG = nullptr, evJ = nullptr, evJ2 = nullptr;
    if (!s2) {
        cudaStreamCreate(&s2);
        cudaEventCreateWithFlags(&evF, cudaEventDisableTiming);
        cudaEventCreateWithFlags(&evG, cudaEventDisableTiming);
        cudaEventCreateWithFlags(&evJ, cudaEventDisableTiming);
        cudaEventCreateWithFlags(&evJ2, cudaEventDisableTiming);
    }

    // fork: side stream builds CSR while main stream does GEMM1
    cudaEventRecord(evF, 0);
    cudaStreamWaitEvent(s2, evF, 0);

    k_prep   <<<(EE + 255) / 256, 256, 0, s2>>>(ei);
    k_scanA  <<<NB2, 512, 0, s2>>>();
    k_scan3  <<<NB2, 512, 0, s2>>>();
    k_scatter<<<(EE + 255) / 256, 256, 0, s2>>>();
    cudaEventRecord(evJ, s2);

    k_gemm1<<<(NN + 63) / 64, 256>>>(x, W1, p_h1, as1, ad1, NN);
    cudaEventRecord(evG, 0);

    // join both ways: main waits CSR; side waits gemm1
    cudaStreamWaitEvent(0, evJ, 0);
    cudaStreamWaitEvent(s2, evG, 0);

    // pipelined halves: gather1_a -> gemm2_a on main; gather1_b -> gemm2_b on s2
    k_gather1<<<NH / 8, 256>>>(b1, 0, NH);
    k_gather1<<<(NN - NH + 7) / 8, 256, 0, s2>>>(b1, NH, NN - NH);
    k_gemm2<<<NH / 64, 256>>>(p_o1, W2, p_h2, as2, ad2, 0, NN);
    k_gemm2<<<(NN - NH + 63) / 64, 256, 0, s2>>>(p_o1, W2, p_h2, as2, ad2, NH, NN);
    cudaEventRecord(evJ2, s2);
    cudaStreamWaitEvent(0, evJ2, 0);

    k_gather2<<<(NN + 7) / 8, 256>>>(b2, out);
}